// round 1
// baseline (speedup 1.0000x reference)
#include <cuda_runtime.h>
#include <math.h>

#define SB    2048
#define DIMD  2048
#define BATCH 2
#define NH    16
#define NKVH  4
#define HD    128
#define KVF   1024
#define ROWS  (BATCH*SB)   // 4096

// ---------------- scratch (device globals: allocation-free) ----------------
__device__ float g_xq[(size_t)ROWS*DIMD];     // gated x
__device__ float g_q [(size_t)ROWS*DIMD];     // q projection
__device__ float g_kv[(size_t)ROWS*KVF];      // k (first 512 cols) | v (last 512)
__device__ float g_at[(size_t)ROWS*DIMD];     // attention output (pre-Wo)

// ---------------- kernel 1: complexity gate ----------------
__global__ __launch_bounds__(256) void gate_kernel(const float* __restrict__ x,
                                                   float* __restrict__ xq) {
    int row = blockIdx.x;
    const float* xr = x + (size_t)row * DIMD;
    float s = 0.f;
    for (int c = threadIdx.x; c < DIMD; c += 256) s += fabsf(xr[c]);
    __shared__ float red[256];
    red[threadIdx.x] = s; __syncthreads();
    for (int off = 128; off > 0; off >>= 1) {
        if (threadIdx.x < off) red[threadIdx.x] += red[threadIdx.x + off];
        __syncthreads();
    }
    float cw = 1.f / (1.f + __expf(-red[0]));
    float* o = xq + (size_t)row * DIMD;
    for (int c = threadIdx.x; c < DIMD; c += 256) o[c] = xr[c] * cw;
}

// ---------------- kernel 2: fp32 SGEMM, C[M,N] = A[M,K] @ B[K,N] (+bias) ----
__global__ __launch_bounds__(256) void sgemm_kernel(
    const float* __restrict__ A, const float* __restrict__ B,
    const float* __restrict__ bias, float* __restrict__ C,
    int M, int N, int K) {
    __shared__ float As[8][128];
    __shared__ float Bs[8][128];
    const int tid = threadIdx.x;
    const int tx = tid & 15, ty = tid >> 4;
    const int bx = blockIdx.x, by = blockIdx.y;
    const float* Ab = A + (size_t)by * 128 * K;
    const float* Bb = B + (size_t)bx * 128;
    const int aRow = tid >> 1, aCol = (tid & 1) * 4;
    const int bRow = tid >> 5, bCol = (tid & 31) * 4;

    float acc[8][8];
#pragma unroll
    for (int i = 0; i < 8; i++)
#pragma unroll
        for (int j = 0; j < 8; j++) acc[i][j] = 0.f;

    for (int k0 = 0; k0 < K; k0 += 8) {
        float4 av = *(const float4*)(Ab + (size_t)aRow * K + k0 + aCol);
        As[aCol + 0][aRow] = av.x; As[aCol + 1][aRow] = av.y;
        As[aCol + 2][aRow] = av.z; As[aCol + 3][aRow] = av.w;
        *(float4*)(&Bs[bRow][bCol]) =
            *(const float4*)(Bb + (size_t)(k0 + bRow) * N + bCol);
        __syncthreads();
#pragma unroll
        for (int kk = 0; kk < 8; kk++) {
            float ar[8], br[8];
            *(float4*)&ar[0] = *(const float4*)&As[kk][ty * 8];
            *(float4*)&ar[4] = *(const float4*)&As[kk][ty * 8 + 4];
            *(float4*)&br[0] = *(const float4*)&Bs[kk][tx * 4];
            *(float4*)&br[4] = *(const float4*)&Bs[kk][64 + tx * 4];
#pragma unroll
            for (int i = 0; i < 8; i++)
#pragma unroll
                for (int j = 0; j < 8; j++) acc[i][j] += ar[i] * br[j];
        }
        __syncthreads();
    }

    const int cbase = bx * 128 + tx * 4;
    float b0[4] = {0.f, 0.f, 0.f, 0.f}, b1[4] = {0.f, 0.f, 0.f, 0.f};
    if (bias) {
#pragma unroll
        for (int j = 0; j < 4; j++) { b0[j] = bias[cbase + j]; b1[j] = bias[cbase + 64 + j]; }
    }
#pragma unroll
    for (int i = 0; i < 8; i++) {
        size_t row = (size_t)by * 128 + ty * 8 + i;
        float4 o0 = make_float4(acc[i][0] + b0[0], acc[i][1] + b0[1],
                                acc[i][2] + b0[2], acc[i][3] + b0[3]);
        float4 o1 = make_float4(acc[i][4] + b1[0], acc[i][5] + b1[1],
                                acc[i][6] + b1[2], acc[i][7] + b1[3]);
        *(float4*)(C + row * N + cbase)      = o0;
        *(float4*)(C + row * N + cbase + 64) = o1;
    }
}

// ---------------- kernel 3: v column-mean for global query rows (i<64) ------
__global__ __launch_bounds__(1024) void vmean_kernel(const float* __restrict__ kv,
                                                     float* __restrict__ out) {
    int b = blockIdx.x >> 2, kvh = blockIdx.x & 3;
    int d = threadIdx.x & 127;
    int c = threadIdx.x >> 7;  // 0..7
    const float* v = kv + (size_t)b * SB * KVF + NKVH * HD + kvh * HD + d;
    float s = 0.f;
    int j0 = c * 256;
#pragma unroll 8
    for (int j = j0; j < j0 + 256; j++) s += v[(size_t)j * KVF];
    __shared__ float red[8][128];
    red[c][d] = s;
    __syncthreads();
    if (c == 0) {
        float t = 0.f;
#pragma unroll
        for (int u = 0; u < 8; u++) t += red[u][d];
        t *= (1.0f / 2048.0f);
        for (int hh = 0; hh < 4; hh++) {
            int h = kvh * 4 + hh;
            for (int i = 0; i < 64; i++)
                out[((size_t)(b * SB) + i) * DIMD + h * HD + d] = t;
        }
    }
}

// ---------------- kernel 4: flash attention (inverted window mask) ----------
#define BQ 64
#define BKT 64
#define PSLD 68
// dynamic smem layout (floats): Qt[128][64] sw | KV max(Kt[128][64] sw, Vs[64][128]) | Ps[64][68] | m,l,f
#define SM_QT 0
#define SM_KV 8192
#define SM_PS 16384
#define SM_M  20736
#define SM_L  20800
#define SM_F  20864
#define ATTN_SMEM_FLOATS 20928
#define ATTN_SMEM_BYTES  (ATTN_SMEM_FLOATS * 4)

__global__ __launch_bounds__(256) void attn_kernel(
    const float* __restrict__ q, const float* __restrict__ kv,
    float* __restrict__ out) {
    extern __shared__ float sm[];
    float* Qt   = sm + SM_QT;
    float* KV   = sm + SM_KV;
    float* Ps   = sm + SM_PS;
    float* mrow = sm + SM_M;
    float* lrow = sm + SM_L;
    float* frow = sm + SM_F;

    const int tid = threadIdx.x;
    const int tx = tid & 15, ty = tid >> 4;
    const int i0 = 64 + blockIdx.x * BQ;   // query rows 64..2047
    const int h  = blockIdx.y;
    const int b  = blockIdx.z;
    const int kvh = h >> 2;
    const float slope = exp2f(-0.5f * (float)(h + 1));
    const float scale = 0.08838834764831845f;  // 1/sqrt(128)

    const float* qbase = q  + ((size_t)(b * SB + i0) * DIMD) + h * HD;
    const float* kbase = kv + ((size_t)b * SB * KVF) + kvh * HD;
    const float* vbase = kbase + NKVH * HD;  // +512

    // load Q transposed with XOR chunk swizzle: Qt[d][qi'] where chunk' = (qi>>2) ^ ((d>>2)&15)
#pragma unroll
    for (int it = 0; it < 8; it++) {
        int flat = it * 1024 + tid * 4;
        int qi = flat >> 7, d0 = flat & 127;
        float4 v = *(const float4*)(qbase + (size_t)qi * DIMD + d0);
        int pc = ((qi >> 2) ^ ((d0 >> 2) & 15)) * 4 + (qi & 3);
        Qt[(d0 + 0) * 64 + pc] = v.x;
        Qt[(d0 + 1) * 64 + pc] = v.y;
        Qt[(d0 + 2) * 64 + pc] = v.z;
        Qt[(d0 + 3) * 64 + pc] = v.w;
    }
    if (tid < BQ) { mrow[tid] = -INFINITY; lrow[tid] = 0.f; }

    float o[4][8];
#pragma unroll
    for (int i = 0; i < 4; i++)
#pragma unroll
        for (int j = 0; j < 8; j++) o[i][j] = 0.f;

    const int r0 = ty * 4, c0 = tx * 4;
    const int ty4 = ty << 2, tx4 = tx << 2;

    for (int j0 = 64; j0 < SB; j0 += BKT) {
        // skip tiles fully inside the attention window (all scores -> -1e9 -> exp 0)
        int mdist = max(abs(i0 - (j0 + BKT - 1)), abs((i0 + BQ - 1) - j0));
        if (mdist <= 256) continue;

        __syncthreads();  // previous Vs consumed / Qt ready
        // load K transposed + swizzled
#pragma unroll
        for (int it = 0; it < 8; it++) {
            int flat = it * 1024 + tid * 4;
            int jr = flat >> 7, d0 = flat & 127;
            float4 v = *(const float4*)(kbase + (size_t)(j0 + jr) * KVF + d0);
            int pc = ((jr >> 2) ^ ((d0 >> 2) & 15)) * 4 + (jr & 3);
            KV[(d0 + 0) * 64 + pc] = v.x;
            KV[(d0 + 1) * 64 + pc] = v.y;
            KV[(d0 + 2) * 64 + pc] = v.z;
            KV[(d0 + 3) * 64 + pc] = v.w;
        }
        __syncthreads();

        // S = Q @ K^T  (4x4 per thread)
        float s[4][4];
#pragma unroll
        for (int i = 0; i < 4; i++)
#pragma unroll
            for (int j = 0; j < 4; j++) s[i][j] = 0.f;
#pragma unroll 4
        for (int d = 0; d < HD; d++) {
            int sw4 = ((d >> 2) & 15) << 2;
            float4 qv = *(const float4*)&Qt[d * 64 + (ty4 ^ sw4)];
            float4 kq = *(const float4*)&KV[d * 64 + (tx4 ^ sw4)];
            float qa[4] = {qv.x, qv.y, qv.z, qv.w};
            float ka[4] = {kq.x, kq.y, kq.z, kq.w};
#pragma unroll
            for (int i = 0; i < 4; i++)
#pragma unroll
                for (int j = 0; j < 4; j++) s[i][j] += qa[i] * ka[j];
        }

        // mask + ALiBi, per-row max over this tile
        float tmax[4];
#pragma unroll
        for (int i = 0; i < 4; i++) {
            int gi = i0 + r0 + i;
            float mx = -INFINITY;
#pragma unroll
            for (int j = 0; j < 4; j++) {
                int gj = j0 + c0 + j;
                int dist = abs(gi - gj);
                float val = (dist <= 256) ? -1e9f
                                          : (s[i][j] * scale - slope * (float)dist);
                s[i][j] = val;
                mx = fmaxf(mx, val);
            }
            tmax[i] = mx;
        }
#pragma unroll
        for (int off = 8; off > 0; off >>= 1)
#pragma unroll
            for (int i = 0; i < 4; i++)
                tmax[i] = fmaxf(tmax[i], __shfl_xor_sync(0xffffffffu, tmax[i], off));

        // online softmax update
        float m_old[4], m_new[4], rsum[4];
#pragma unroll
        for (int i = 0; i < 4; i++) {
            m_old[i] = mrow[r0 + i];
            m_new[i] = fmaxf(m_old[i], tmax[i]);
            float rs = 0.f;
#pragma unroll
            for (int j = 0; j < 4; j++) {
                float p = __expf(s[i][j] - m_new[i]);
                s[i][j] = p;
                rs += p;
            }
            rsum[i] = rs;
        }
#pragma unroll
        for (int off = 8; off > 0; off >>= 1)
#pragma unroll
            for (int i = 0; i < 4; i++)
                rsum[i] += __shfl_xor_sync(0xffffffffu, rsum[i], off);

        __syncwarp();
        if (tx == 0) {
#pragma unroll
            for (int i = 0; i < 4; i++) {
                float f = __expf(m_old[i] - m_new[i]);
                frow[r0 + i] = f;
                lrow[r0 + i] = lrow[r0 + i] * f + rsum[i];
                mrow[r0 + i] = m_new[i];
            }
        }
#pragma unroll
        for (int i = 0; i < 4; i++)
#pragma unroll
            for (int j = 0; j < 4; j++)
                Ps[(r0 + i) * PSLD + c0 + j] = s[i][j];
        __syncthreads();  // Kt consumed, Ps/frow visible

        // load V (row-major) over the K buffer
#pragma unroll
        for (int it = 0; it < 8; it++) {
            int flat = it * 1024 + tid * 4;
            *(float4*)&KV[flat] =
                *(const float4*)(vbase + (size_t)(j0 + (flat >> 7)) * KVF + (flat & 127));
        }
        __syncthreads();

        // O = O*f + P @ V   (4 rows x 8 cols per thread, cols tx*4 and 64+tx*4)
        float f[4];
#pragma unroll
        for (int i = 0; i < 4; i++) {
            f[i] = frow[r0 + i];
#pragma unroll
            for (int j = 0; j < 8; j++) o[i][j] *= f[i];
        }
#pragma unroll 2
        for (int kk = 0; kk < BKT; kk++) {
            float p0 = Ps[(r0 + 0) * PSLD + kk];
            float p1 = Ps[(r0 + 1) * PSLD + kk];
            float p2 = Ps[(r0 + 2) * PSLD + kk];
            float p3 = Ps[(r0 + 3) * PSLD + kk];
            float4 va = *(const float4*)&KV[kk * 128 + tx4];
            float4 vb = *(const float4*)&KV[kk * 128 + 64 + tx4];
            float vv[8] = {va.x, va.y, va.z, va.w, vb.x, vb.y, vb.z, vb.w};
#pragma unroll
            for (int j = 0; j < 8; j++) {
                o[0][j] += p0 * vv[j];
                o[1][j] += p1 * vv[j];
                o[2][j] += p2 * vv[j];
                o[3][j] += p3 * vv[j];
            }
        }
    }

    __syncthreads();
#pragma unroll
    for (int i = 0; i < 4; i++) {
        float inv = 1.f / lrow[r0 + i];
        size_t row = (size_t)(b * SB + i0 + r0 + i);
        float* op = out + row * DIMD + h * HD + tx4;
        float4 o0 = make_float4(o[i][0] * inv, o[i][1] * inv, o[i][2] * inv, o[i][3] * inv);
        float4 o1 = make_float4(o[i][4] * inv, o[i][5] * inv, o[i][6] * inv, o[i][7] * inv);
        *(float4*)op        = o0;
        *(float4*)(op + 64) = o1;
    }
}

// ---------------- launcher ----------------
extern "C" void kernel_launch(void* const* d_in, const int* in_sizes, int n_in,
                              void* d_out, int out_size) {
    (void)in_sizes; (void)n_in; (void)out_size;
    const float* x   = (const float*)d_in[0];
    const float* Wq  = (const float*)d_in[1];
    const float* Wkv = (const float*)d_in[2];
    const float* Wo  = (const float*)d_in[3];
    const float* bo  = (const float*)d_in[4];
    float* out = (float*)d_out;

    float *xq, *qb, *kvb, *attnb;
    cudaGetSymbolAddress((void**)&xq,    g_xq);
    cudaGetSymbolAddress((void**)&qb,    g_q);
    cudaGetSymbolAddress((void**)&kvb,   g_kv);
    cudaGetSymbolAddress((void**)&attnb, g_at);

    cudaFuncSetAttribute(attn_kernel,
                         cudaFuncAttributeMaxDynamicSharedMemorySize,
                         ATTN_SMEM_BYTES);

    gate_kernel<<<ROWS, 256>>>(x, xq);

    dim3 gq(DIMD / 128, ROWS / 128);
    sgemm_kernel<<<gq, 256>>>(xq, Wq, nullptr, qb, ROWS, DIMD, DIMD);

    dim3 gkv(KVF / 128, ROWS / 128);
    sgemm_kernel<<<gkv, 256>>>(x, Wkv, nullptr, kvb, ROWS, KVF, DIMD);

    vmean_kernel<<<BATCH * NKVH, 1024>>>(kvb, attnb);

    dim3 ga(31, NH, BATCH);  // query tiles 64..2047
    attn_kernel<<<ga, 256, ATTN_SMEM_BYTES>>>(qb, kvb, attnb);

    dim3 go(DIMD / 128, ROWS / 128);
    sgemm_kernel<<<go, 256>>>(attnb, Wo, bo, out, ROWS, DIMD, DIMD);
}

// round 5
// speedup vs baseline: 1.3283x; 1.3283x over previous
#include <cuda_runtime.h>
#include <cuda_bf16.h>
#include <cstdint>
#include <stdint.h>
#include <math.h>

#define SB    2048
#define DIMD  2048
#define BATCH 2
#define NH    16
#define NKVH  4
#define HD    128
#define KVF   1024
#define ROWS  (BATCH*SB)   // 4096

// ---------------- scratch (device globals: allocation-free) ----------------
__device__ float g_q [(size_t)ROWS*DIMD];     // q projection (fp32)
__device__ float g_kv[(size_t)ROWS*KVF];      // k | v (fp32)
__device__ float g_at[(size_t)ROWS*DIMD];     // attention output (fp32)

// bf16 hi/lo splits
__device__ __nv_bfloat16 g_xq_h[(size_t)ROWS*DIMD], g_xq_l[(size_t)ROWS*DIMD];
__device__ __nv_bfloat16 g_x_h [(size_t)ROWS*DIMD], g_x_l [(size_t)ROWS*DIMD];
__device__ __nv_bfloat16 g_at_h[(size_t)ROWS*DIMD], g_at_l[(size_t)ROWS*DIMD];
// transposed weights [N][K]
__device__ __nv_bfloat16 g_wq_h [(size_t)DIMD*DIMD], g_wq_l [(size_t)DIMD*DIMD];
__device__ __nv_bfloat16 g_wkv_h[(size_t)KVF *DIMD], g_wkv_l[(size_t)KVF *DIMD];
__device__ __nv_bfloat16 g_wo_h [(size_t)DIMD*DIMD], g_wo_l [(size_t)DIMD*DIMD];

// ---------------- helpers ----------------
__device__ __forceinline__ void bfsplit(float v, __nv_bfloat16& h, __nv_bfloat16& l) {
    h = __float2bfloat16_rn(v);
    l = __float2bfloat16_rn(v - __bfloat162float(h));
}

// ---------------- kernel 1: complexity gate + split ----------------
__global__ __launch_bounds__(256) void gate_split_kernel(const float* __restrict__ x,
                                                         __nv_bfloat16* __restrict__ xh,
                                                         __nv_bfloat16* __restrict__ xl) {
    int row = blockIdx.x;
    const float* xr = x + (size_t)row * DIMD;
    float s = 0.f;
    for (int c = threadIdx.x; c < DIMD; c += 256) s += fabsf(xr[c]);
    __shared__ float red[256];
    red[threadIdx.x] = s; __syncthreads();
    for (int off = 128; off > 0; off >>= 1) {
        if (threadIdx.x < off) red[threadIdx.x] += red[threadIdx.x + off];
        __syncthreads();
    }
    float cw = 1.f / (1.f + __expf(-red[0]));
    size_t base = (size_t)row * DIMD;
    for (int c = threadIdx.x; c < DIMD; c += 256) {
        __nv_bfloat16 h, l;
        bfsplit(xr[c] * cw, h, l);
        xh[base + c] = h; xl[base + c] = l;
    }
}

// ---------------- kernel: elementwise split ----------------
__global__ __launch_bounds__(256) void split_kernel(const float* __restrict__ in,
                                                    __nv_bfloat16* __restrict__ h,
                                                    __nv_bfloat16* __restrict__ l, int n) {
    int i = (blockIdx.x * 256 + threadIdx.x) * 4;
    if (i >= n) return;
    float4 v = *(const float4*)(in + i);
    __nv_bfloat16 hh[4], ll[4];
    bfsplit(v.x, hh[0], ll[0]); bfsplit(v.y, hh[1], ll[1]);
    bfsplit(v.z, hh[2], ll[2]); bfsplit(v.w, hh[3], ll[3]);
    *(uint2*)(h + i) = *(uint2*)hh;
    *(uint2*)(l + i) = *(uint2*)ll;
}

// ---------------- kernel: transpose + split  W[K][N] -> T[N][K] ------------
__global__ __launch_bounds__(256) void transpose_split_kernel(
    const float* __restrict__ W, __nv_bfloat16* __restrict__ Th,
    __nv_bfloat16* __restrict__ Tl, int K, int N) {
    __shared__ float tile[32][33];
    int n0 = blockIdx.x * 32, k0 = blockIdx.y * 32;
    int tx = threadIdx.x, ty = threadIdx.y;
#pragma unroll
    for (int r = ty; r < 32; r += 8)
        tile[r][tx] = W[(size_t)(k0 + r) * N + n0 + tx];
    __syncthreads();
#pragma unroll
    for (int r = ty; r < 32; r += 8) {
        float v = tile[tx][r];  // element (k0+tx, n0+r)
        __nv_bfloat16 h, l; bfsplit(v, h, l);
        size_t o = (size_t)(n0 + r) * K + k0 + tx;
        Th[o] = h; Tl[o] = l;
    }
}

// ---------------- bf16x3 tensor-core GEMM: C = A @ Bt^T (+bias) -------------
// A[M][K] (hi/lo bf16), Bt[N][K] (hi/lo bf16), C[M][N] fp32
#define BM 128
#define BN 128
#define BKT32 32
#define SROWB 80            // padded smem row stride bytes (40 bf16)
#define BUFB  (128*SROWB)   // 10240 B per buffer
#define STAGEB (4*BUFB)     // Ahi|Alo|Bhi|Blo = 40960 B
#define GEMM_SMEM (2*STAGEB)

__device__ __forceinline__ void cp16(uint32_t dst, const void* src) {
    asm volatile("cp.async.cg.shared.global [%0], [%1], 16;\n" :: "r"(dst), "l"(src));
}
__device__ __forceinline__ void cp_commit() { asm volatile("cp.async.commit_group;\n"); }
__device__ __forceinline__ void cp_wait1() { asm volatile("cp.async.wait_group 1;\n"); }
__device__ __forceinline__ void cp_wait0() { asm volatile("cp.async.wait_group 0;\n"); }
__device__ __forceinline__ void ldsm4(uint32_t& r0, uint32_t& r1, uint32_t& r2, uint32_t& r3,
                                      uint32_t addr) {
    asm volatile("ldmatrix.sync.aligned.m8n8.x4.shared.b16 {%0,%1,%2,%3}, [%4];\n"
                 : "=r"(r0), "=r"(r1), "=r"(r2), "=r"(r3) : "r"(addr));
}
__device__ __forceinline__ void mma_bf16(float* d, uint32_t a0, uint32_t a1, uint32_t a2,
                                         uint32_t a3, uint32_t b0, uint32_t b1) {
    asm volatile("mma.sync.aligned.m16n8k16.row.col.f32.bf16.bf16.f32 "
                 "{%0,%1,%2,%3}, {%4,%5,%6,%7}, {%8,%9}, {%0,%1,%2,%3};\n"
                 : "+f"(d[0]), "+f"(d[1]), "+f"(d[2]), "+f"(d[3])
                 : "r"(a0), "r"(a1), "r"(a2), "r"(a3), "r"(b0), "r"(b1));
}

__global__ __launch_bounds__(256) void gemm3_kernel(
    const __nv_bfloat16* __restrict__ Ahi, const __nv_bfloat16* __restrict__ Alo,
    const __nv_bfloat16* __restrict__ Bhi, const __nv_bfloat16* __restrict__ Blo,
    const float* __restrict__ bias, float* __restrict__ C,
    int M, int N, int K) {
    extern __shared__ char smem[];
    const uint32_t sb = (uint32_t)__cvta_generic_to_shared(smem);
    const int tid = threadIdx.x;
    const int lane = tid & 31, wid = tid >> 5;
    const int warpM = wid >> 2, warpN = wid & 3;     // 2 x 4 warps -> 64x32 warp tile
    const int mBlk = blockIdx.y * BM, nBlk = blockIdx.x * BN;

    // -- load mapping: 2 chunks (16B each) per buffer per thread --
    const int lrow = tid >> 1;              // 0..127
    const int lc0  = (tid & 1) * 2;         // chunk 0/2
    const size_t aG = (size_t)(mBlk + lrow) * K + lc0 * 8;
    const size_t bG = (size_t)(nBlk + lrow) * K + lc0 * 8;
    const uint32_t sD = sb + lrow * SROWB + lc0 * 16;

    // -- ldmatrix per-thread bases --
    const int aRow = warpM * 64 + (lane & 7) + ((lane >> 3) & 1) * 8;
    const uint32_t aLd = aRow * SROWB + (lane >> 4) * 16;
    const int bRow = warpN * 32 + (lane & 7) + (lane >> 4) * 8;
    const uint32_t bLd = bRow * SROWB + ((lane >> 3) & 1) * 16;

    float acc[4][4][4];
#pragma unroll
    for (int i = 0; i < 4; i++)
#pragma unroll
        for (int j = 0; j < 4; j++)
#pragma unroll
            for (int r = 0; r < 4; r++) acc[i][j][r] = 0.f;

    const int nkt = K / BKT32;

    // prefetch stage 0
    {
        uint32_t d = sD;
        cp16(d,              Ahi + aG); cp16(d + 16,              Ahi + aG + 8);
        cp16(d + BUFB,       Alo + aG); cp16(d + BUFB + 16,       Alo + aG + 8);
        cp16(d + 2*BUFB,     Bhi + bG); cp16(d + 2*BUFB + 16,     Bhi + bG + 8);
        cp16(d + 3*BUFB,     Blo + bG); cp16(d + 3*BUFB + 16,     Blo + bG + 8);
        cp_commit();
    }

    for (int kt = 0; kt < nkt; kt++) {
        const int cur = kt & 1;
        if (kt + 1 < nkt) {
            uint32_t d = sD + (cur ^ 1) * STAGEB;
            size_t ga = aG + (size_t)(kt + 1) * 32;
            size_t gb = bG + (size_t)(kt + 1) * 32;
            cp16(d,          Ahi + ga); cp16(d + 16,          Ahi + ga + 8);
            cp16(d + BUFB,   Alo + ga); cp16(d + BUFB + 16,   Alo + ga + 8);
            cp16(d + 2*BUFB, Bhi + gb); cp16(d + 2*BUFB + 16, Bhi + gb + 8);
            cp16(d + 3*BUFB, Blo + gb); cp16(d + 3*BUFB + 16, Blo + gb + 8);
            cp_commit();
            cp_wait1();
        } else {
            cp_wait0();
        }
        __syncthreads();

        const uint32_t base = sb + cur * STAGEB;
#pragma unroll
        for (int kkB = 0; kkB < 64; kkB += 32) {   // two k16 halves (bytes)
            uint32_t bh[8], bl[8];
            ldsm4(bh[0], bh[1], bh[2], bh[3], base + 2*BUFB + bLd + kkB);
            ldsm4(bh[4], bh[5], bh[6], bh[7], base + 2*BUFB + bLd + kkB + 16*SROWB);
            ldsm4(bl[0], bl[1], bl[2], bl[3], base + 3*BUFB + bLd + kkB);
            ldsm4(bl[4], bl[5], bl[6], bl[7], base + 3*BUFB + bLd + kkB + 16*SROWB);
#pragma unroll
            for (int i = 0; i < 4; i++) {
                uint32_t ah[4], al[4];
                ldsm4(ah[0], ah[1], ah[2], ah[3], base + aLd + i*16*SROWB + kkB);
                ldsm4(al[0], al[1], al[2], al[3], base + BUFB + aLd + i*16*SROWB + kkB);
#pragma unroll
                for (int j = 0; j < 4; j++) {
                    mma_bf16(acc[i][j], ah[0], ah[1], ah[2], ah[3], bh[2*j], bh[2*j+1]);
                    mma_bf16(acc[i][j], ah[0], ah[1], ah[2], ah[3], bl[2*j], bl[2*j+1]);
                    mma_bf16(acc[i][j], al[0], al[1], al[2], al[3], bh[2*j], bh[2*j+1]);
                }
            }
        }
        __syncthreads();
    }

    // epilogue
#pragma unroll
    for (int i = 0; i < 4; i++) {
#pragma unroll
        for (int j = 0; j < 4; j++) {
            int rg = mBlk + warpM * 64 + i * 16 + (lane >> 2);
            int cg = nBlk + warpN * 32 + j * 8 + (lane & 3) * 2;
            float b0 = 0.f, b1 = 0.f;
            if (bias) { b0 = bias[cg]; b1 = bias[cg + 1]; }
            float2 v0 = make_float2(acc[i][j][0] + b0, acc[i][j][1] + b1);
            float2 v1 = make_float2(acc[i][j][2] + b0, acc[i][j][3] + b1);
            *(float2*)(C + (size_t)rg * N + cg)       = v0;
            *(float2*)(C + (size_t)(rg + 8) * N + cg) = v1;
        }
    }
}

// ---------------- kernel: v column-mean for global query rows (i<64) ------
__global__ __launch_bounds__(1024) void vmean_kernel(const float* __restrict__ kv,
                                                     float* __restrict__ out) {
    int b = blockIdx.x >> 2, kvh = blockIdx.x & 3;
    int d = threadIdx.x & 127;
    int c = threadIdx.x >> 7;  // 0..7
    const float* v = kv + (size_t)b * SB * KVF + NKVH * HD + kvh * HD + d;
    float s = 0.f;
    int j0 = c * 256;
#pragma unroll 8
    for (int j = j0; j < j0 + 256; j++) s += v[(size_t)j * KVF];
    __shared__ float red[8][128];
    red[c][d] = s;
    __syncthreads();
    if (c == 0) {
        float t = 0.f;
#pragma unroll
        for (int u = 0; u < 8; u++) t += red[u][d];
        t *= (1.0f / 2048.0f);
        for (int hh = 0; hh < 4; hh++) {
            int h = kvh * 4 + hh;
            for (int i = 0; i < 64; i++)
                out[((size_t)(b * SB) + i) * DIMD + h * HD + d] = t;
        }
    }
}

// ---------------- flash attention (inverted window mask) ----------
#define BQ 64
#define BKTILE 64
#define PSLD 68
#define SM_QT 0
#define SM_KV 8192
#define SM_PS 16384
#define SM_M  20736
#define SM_L  20800
#define SM_F  20864
#define ATTN_SMEM_FLOATS 20928
#define ATTN_SMEM_BYTES  (ATTN_SMEM_FLOATS * 4)

__global__ __launch_bounds__(256) void attn_kernel(
    const float* __restrict__ q, const float* __restrict__ kv,
    float* __restrict__ out) {
    extern __shared__ float sm[];
    float* Qt   = sm + SM_QT;
    float* KV   = sm + SM_KV;
    float* Ps   = sm + SM_PS;
    float* mrow = sm + SM_M;
    float* lrow = sm + SM_L;
    float* frow = sm + SM_F;

    const int tid = threadIdx.x;
    const int tx = tid & 15, ty = tid >> 4;
    const int i0 = 64 + blockIdx.x * BQ;
    const int h  = blockIdx.y;
    const int b  = blockIdx.z;
    const int kvh = h >> 2;
    const float slope = exp2f(-0.5f * (float)(h + 1));
    const float scale = 0.08838834764831845f;

    const float* qbase = q  + ((size_t)(b * SB + i0) * DIMD) + h * HD;
    const float* kbase = kv + ((size_t)b * SB * KVF) + kvh * HD;
    const float* vbase = kbase + NKVH * HD;

#pragma unroll
    for (int it = 0; it < 8; it++) {
        int flat = it * 1024 + tid * 4;
        int qi = flat >> 7, d0 = flat & 127;
        float4 v = *(const float4*)(qbase + (size_t)qi * DIMD + d0);
        int pc = ((qi >> 2) ^ ((d0 >> 2) & 15)) * 4 + (qi & 3);
        Qt[(d0 + 0) * 64 + pc] = v.x;
        Qt[(d0 + 1) * 64 + pc] = v.y;
        Qt[(d0 + 2) * 64 + pc] = v.z;
        Qt[(d0 + 3) * 64 + pc] = v.w;
    }
    if (tid < BQ) { mrow[tid] = -INFINITY; lrow[tid] = 0.f; }

    float o[4][8];
#pragma unroll
    for (int i = 0; i < 4; i++)
#pragma unroll
        for (int j = 0; j < 8; j++) o[i][j] = 0.f;

    const int r0 = ty * 4, c0 = tx * 4;
    const int ty4 = ty << 2, tx4 = tx << 2;

    for (int j0 = 64; j0 < SB; j0 += BKTILE) {
        int mdist = max(abs(i0 - (j0 + BKTILE - 1)), abs((i0 + BQ - 1) - j0));
        if (mdist <= 256) continue;

        __syncthreads();
#pragma unroll
        for (int it = 0; it < 8; it++) {
            int flat = it * 1024 + tid * 4;
            int jr = flat >> 7, d0 = flat & 127;
            float4 v = *(const float4*)(kbase + (size_t)(j0 + jr) * KVF + d0);
            int pc = ((jr >> 2) ^ ((d0 >> 2) & 15)) * 4 + (jr & 3);
            KV[(d0 + 0) * 64 + pc] = v.x;
            KV[(d0 + 1) * 64 + pc] = v.y;
            KV[(d0 + 2) * 64 + pc] = v.z;
            KV[(d0 + 3) * 64 + pc] = v.w;
        }
        __syncthreads();

        float s[4][4];
#pragma unroll
        for (int i = 0; i < 4; i++)
#pragma unroll
            for (int j = 0; j < 4; j++) s[i][j] = 0.f;
#pragma unroll 4
        for (int d = 0; d < HD; d++) {
            int sw4 = ((d >> 2) & 15) << 2;
            float4 qv = *(const float4*)&Qt[d * 64 + (ty4 ^ sw4)];
            float4 kq = *(const float4*)&KV[d * 64 + (tx4 ^ sw4)];
            float qa[4] = {qv.x, qv.y, qv.z, qv.w};
            float ka[4] = {kq.x, kq.y, kq.z, kq.w};
#pragma unroll
            for (int i = 0; i < 4; i++)
#pragma unroll
                for (int j = 0; j < 4; j++) s[i][j] += qa[i] * ka[j];
        }

        float tmax[4];
#pragma unroll
        for (int i = 0; i < 4; i++) {
            int gi = i0 + r0 + i;
            float mx = -INFINITY;
#pragma unroll
            for (int j = 0; j < 4; j++) {
                int gj = j0 + c0 + j;
                int dist = abs(gi - gj);
                float val = (dist <= 256) ? -1e9f
                                          : (s[i][j] * scale - slope * (float)dist);
                s[i][j] = val;
                mx = fmaxf(mx, val);
            }
            tmax[i] = mx;
        }
#pragma unroll
        for (int off = 8; off > 0; off >>= 1)
#pragma unroll
            for (int i = 0; i < 4; i++)
                tmax[i] = fmaxf(tmax[i], __shfl_xor_sync(0xffffffffu, tmax[i], off));

        float m_old[4], m_new[4], rsum[4];
#pragma unroll
        for (int i = 0; i < 4; i++) {
            m_old[i] = mrow[r0 + i];
            m_new[i] = fmaxf(m_old[i], tmax[i]);
            float rs = 0.f;
#pragma unroll
            for (int j = 0; j < 4; j++) {
                float p = __expf(s[i][j] - m_new[i]);
                s[i][j] = p;
                rs += p;
            }
            rsum[i] = rs;
        }
#pragma unroll
        for (int off = 8; off > 0; off >>= 1)
#pragma unroll
            for (int i = 0; i < 4; i++)
                rsum[i] += __shfl_xor_sync(0xffffffffu, rsum[i], off);

        __syncwarp();
        if (tx == 0) {
#pragma unroll
            for (int i = 0; i < 4; i++) {
                float f = __expf(m_old[i] - m_new[i]);
                frow[r0 + i] = f;
                lrow[r0 + i] = lrow[r0 + i] * f + rsum[i];
                mrow[r0 + i] = m_new[i];
            }
        }
#pragma unroll
        for (int i = 0; i < 4; i++)
#pragma unroll
            for (int j = 0; j < 4; j++)
                Ps[(r0 + i) * PSLD + c0 + j] = s[i][j];
        __syncthreads();

#pragma unroll
        for (int it = 0; it < 8; it++) {
            int flat = it * 1024 + tid * 4;
            *(float4*)&KV[flat] =
                *(const float4*)(vbase + (size_t)(j0 + (flat >> 7)) * KVF + (flat & 127));
        }
        __syncthreads();

        float f[4];
#pragma unroll
        for (int i = 0; i < 4; i++) {
            f[i] = frow[r0 + i];
#pragma unroll
            for (int j = 0; j < 8; j++) o[i][j] *= f[i];
        }
#pragma unroll 2
        for (int kk = 0; kk < BKTILE; kk++) {
            float p0 = Ps[(r0 + 0) * PSLD + kk];
            float p1 = Ps[(r0 + 1) * PSLD + kk];
            float p2 = Ps[(r0 + 2) * PSLD + kk];
            float p3 = Ps[(r0 + 3) * PSLD + kk];
            float4 va = *(const float4*)&KV[kk * 128 + tx4];
            float4 vb = *(const float4*)&KV[kk * 128 + 64 + tx4];
            float vv[8] = {va.x, va.y, va.z, va.w, vb.x, vb.y, vb.z, vb.w};
#pragma unroll
            for (int j = 0; j < 8; j++) {
                o[0][j] += p0 * vv[j];
                o[1][j] += p1 * vv[j];
                o[2][j] += p2 * vv[j];
                o[3][j] += p3 * vv[j];
            }
        }
    }

    __syncthreads();
#pragma unroll
    for (int i = 0; i < 4; i++) {
        float inv = 1.f / lrow[r0 + i];
        size_t row = (size_t)(b * SB + i0 + r0 + i);
        float* op = out + row * DIMD + h * HD + tx4;
        float4 o0 = make_float4(o[i][0] * inv, o[i][1] * inv, o[i][2] * inv, o[i][3] * inv);
        float4 o1 = make_float4(o[i][4] * inv, o[i][5] * inv, o[i][6] * inv, o[i][7] * inv);
        *(float4*)op        = o0;
        *(float4*)(op + 64) = o1;
    }
}

// ---------------- launcher ----------------
extern "C" void kernel_launch(void* const* d_in, const int* in_sizes, int n_in,
                              void* d_out, int out_size) {
    (void)in_sizes; (void)n_in; (void)out_size;
    const float* x   = (const float*)d_in[0];
    const float* Wq  = (const float*)d_in[1];
    const float* Wkv = (const float*)d_in[2];
    const float* Wo  = (const float*)d_in[3];
    const float* bo  = (const float*)d_in[4];
    float* out = (float*)d_out;

    float *qb, *kvb, *attnb;
    cudaGetSymbolAddress((void**)&qb,    g_q);
    cudaGetSymbolAddress((void**)&kvb,   g_kv);
    cudaGetSymbolAddress((void**)&attnb, g_at);
    __nv_bfloat16 *xqh, *xql, *xh, *xl, *ath, *atl, *wqh, *wql, *wkvh, *wkvl, *woh, *wol;
    cudaGetSymbolAddress((void**)&xqh, g_xq_h);  cudaGetSymbolAddress((void**)&xql, g_xq_l);
    cudaGetSymbolAddress((void**)&xh,  g_x_h);   cudaGetSymbolAddress((void**)&xl,  g_x_l);
    cudaGetSymbolAddress((void**)&ath, g_at_h);  cudaGetSymbolAddress((void**)&atl, g_at_l);
    cudaGetSymbolAddress((void**)&wqh, g_wq_h);  cudaGetSymbolAddress((void**)&wql, g_wq_l);
    cudaGetSymbolAddress((void**)&wkvh,g_wkv_h); cudaGetSymbolAddress((void**)&wkvl,g_wkv_l);
    cudaGetSymbolAddress((void**)&woh, g_wo_h);  cudaGetSymbolAddress((void**)&wol, g_wo_l);

    cudaFuncSetAttribute(attn_kernel, cudaFuncAttributeMaxDynamicSharedMemorySize,
                         ATTN_SMEM_BYTES);
    cudaFuncSetAttribute(gemm3_kernel, cudaFuncAttributeMaxDynamicSharedMemorySize,
                         GEMM_SMEM);

    // gating + operand splits
    gate_split_kernel<<<ROWS, 256>>>(x, xqh, xql);
    split_kernel<<<(ROWS * DIMD) / 1024, 256>>>(x, xh, xl, ROWS * DIMD);
    transpose_split_kernel<<<dim3(DIMD/32, DIMD/32), dim3(32, 8)>>>(Wq,  wqh,  wql,  DIMD, DIMD);
    transpose_split_kernel<<<dim3(KVF/32,  DIMD/32), dim3(32, 8)>>>(Wkv, wkvh, wkvl, DIMD, KVF);
    transpose_split_kernel<<<dim3(DIMD/32, DIMD/32), dim3(32, 8)>>>(Wo,  woh,  wol,  DIMD, DIMD);

    // projections on tensor cores
    gemm3_kernel<<<dim3(DIMD/BN, ROWS/BM), 256, GEMM_SMEM>>>(
        xqh, xql, wqh, wql, nullptr, qb, ROWS, DIMD, DIMD);
    gemm3_kernel<<<dim3(KVF/BN, ROWS/BM), 256, GEMM_SMEM>>>(
        xh, xl, wkvh, wkvl, nullptr, kvb, ROWS, KVF, DIMD);

    // attention
    vmean_kernel<<<BATCH * NKVH, 1024>>>(kvb, attnb);
    dim3 ga(31, NH, BATCH);
    attn_kernel<<<ga, 256, ATTN_SMEM_BYTES>>>(qb, kvb, attnb);

    // output projection
    split_kernel<<<(ROWS * DIMD) / 1024, 256>>>(attnb, ath, atl, ROWS * DIMD);
    gemm3_kernel<<<dim3(DIMD/BN, ROWS/BM), 256, GEMM_SMEM>>>(
        ath, atl, woh, wol, bo, out, ROWS, DIMD, DIMD);
}

// round 6
// speedup vs baseline: 2.2472x; 1.6918x over previous
#include <cuda_runtime.h>
#include <cuda_bf16.h>
#include <cstdint>
#include <stdint.h>
#include <math.h>

#define SB    2048
#define DIMD  2048
#define BATCH 2
#define NH    16
#define NKVH  4
#define HD    128
#define KVF   1024
#define ROWS  (BATCH*SB)   // 4096

// ---------------- scratch (device globals: allocation-free) ----------------
__device__ float g_q [(size_t)ROWS*DIMD];     // q projection (fp32)
__device__ float g_kv[(size_t)ROWS*KVF];      // k | v (fp32)
__device__ float g_at[(size_t)ROWS*DIMD];     // attention output (fp32)

// bf16 hi/lo splits
__device__ __nv_bfloat16 g_xq_h[(size_t)ROWS*DIMD], g_xq_l[(size_t)ROWS*DIMD];
__device__ __nv_bfloat16 g_x_h [(size_t)ROWS*DIMD], g_x_l [(size_t)ROWS*DIMD];
__device__ __nv_bfloat16 g_at_h[(size_t)ROWS*DIMD], g_at_l[(size_t)ROWS*DIMD];
// transposed weights [N][K]
__device__ __nv_bfloat16 g_wq_h [(size_t)DIMD*DIMD], g_wq_l [(size_t)DIMD*DIMD];
__device__ __nv_bfloat16 g_wkv_h[(size_t)KVF *DIMD], g_wkv_l[(size_t)KVF *DIMD];
__device__ __nv_bfloat16 g_wo_h [(size_t)DIMD*DIMD], g_wo_l [(size_t)DIMD*DIMD];

// ---------------- helpers ----------------
__device__ __forceinline__ void bfsplit(float v, __nv_bfloat16& h, __nv_bfloat16& l) {
    h = __float2bfloat16_rn(v);
    l = __float2bfloat16_rn(v - __bfloat162float(h));
}

// ---------------- kernel 1: complexity gate + split ----------------
__global__ __launch_bounds__(256) void gate_split_kernel(const float* __restrict__ x,
                                                         __nv_bfloat16* __restrict__ xh,
                                                         __nv_bfloat16* __restrict__ xl) {
    int row = blockIdx.x;
    const float* xr = x + (size_t)row * DIMD;
    float s = 0.f;
    for (int c = threadIdx.x; c < DIMD; c += 256) s += fabsf(xr[c]);
    __shared__ float red[256];
    red[threadIdx.x] = s; __syncthreads();
    for (int off = 128; off > 0; off >>= 1) {
        if (threadIdx.x < off) red[threadIdx.x] += red[threadIdx.x + off];
        __syncthreads();
    }
    float cw = 1.f / (1.f + __expf(-red[0]));
    size_t base = (size_t)row * DIMD;
    for (int c = threadIdx.x; c < DIMD; c += 256) {
        __nv_bfloat16 h, l;
        bfsplit(xr[c] * cw, h, l);
        xh[base + c] = h; xl[base + c] = l;
    }
}

// ---------------- kernel: elementwise split ----------------
__global__ __launch_bounds__(256) void split_kernel(const float* __restrict__ in,
                                                    __nv_bfloat16* __restrict__ h,
                                                    __nv_bfloat16* __restrict__ l, int n) {
    int i = (blockIdx.x * 256 + threadIdx.x) * 4;
    if (i >= n) return;
    float4 v = *(const float4*)(in + i);
    __nv_bfloat16 hh[4], ll[4];
    bfsplit(v.x, hh[0], ll[0]); bfsplit(v.y, hh[1], ll[1]);
    bfsplit(v.z, hh[2], ll[2]); bfsplit(v.w, hh[3], ll[3]);
    *(uint2*)(h + i) = *(uint2*)hh;
    *(uint2*)(l + i) = *(uint2*)ll;
}

// ---------------- kernel: transpose + split  W[K][N] -> T[N][K] ------------
__global__ __launch_bounds__(256) void transpose_split_kernel(
    const float* __restrict__ W, __nv_bfloat16* __restrict__ Th,
    __nv_bfloat16* __restrict__ Tl, int K, int N) {
    __shared__ float tile[32][33];
    int n0 = blockIdx.x * 32, k0 = blockIdx.y * 32;
    int tx = threadIdx.x, ty = threadIdx.y;
#pragma unroll
    for (int r = ty; r < 32; r += 8)
        tile[r][tx] = W[(size_t)(k0 + r) * N + n0 + tx];
    __syncthreads();
#pragma unroll
    for (int r = ty; r < 32; r += 8) {
        float v = tile[tx][r];  // element (k0+tx, n0+r)
        __nv_bfloat16 h, l; bfsplit(v, h, l);
        size_t o = (size_t)(n0 + r) * K + k0 + tx;
        Th[o] = h; Tl[o] = l;
    }
}

// ---------------- mma primitives ----------------
__device__ __forceinline__ void cp16(uint32_t dst, const void* src) {
    asm volatile("cp.async.cg.shared.global [%0], [%1], 16;\n" :: "r"(dst), "l"(src));
}
__device__ __forceinline__ void cp_commit() { asm volatile("cp.async.commit_group;\n"); }
__device__ __forceinline__ void cp_wait1() { asm volatile("cp.async.wait_group 1;\n"); }
__device__ __forceinline__ void cp_wait0() { asm volatile("cp.async.wait_group 0;\n"); }
__device__ __forceinline__ void ldsm4(uint32_t& r0, uint32_t& r1, uint32_t& r2, uint32_t& r3,
                                      uint32_t addr) {
    asm volatile("ldmatrix.sync.aligned.m8n8.x4.shared.b16 {%0,%1,%2,%3}, [%4];\n"
                 : "=r"(r0), "=r"(r1), "=r"(r2), "=r"(r3) : "r"(addr));
}
__device__ __forceinline__ void ldsm4t(uint32_t& r0, uint32_t& r1, uint32_t& r2, uint32_t& r3,
                                       uint32_t addr) {
    asm volatile("ldmatrix.sync.aligned.m8n8.x4.trans.shared.b16 {%0,%1,%2,%3}, [%4];\n"
                 : "=r"(r0), "=r"(r1), "=r"(r2), "=r"(r3) : "r"(addr));
}
__device__ __forceinline__ void mma_bf16(float* d, uint32_t a0, uint32_t a1, uint32_t a2,
                                         uint32_t a3, uint32_t b0, uint32_t b1) {
    asm volatile("mma.sync.aligned.m16n8k16.row.col.f32.bf16.bf16.f32 "
                 "{%0,%1,%2,%3}, {%4,%5,%6,%7}, {%8,%9}, {%0,%1,%2,%3};\n"
                 : "+f"(d[0]), "+f"(d[1]), "+f"(d[2]), "+f"(d[3])
                 : "r"(a0), "r"(a1), "r"(a2), "r"(a3), "r"(b0), "r"(b1));
}

// ---------------- bf16x3 tensor-core GEMM: C = A @ Bt^T (+bias) -------------
#define BM 128
#define BN 128
#define BKT32 32
#define SROWB 80
#define BUFB  (128*SROWB)
#define STAGEB (4*BUFB)
#define GEMM_SMEM (2*STAGEB)

__global__ __launch_bounds__(256) void gemm3_kernel(
    const __nv_bfloat16* __restrict__ Ahi, const __nv_bfloat16* __restrict__ Alo,
    const __nv_bfloat16* __restrict__ Bhi, const __nv_bfloat16* __restrict__ Blo,
    const float* __restrict__ bias, float* __restrict__ C,
    int M, int N, int K) {
    extern __shared__ char smem[];
    const uint32_t sb = (uint32_t)__cvta_generic_to_shared(smem);
    const int tid = threadIdx.x;
    const int lane = tid & 31, wid = tid >> 5;
    const int warpM = wid >> 2, warpN = wid & 3;
    const int mBlk = blockIdx.y * BM, nBlk = blockIdx.x * BN;

    const int lrow = tid >> 1;
    const int lc0  = (tid & 1) * 2;
    const size_t aG = (size_t)(mBlk + lrow) * K + lc0 * 8;
    const size_t bG = (size_t)(nBlk + lrow) * K + lc0 * 8;
    const uint32_t sD = sb + lrow * SROWB + lc0 * 16;

    const int aRow = warpM * 64 + (lane & 7) + ((lane >> 3) & 1) * 8;
    const uint32_t aLd = aRow * SROWB + (lane >> 4) * 16;
    const int bRow = warpN * 32 + (lane & 7) + (lane >> 4) * 8;
    const uint32_t bLd = bRow * SROWB + ((lane >> 3) & 1) * 16;

    float acc[4][4][4];
#pragma unroll
    for (int i = 0; i < 4; i++)
#pragma unroll
        for (int j = 0; j < 4; j++)
#pragma unroll
            for (int r = 0; r < 4; r++) acc[i][j][r] = 0.f;

    const int nkt = K / BKT32;

    {
        uint32_t d = sD;
        cp16(d,              Ahi + aG); cp16(d + 16,              Ahi + aG + 8);
        cp16(d + BUFB,       Alo + aG); cp16(d + BUFB + 16,       Alo + aG + 8);
        cp16(d + 2*BUFB,     Bhi + bG); cp16(d + 2*BUFB + 16,     Bhi + bG + 8);
        cp16(d + 3*BUFB,     Blo + bG); cp16(d + 3*BUFB + 16,     Blo + bG + 8);
        cp_commit();
    }

    for (int kt = 0; kt < nkt; kt++) {
        const int cur = kt & 1;
        if (kt + 1 < nkt) {
            uint32_t d = sD + (cur ^ 1) * STAGEB;
            size_t ga = aG + (size_t)(kt + 1) * 32;
            size_t gb = bG + (size_t)(kt + 1) * 32;
            cp16(d,          Ahi + ga); cp16(d + 16,          Ahi + ga + 8);
            cp16(d + BUFB,   Alo + ga); cp16(d + BUFB + 16,   Alo + ga + 8);
            cp16(d + 2*BUFB, Bhi + gb); cp16(d + 2*BUFB + 16, Bhi + gb + 8);
            cp16(d + 3*BUFB, Blo + gb); cp16(d + 3*BUFB + 16, Blo + gb + 8);
            cp_commit();
            cp_wait1();
        } else {
            cp_wait0();
        }
        __syncthreads();

        const uint32_t base = sb + cur * STAGEB;
#pragma unroll
        for (int kkB = 0; kkB < 64; kkB += 32) {
            uint32_t bh[8], bl[8];
            ldsm4(bh[0], bh[1], bh[2], bh[3], base + 2*BUFB + bLd + kkB);
            ldsm4(bh[4], bh[5], bh[6], bh[7], base + 2*BUFB + bLd + kkB + 16*SROWB);
            ldsm4(bl[0], bl[1], bl[2], bl[3], base + 3*BUFB + bLd + kkB);
            ldsm4(bl[4], bl[5], bl[6], bl[7], base + 3*BUFB + bLd + kkB + 16*SROWB);
#pragma unroll
            for (int i = 0; i < 4; i++) {
                uint32_t ah[4], al[4];
                ldsm4(ah[0], ah[1], ah[2], ah[3], base + aLd + i*16*SROWB + kkB);
                ldsm4(al[0], al[1], al[2], al[3], base + BUFB + aLd + i*16*SROWB + kkB);
#pragma unroll
                for (int j = 0; j < 4; j++) {
                    mma_bf16(acc[i][j], ah[0], ah[1], ah[2], ah[3], bh[2*j], bh[2*j+1]);
                    mma_bf16(acc[i][j], ah[0], ah[1], ah[2], ah[3], bl[2*j], bl[2*j+1]);
                    mma_bf16(acc[i][j], al[0], al[1], al[2], al[3], bh[2*j], bh[2*j+1]);
                }
            }
        }
        __syncthreads();
    }

#pragma unroll
    for (int i = 0; i < 4; i++) {
#pragma unroll
        for (int j = 0; j < 4; j++) {
            int rg = mBlk + warpM * 64 + i * 16 + (lane >> 2);
            int cg = nBlk + warpN * 32 + j * 8 + (lane & 3) * 2;
            float b0 = 0.f, b1 = 0.f;
            if (bias) { b0 = bias[cg]; b1 = bias[cg + 1]; }
            float2 v0 = make_float2(acc[i][j][0] + b0, acc[i][j][1] + b1);
            float2 v1 = make_float2(acc[i][j][2] + b0, acc[i][j][3] + b1);
            *(float2*)(C + (size_t)rg * N + cg)       = v0;
            *(float2*)(C + (size_t)(rg + 8) * N + cg) = v1;
        }
    }
}

// ---------------- kernel: v column-mean for global query rows (i<64) ------
__global__ __launch_bounds__(1024) void vmean_kernel(const float* __restrict__ kv,
                                                     float* __restrict__ out) {
    int b = blockIdx.x >> 2, kvh = blockIdx.x & 3;
    int d = threadIdx.x & 127;
    int c = threadIdx.x >> 7;
    const float* v = kv + (size_t)b * SB * KVF + NKVH * HD + kvh * HD + d;
    float s = 0.f;
    int j0 = c * 256;
#pragma unroll 8
    for (int j = j0; j < j0 + 256; j++) s += v[(size_t)j * KVF];
    __shared__ float red[8][128];
    red[c][d] = s;
    __syncthreads();
    if (c == 0) {
        float t = 0.f;
#pragma unroll
        for (int u = 0; u < 8; u++) t += red[u][d];
        t *= (1.0f / 2048.0f);
        for (int hh = 0; hh < 4; hh++) {
            int h = kvh * 4 + hh;
            for (int i = 0; i < 64; i++)
                out[((size_t)(b * SB) + i) * DIMD + h * HD + d] = t;
        }
    }
}

// ---------------- tensor-core flash attention (inverted window mask) --------
// Block: 128 threads (4 warps). Warp w owns query rows 16w..16w+15.
// smem: bf16 tiles Qh,Ql,Kh,Kl (rows [64][d 128]), Vh,Vl (rows [64][d 128]),
// all with padded row stride of 136 bf16 (272B -> conflict-free ldmatrix).
#define ASTR 136                   // bf16 per smem row
#define ATILE (64*ASTR)            // bf16 per buffer
#define AQH 0
#define AQL (ATILE*2)
#define AKH (2*ATILE*2)
#define AKL (3*ATILE*2)
#define AVH (4*ATILE*2)
#define AVL (5*ATILE*2)
#define ATTN_SMEM_BYTES (6*ATILE*2)   // 104448

__device__ __forceinline__ uint32_t pack_bf2(__nv_bfloat16 a, __nv_bfloat16 b) {
    __nv_bfloat162 t; t.x = a; t.y = b;
    return *(uint32_t*)&t;
}

__global__ __launch_bounds__(128) void attn_mma_kernel(
    const float* __restrict__ q, const float* __restrict__ kv,
    float* __restrict__ out) {
    extern __shared__ char asmem[];
    __nv_bfloat16* sB = (__nv_bfloat16*)asmem;
    const uint32_t sb = (uint32_t)__cvta_generic_to_shared(asmem);

    const int tid = threadIdx.x;
    const int lane = tid & 31, w = tid >> 5;
    const int i0 = 64 + blockIdx.x * 64;
    const int h  = blockIdx.y;
    const int b  = blockIdx.z;
    const int kvh = h >> 2;
    const float slope = exp2f(-0.5f * (float)(h + 1));
    const float scale = 0.08838834764831845f;

    const float* qbase = q  + ((size_t)(b * SB + i0) * DIMD) + h * HD;
    const float* kbase = kv + ((size_t)b * SB * KVF) + kvh * HD;
    const float* vbase = kbase + NKVH * HD;

    // load Q tile -> bf16 hi/lo smem (once)
#pragma unroll
    for (int it = 0; it < 16; it++) {
        int flat = it * 512 + tid * 4;
        int r = flat >> 7, c = flat & 127;
        float4 v = *(const float4*)(qbase + (size_t)r * DIMD + c);
        __nv_bfloat16 hh[4], ll[4];
        bfsplit(v.x, hh[0], ll[0]); bfsplit(v.y, hh[1], ll[1]);
        bfsplit(v.z, hh[2], ll[2]); bfsplit(v.w, hh[3], ll[3]);
        *(uint2*)(sB + (AQH/2) + r * ASTR + c) = *(uint2*)hh;
        *(uint2*)(sB + (AQL/2) + r * ASTR + c) = *(uint2*)ll;
    }

    // ldmatrix per-thread offsets
    const uint32_t aOff = (uint32_t)((w * 16 + (lane & 7) + ((lane >> 3) & 1) * 8) * 272
                                     + (lane >> 4) * 16);          // A (Q) base
    const uint32_t bRowOff = (uint32_t)(((lane & 7) + (lane >> 4) * 8) * 272
                                        + ((lane >> 3) & 1) * 16); // B (K) base (add g*16*272)
    const uint32_t vOff = (uint32_t)(((lane & 7) + ((lane >> 3) & 1) * 8) * 272
                                     + (lane >> 4) * 16);          // V trans base (add kk*16*272 + g*32)

    // per-thread softmax state: rows r0 = i0+16w+(lane>>2), r1 = r0+8 (replicated in quad)
    const int gi0 = i0 + w * 16 + (lane >> 2);
    const int gi1 = gi0 + 8;
    const int cb  = (lane & 3) * 2;
    float m0 = -INFINITY, m1 = -INFINITY, l0 = 0.f, l1 = 0.f;

    float o[16][4];
#pragma unroll
    for (int f = 0; f < 16; f++)
#pragma unroll
        for (int r = 0; r < 4; r++) o[f][r] = 0.f;

    for (int j0t = 64; j0t < SB; j0t += 64) {
        int mdist = max(abs(i0 - (j0t + 63)), abs((i0 + 63) - j0t));
        if (mdist <= 256) continue;

        __syncthreads();
        // load K and V tiles -> bf16 hi/lo smem
#pragma unroll
        for (int it = 0; it < 16; it++) {
            int flat = it * 512 + tid * 4;
            int r = flat >> 7, c = flat & 127;
            float4 kvv = *(const float4*)(kbase + (size_t)(j0t + r) * KVF + c);
            __nv_bfloat16 hh[4], ll[4];
            bfsplit(kvv.x, hh[0], ll[0]); bfsplit(kvv.y, hh[1], ll[1]);
            bfsplit(kvv.z, hh[2], ll[2]); bfsplit(kvv.w, hh[3], ll[3]);
            *(uint2*)(sB + (AKH/2) + r * ASTR + c) = *(uint2*)hh;
            *(uint2*)(sB + (AKL/2) + r * ASTR + c) = *(uint2*)ll;
            float4 vv = *(const float4*)(vbase + (size_t)(j0t + r) * KVF + c);
            bfsplit(vv.x, hh[0], ll[0]); bfsplit(vv.y, hh[1], ll[1]);
            bfsplit(vv.z, hh[2], ll[2]); bfsplit(vv.w, hh[3], ll[3]);
            *(uint2*)(sB + (AVH/2) + r * ASTR + c) = *(uint2*)hh;
            *(uint2*)(sB + (AVL/2) + r * ASTR + c) = *(uint2*)ll;
        }
        __syncthreads();

        // ---- S = Q K^T (bf16 x3) ----
        float sacc[8][4];
#pragma unroll
        for (int j = 0; j < 8; j++)
#pragma unroll
            for (int r = 0; r < 4; r++) sacc[j][r] = 0.f;

#pragma unroll
        for (int kk = 0; kk < 8; kk++) {
            uint32_t qh[4], ql[4];
            ldsm4(qh[0], qh[1], qh[2], qh[3], sb + AQH + aOff + kk * 32);
            ldsm4(ql[0], ql[1], ql[2], ql[3], sb + AQL + aOff + kk * 32);
#pragma unroll
            for (int g = 0; g < 4; g++) {
                uint32_t kh[4], kl[4];
                uint32_t bo = bRowOff + (uint32_t)(g * 16 * 272) + kk * 32;
                ldsm4(kh[0], kh[1], kh[2], kh[3], sb + AKH + bo);
                ldsm4(kl[0], kl[1], kl[2], kl[3], sb + AKL + bo);
                mma_bf16(sacc[2*g],   qh[0], qh[1], qh[2], qh[3], kh[0], kh[1]);
                mma_bf16(sacc[2*g],   qh[0], qh[1], qh[2], qh[3], kl[0], kl[1]);
                mma_bf16(sacc[2*g],   ql[0], ql[1], ql[2], ql[3], kh[0], kh[1]);
                mma_bf16(sacc[2*g+1], qh[0], qh[1], qh[2], qh[3], kh[2], kh[3]);
                mma_bf16(sacc[2*g+1], qh[0], qh[1], qh[2], qh[3], kl[2], kl[3]);
                mma_bf16(sacc[2*g+1], ql[0], ql[1], ql[2], ql[3], kh[2], kh[3]);
            }
        }

        // ---- mask + ALiBi + online softmax (fp32, in fragments) ----
        float tmax0 = -INFINITY, tmax1 = -INFINITY;
#pragma unroll
        for (int j = 0; j < 8; j++) {
            int gj = j0t + j * 8 + cb;
#pragma unroll
            for (int e = 0; e < 4; e++) {
                int gi = (e < 2) ? gi0 : gi1;
                int dist = abs(gi - (gj + (e & 1)));
                float val = (dist <= 256) ? -1e9f
                                          : (sacc[j][e] * scale - slope * (float)dist);
                sacc[j][e] = val;
                if (e < 2) tmax0 = fmaxf(tmax0, val);
                else       tmax1 = fmaxf(tmax1, val);
            }
        }
        tmax0 = fmaxf(tmax0, __shfl_xor_sync(0xffffffffu, tmax0, 1));
        tmax0 = fmaxf(tmax0, __shfl_xor_sync(0xffffffffu, tmax0, 2));
        tmax1 = fmaxf(tmax1, __shfl_xor_sync(0xffffffffu, tmax1, 1));
        tmax1 = fmaxf(tmax1, __shfl_xor_sync(0xffffffffu, tmax1, 2));

        float mn0 = fmaxf(m0, tmax0), mn1 = fmaxf(m1, tmax1);
        float f0 = __expf(m0 - mn0), f1 = __expf(m1 - mn1);
        float rs0 = 0.f, rs1 = 0.f;
#pragma unroll
        for (int j = 0; j < 8; j++) {
            float p0 = __expf(sacc[j][0] - mn0);
            float p1 = __expf(sacc[j][1] - mn0);
            float p2 = __expf(sacc[j][2] - mn1);
            float p3 = __expf(sacc[j][3] - mn1);
            sacc[j][0] = p0; sacc[j][1] = p1; sacc[j][2] = p2; sacc[j][3] = p3;
            rs0 += p0 + p1; rs1 += p2 + p3;
        }
        rs0 += __shfl_xor_sync(0xffffffffu, rs0, 1);
        rs0 += __shfl_xor_sync(0xffffffffu, rs0, 2);
        rs1 += __shfl_xor_sync(0xffffffffu, rs1, 1);
        rs1 += __shfl_xor_sync(0xffffffffu, rs1, 2);
        l0 = l0 * f0 + rs0; l1 = l1 * f1 + rs1;
        m0 = mn0; m1 = mn1;

        // rescale O
#pragma unroll
        for (int f = 0; f < 16; f++) {
            o[f][0] *= f0; o[f][1] *= f0;
            o[f][2] *= f1; o[f][3] *= f1;
        }

        // ---- O += P V (P split hi/lo, V split hi/lo; 3 mma) ----
#pragma unroll
        for (int kk = 0; kk < 4; kk++) {
            uint32_t pH[4], pL[4];
            {
                __nv_bfloat16 h0, l0b, h1, l1b;
                bfsplit(sacc[2*kk][0], h0, l0b);  bfsplit(sacc[2*kk][1], h1, l1b);
                pH[0] = pack_bf2(h0, h1); pL[0] = pack_bf2(l0b, l1b);
                bfsplit(sacc[2*kk][2], h0, l0b);  bfsplit(sacc[2*kk][3], h1, l1b);
                pH[1] = pack_bf2(h0, h1); pL[1] = pack_bf2(l0b, l1b);
                bfsplit(sacc[2*kk+1][0], h0, l0b); bfsplit(sacc[2*kk+1][1], h1, l1b);
                pH[2] = pack_bf2(h0, h1); pL[2] = pack_bf2(l0b, l1b);
                bfsplit(sacc[2*kk+1][2], h0, l0b); bfsplit(sacc[2*kk+1][3], h1, l1b);
                pH[3] = pack_bf2(h0, h1); pL[3] = pack_bf2(l0b, l1b);
            }
#pragma unroll
            for (int g = 0; g < 8; g++) {
                uint32_t vh[4], vl[4];
                uint32_t vo = vOff + (uint32_t)(kk * 16 * 272) + (uint32_t)(g * 32);
                ldsm4t(vh[0], vh[1], vh[2], vh[3], sb + AVH + vo);
                ldsm4t(vl[0], vl[1], vl[2], vl[3], sb + AVL + vo);
                mma_bf16(o[2*g],   pH[0], pH[1], pH[2], pH[3], vh[0], vh[1]);
                mma_bf16(o[2*g],   pH[0], pH[1], pH[2], pH[3], vl[0], vl[1]);
                mma_bf16(o[2*g],   pL[0], pL[1], pL[2], pL[3], vh[0], vh[1]);
                mma_bf16(o[2*g+1], pH[0], pH[1], pH[2], pH[3], vh[2], vh[3]);
                mma_bf16(o[2*g+1], pH[0], pH[1], pH[2], pH[3], vl[2], vl[3]);
                mma_bf16(o[2*g+1], pL[0], pL[1], pL[2], pL[3], vh[2], vh[3]);
            }
        }
    }

    // ---- epilogue: divide by l, write ----
    float inv0 = 1.f / l0, inv1 = 1.f / l1;
    size_t row0 = (size_t)(b * SB) + gi0;
    size_t row1 = (size_t)(b * SB) + gi1;
#pragma unroll
    for (int f = 0; f < 16; f++) {
        int cg = h * HD + f * 8 + cb;
        *(float2*)(out + row0 * DIMD + cg) = make_float2(o[f][0] * inv0, o[f][1] * inv0);
        *(float2*)(out + row1 * DIMD + cg) = make_float2(o[f][2] * inv1, o[f][3] * inv1);
    }
}

// ---------------- launcher ----------------
extern "C" void kernel_launch(void* const* d_in, const int* in_sizes, int n_in,
                              void* d_out, int out_size) {
    (void)in_sizes; (void)n_in; (void)out_size;
    const float* x   = (const float*)d_in[0];
    const float* Wq  = (const float*)d_in[1];
    const float* Wkv = (const float*)d_in[2];
    const float* Wo  = (const float*)d_in[3];
    const float* bo  = (const float*)d_in[4];
    float* out = (float*)d_out;

    float *qb, *kvb, *attnb;
    cudaGetSymbolAddress((void**)&qb,    g_q);
    cudaGetSymbolAddress((void**)&kvb,   g_kv);
    cudaGetSymbolAddress((void**)&attnb, g_at);
    __nv_bfloat16 *xqh, *xql, *xh, *xl, *ath, *atl, *wqh, *wql, *wkvh, *wkvl, *woh, *wol;
    cudaGetSymbolAddress((void**)&xqh, g_xq_h);  cudaGetSymbolAddress((void**)&xql, g_xq_l);
    cudaGetSymbolAddress((void**)&xh,  g_x_h);   cudaGetSymbolAddress((void**)&xl,  g_x_l);
    cudaGetSymbolAddress((void**)&ath, g_at_h);  cudaGetSymbolAddress((void**)&atl, g_at_l);
    cudaGetSymbolAddress((void**)&wqh, g_wq_h);  cudaGetSymbolAddress((void**)&wql, g_wq_l);
    cudaGetSymbolAddress((void**)&wkvh,g_wkv_h); cudaGetSymbolAddress((void**)&wkvl,g_wkv_l);
    cudaGetSymbolAddress((void**)&woh, g_wo_h);  cudaGetSymbolAddress((void**)&wol, g_wo_l);

    cudaFuncSetAttribute(attn_mma_kernel, cudaFuncAttributeMaxDynamicSharedMemorySize,
                         ATTN_SMEM_BYTES);
    cudaFuncSetAttribute(gemm3_kernel, cudaFuncAttributeMaxDynamicSharedMemorySize,
                         GEMM_SMEM);

    // gating + operand splits
    gate_split_kernel<<<ROWS, 256>>>(x, xqh, xql);
    split_kernel<<<(ROWS * DIMD) / 1024, 256>>>(x, xh, xl, ROWS * DIMD);
    transpose_split_kernel<<<dim3(DIMD/32, DIMD/32), dim3(32, 8)>>>(Wq,  wqh,  wql,  DIMD, DIMD);
    transpose_split_kernel<<<dim3(KVF/32,  DIMD/32), dim3(32, 8)>>>(Wkv, wkvh, wkvl, DIMD, KVF);
    transpose_split_kernel<<<dim3(DIMD/32, DIMD/32), dim3(32, 8)>>>(Wo,  woh,  wol,  DIMD, DIMD);

    // projections on tensor cores
    gemm3_kernel<<<dim3(DIMD/BN, ROWS/BM), 256, GEMM_SMEM>>>(
        xqh, xql, wqh, wql, nullptr, qb, ROWS, DIMD, DIMD);
    gemm3_kernel<<<dim3(KVF/BN, ROWS/BM), 256, GEMM_SMEM>>>(
        xh, xl, wkvh, wkvl, nullptr, kvb, ROWS, KVF, DIMD);

    // attention
    vmean_kernel<<<BATCH * NKVH, 1024>>>(kvb, attnb);
    dim3 ga(31, NH, BATCH);
    attn_mma_kernel<<<ga, 128, ATTN_SMEM_BYTES>>>(qb, kvb, attnb);

    // output projection
    split_kernel<<<(ROWS * DIMD) / 1024, 256>>>(attnb, ath, atl, ROWS * DIMD);
    gemm3_kernel<<<dim3(DIMD/BN, ROWS/BM), 256, GEMM_SMEM>>>(
        ath, atl, woh, wol, bo, out, ROWS, DIMD, DIMD);
}

// round 8
// speedup vs baseline: 2.2545x; 1.0032x over previous
#include <cuda_runtime.h>
#include <cuda_bf16.h>
#include <cstdint>
#include <stdint.h>
#include <math.h>

#define SB    2048
#define DIMD  2048
#define BATCH 2
#define NH    16
#define NKVH  4
#define HD    128
#define KVF   1024
#define ROWS  (BATCH*SB)   // 4096

// ---------------- scratch (device globals: allocation-free) ----------------
__device__ float g_q [(size_t)ROWS*DIMD];
__device__ float g_kv[(size_t)ROWS*KVF];
__device__ float g_at[(size_t)ROWS*DIMD];

__device__ __nv_bfloat16 g_xq_h[(size_t)ROWS*DIMD], g_xq_l[(size_t)ROWS*DIMD];
__device__ __nv_bfloat16 g_x_h [(size_t)ROWS*DIMD], g_x_l [(size_t)ROWS*DIMD];
__device__ __nv_bfloat16 g_at_h[(size_t)ROWS*DIMD], g_at_l[(size_t)ROWS*DIMD];
__device__ __nv_bfloat16 g_wq_h [(size_t)DIMD*DIMD], g_wq_l [(size_t)DIMD*DIMD];
__device__ __nv_bfloat16 g_wkv_h[(size_t)KVF *DIMD], g_wkv_l[(size_t)KVF *DIMD];
__device__ __nv_bfloat16 g_wo_h [(size_t)DIMD*DIMD], g_wo_l [(size_t)DIMD*DIMD];

// ---------------- helpers ----------------
__device__ __forceinline__ void bfsplit(float v, __nv_bfloat16& h, __nv_bfloat16& l) {
    h = __float2bfloat16_rn(v);
    l = __float2bfloat16_rn(v - __bfloat162float(h));
}

// ---------------- kernel 1: complexity gate + split ----------------
__global__ __launch_bounds__(256) void gate_split_kernel(const float* __restrict__ x,
                                                         __nv_bfloat16* __restrict__ xh,
                                                         __nv_bfloat16* __restrict__ xl) {
    int row = blockIdx.x;
    const float* xr = x + (size_t)row * DIMD;
    float s = 0.f;
    for (int c = threadIdx.x; c < DIMD; c += 256) s += fabsf(xr[c]);
    __shared__ float red[256];
    red[threadIdx.x] = s; __syncthreads();
    for (int off = 128; off > 0; off >>= 1) {
        if (threadIdx.x < off) red[threadIdx.x] += red[threadIdx.x + off];
        __syncthreads();
    }
    float cw = 1.f / (1.f + __expf(-red[0]));
    size_t base = (size_t)row * DIMD;
    for (int c = threadIdx.x; c < DIMD; c += 256) {
        __nv_bfloat16 h, l;
        bfsplit(xr[c] * cw, h, l);
        xh[base + c] = h; xl[base + c] = l;
    }
}

// ---------------- kernel: elementwise split ----------------
__global__ __launch_bounds__(256) void split_kernel(const float* __restrict__ in,
                                                    __nv_bfloat16* __restrict__ h,
                                                    __nv_bfloat16* __restrict__ l, int n) {
    int i = (blockIdx.x * 256 + threadIdx.x) * 4;
    if (i >= n) return;
    float4 v = *(const float4*)(in + i);
    __nv_bfloat16 hh[4], ll[4];
    bfsplit(v.x, hh[0], ll[0]); bfsplit(v.y, hh[1], ll[1]);
    bfsplit(v.z, hh[2], ll[2]); bfsplit(v.w, hh[3], ll[3]);
    *(uint2*)(h + i) = *(uint2*)hh;
    *(uint2*)(l + i) = *(uint2*)ll;
}

// ---------------- kernel: transpose + split  W[K][N] -> T[N][K] ------------
__global__ __launch_bounds__(256) void transpose_split_kernel(
    const float* __restrict__ W, __nv_bfloat16* __restrict__ Th,
    __nv_bfloat16* __restrict__ Tl, int K, int N) {
    __shared__ float tile[32][33];
    int n0 = blockIdx.x * 32, k0 = blockIdx.y * 32;
    int tx = threadIdx.x, ty = threadIdx.y;
#pragma unroll
    for (int r = ty; r < 32; r += 8)
        tile[r][tx] = W[(size_t)(k0 + r) * N + n0 + tx];
    __syncthreads();
#pragma unroll
    for (int r = ty; r < 32; r += 8) {
        float v = tile[tx][r];
        __nv_bfloat16 h, l; bfsplit(v, h, l);
        size_t o = (size_t)(n0 + r) * K + k0 + tx;
        Th[o] = h; Tl[o] = l;
    }
}

// ---------------- mma primitives ----------------
__device__ __forceinline__ void cp16(uint32_t dst, const void* src) {
    asm volatile("cp.async.cg.shared.global [%0], [%1], 16;\n" :: "r"(dst), "l"(src));
}
__device__ __forceinline__ void cp_commit() { asm volatile("cp.async.commit_group;\n"); }
__device__ __forceinline__ void cp_wait1() { asm volatile("cp.async.wait_group 1;\n"); }
__device__ __forceinline__ void cp_wait0() { asm volatile("cp.async.wait_group 0;\n"); }
__device__ __forceinline__ void ldsm4(uint32_t& r0, uint32_t& r1, uint32_t& r2, uint32_t& r3,
                                      uint32_t addr) {
    asm volatile("ldmatrix.sync.aligned.m8n8.x4.shared.b16 {%0,%1,%2,%3}, [%4];\n"
                 : "=r"(r0), "=r"(r1), "=r"(r2), "=r"(r3) : "r"(addr));
}
__device__ __forceinline__ void ldsm4t(uint32_t& r0, uint32_t& r1, uint32_t& r2, uint32_t& r3,
                                       uint32_t addr) {
    asm volatile("ldmatrix.sync.aligned.m8n8.x4.trans.shared.b16 {%0,%1,%2,%3}, [%4];\n"
                 : "=r"(r0), "=r"(r1), "=r"(r2), "=r"(r3) : "r"(addr));
}
__device__ __forceinline__ void mma_bf16(float* d, uint32_t a0, uint32_t a1, uint32_t a2,
                                         uint32_t a3, uint32_t b0, uint32_t b1) {
    asm volatile("mma.sync.aligned.m16n8k16.row.col.f32.bf16.bf16.f32 "
                 "{%0,%1,%2,%3}, {%4,%5,%6,%7}, {%8,%9}, {%0,%1,%2,%3};\n"
                 : "+f"(d[0]), "+f"(d[1]), "+f"(d[2]), "+f"(d[3])
                 : "r"(a0), "r"(a1), "r"(a2), "r"(a3), "r"(b0), "r"(b1));
}

// ---------------- bf16x3 tensor-core GEMM: C = A @ Bt^T (+bias) -------------
// Block tile 256x128, 8 warps (4 M x 2 N), warp tile 64x64, K-stage 32.
#define BKT32 32
#define SROWB 80                 // padded smem row stride bytes (32 bf16 + 16B pad)
#define ABUF  (256*SROWB)        // 20480 B (A hi or lo)
#define BBUF  (128*SROWB)        // 10240 B (B hi or lo)
#define STAGEB (2*ABUF + 2*BBUF) // 61440 B
#define GEMM_SMEM (2*STAGEB)     // 122880 B

__global__ __launch_bounds__(256, 1) void gemm3_kernel(
    const __nv_bfloat16* __restrict__ Ahi, const __nv_bfloat16* __restrict__ Alo,
    const __nv_bfloat16* __restrict__ Bhi, const __nv_bfloat16* __restrict__ Blo,
    const float* __restrict__ bias, float* __restrict__ C,
    int M, int N, int K) {
    extern __shared__ char smem[];
    const uint32_t sb = (uint32_t)__cvta_generic_to_shared(smem);
    const int tid = threadIdx.x;
    const int lane = tid & 31, wid = tid >> 5;
    const int warpM = wid >> 1, warpN = wid & 1;      // 4 x 2 warps -> 64x64 warp tile
    const int mBlk = blockIdx.y * 256, nBlk = blockIdx.x * 128;

    // -- load mapping --
    // A: thread t owns row t (256 rows), 4 chunks of 16B
    // B: thread t owns row t>>1 (128 rows), 2 chunks of 16B (t&1 selects pair)
    const size_t aG = (size_t)(mBlk + tid) * K;
    const int brow = tid >> 1, bc0 = (tid & 1) * 2;
    const size_t bG = (size_t)(nBlk + brow) * K + bc0 * 8;
    const uint32_t aD = sb + tid * SROWB;
    const uint32_t bD = sb + 2*ABUF + brow * SROWB + bc0 * 16;

    // -- ldmatrix per-thread bases (same 80B-row permutation as proven config) --
    const int aRow = warpM * 64 + (lane & 7) + ((lane >> 3) & 1) * 8;
    const uint32_t aLd = aRow * SROWB + (lane >> 4) * 16;
    const int bRow = warpN * 64 + (lane & 7) + (lane >> 4) * 8;
    const uint32_t bLd = bRow * SROWB + ((lane >> 3) & 1) * 16;

    float acc[4][8][4];
#pragma unroll
    for (int i = 0; i < 4; i++)
#pragma unroll
        for (int j = 0; j < 8; j++)
#pragma unroll
            for (int r = 0; r < 4; r++) acc[i][j][r] = 0.f;

    const int nkt = K / BKT32;

    // prefetch stage 0
    {
#pragma unroll
        for (int c = 0; c < 4; c++) {
            cp16(aD + c * 16,        Ahi + aG + c * 8);
            cp16(aD + ABUF + c * 16, Alo + aG + c * 8);
        }
        cp16(bD,               Bhi + bG);
        cp16(bD + 16,          Bhi + bG + 8);
        cp16(bD + BBUF,        Blo + bG);
        cp16(bD + BBUF + 16,   Blo + bG + 8);
        cp_commit();
    }

    for (int kt = 0; kt < nkt; kt++) {
        const int cur = kt & 1;
        if (kt + 1 < nkt) {
            const uint32_t so = (cur ^ 1) * STAGEB;
            const size_t off = (size_t)(kt + 1) * 32;
#pragma unroll
            for (int c = 0; c < 4; c++) {
                cp16(aD + so + c * 16,        Ahi + aG + off + c * 8);
                cp16(aD + so + ABUF + c * 16, Alo + aG + off + c * 8);
            }
            cp16(bD + so,             Bhi + bG + off);
            cp16(bD + so + 16,        Bhi + bG + off + 8);
            cp16(bD + so + BBUF,      Blo + bG + off);
            cp16(bD + so + BBUF + 16, Blo + bG + off + 8);
            cp_commit();
            cp_wait1();
        } else {
            cp_wait0();
        }
        __syncthreads();

        const uint32_t base = sb + cur * STAGEB;
#pragma unroll
        for (int kkB = 0; kkB < 64; kkB += 32) {   // two k16 halves
            uint32_t bh[16], bl[16];
#pragma unroll
            for (int g = 0; g < 4; g++) {
                uint32_t bo = base + 2*ABUF + bLd + kkB + (uint32_t)(g * 16 * SROWB);
                ldsm4(bh[4*g], bh[4*g+1], bh[4*g+2], bh[4*g+3], bo);
                ldsm4(bl[4*g], bl[4*g+1], bl[4*g+2], bl[4*g+3], bo + BBUF);
            }
#pragma unroll
            for (int i = 0; i < 4; i++) {
                uint32_t ah[4], al[4];
                uint32_t ao = base + aLd + (uint32_t)(i * 16 * SROWB) + kkB;
                ldsm4(ah[0], ah[1], ah[2], ah[3], ao);
                ldsm4(al[0], al[1], al[2], al[3], ao + ABUF);
#pragma unroll
                for (int j = 0; j < 8; j++) {
                    mma_bf16(acc[i][j], ah[0], ah[1], ah[2], ah[3], bh[2*j], bh[2*j+1]);
                    mma_bf16(acc[i][j], ah[0], ah[1], ah[2], ah[3], bl[2*j], bl[2*j+1]);
                    mma_bf16(acc[i][j], al[0], al[1], al[2], al[3], bh[2*j], bh[2*j+1]);
                }
            }
        }
        __syncthreads();
    }

    // epilogue
#pragma unroll
    for (int i = 0; i < 4; i++) {
#pragma unroll
        for (int j = 0; j < 8; j++) {
            int rg = mBlk + warpM * 64 + i * 16 + (lane >> 2);
            int cg = nBlk + warpN * 64 + j * 8 + (lane & 3) * 2;
            float b0 = 0.f, b1 = 0.f;
            if (bias) { b0 = bias[cg]; b1 = bias[cg + 1]; }
            float2 v0 = make_float2(acc[i][j][0] + b0, acc[i][j][1] + b1);
            float2 v1 = make_float2(acc[i][j][2] + b0, acc[i][j][3] + b1);
            *(float2*)(C + (size_t)rg * N + cg)       = v0;
            *(float2*)(C + (size_t)(rg + 8) * N + cg) = v1;
        }
    }
}

// ---------------- kernel: v column-mean for global query rows (i<64) ------
__global__ __launch_bounds__(1024) void vmean_kernel(const float* __restrict__ kv,
                                                     float* __restrict__ out) {
    int b = blockIdx.x >> 2, kvh = blockIdx.x & 3;
    int d = threadIdx.x & 127;
    int c = threadIdx.x >> 7;
    const float* v = kv + (size_t)b * SB * KVF + NKVH * HD + kvh * HD + d;
    float s = 0.f;
    int j0 = c * 256;
#pragma unroll 8
    for (int j = j0; j < j0 + 256; j++) s += v[(size_t)j * KVF];
    __shared__ float red[8][128];
    red[c][d] = s;
    __syncthreads();
    if (c == 0) {
        float t = 0.f;
#pragma unroll
        for (int u = 0; u < 8; u++) t += red[u][d];
        t *= (1.0f / 2048.0f);
        for (int hh = 0; hh < 4; hh++) {
            int h = kvh * 4 + hh;
            for (int i = 0; i < 64; i++)
                out[((size_t)(b * SB) + i) * DIMD + h * HD + d] = t;
        }
    }
}

// ---------------- tensor-core flash attention (inverted window mask) --------
#define ASTR 136
#define ATILE (64*ASTR)
#define AQH 0
#define AQL (ATILE*2)
#define AKH (2*ATILE*2)
#define AKL (3*ATILE*2)
#define AVH (4*ATILE*2)
#define AVL (5*ATILE*2)
#define ATTN_SMEM_BYTES (6*ATILE*2)

__device__ __forceinline__ uint32_t pack_bf2(__nv_bfloat16 a, __nv_bfloat16 b) {
    __nv_bfloat162 t; t.x = a; t.y = b;
    return *(uint32_t*)&t;
}

__global__ __launch_bounds__(128) void attn_mma_kernel(
    const float* __restrict__ q, const float* __restrict__ kv,
    float* __restrict__ out) {
    extern __shared__ char asmem[];
    __nv_bfloat16* sB = (__nv_bfloat16*)asmem;
    const uint32_t sb = (uint32_t)__cvta_generic_to_shared(asmem);

    const int tid = threadIdx.x;
    const int lane = tid & 31, w = tid >> 5;
    const int i0 = 64 + blockIdx.x * 64;
    const int h  = blockIdx.y;
    const int b  = blockIdx.z;
    const int kvh = h >> 2;
    const float slope = exp2f(-0.5f * (float)(h + 1));
    const float scale = 0.08838834764831845f;

    const float* qbase = q  + ((size_t)(b * SB + i0) * DIMD) + h * HD;
    const float* kbase = kv + ((size_t)b * SB * KVF) + kvh * HD;
    const float* vbase = kbase + NKVH * HD;

#pragma unroll
    for (int it = 0; it < 16; it++) {
        int flat = it * 512 + tid * 4;
        int r = flat >> 7, c = flat & 127;
        float4 v = *(const float4*)(qbase + (size_t)r * DIMD + c);
        __nv_bfloat16 hh[4], ll[4];
        bfsplit(v.x, hh[0], ll[0]); bfsplit(v.y, hh[1], ll[1]);
        bfsplit(v.z, hh[2], ll[2]); bfsplit(v.w, hh[3], ll[3]);
        *(uint2*)(sB + (AQH/2) + r * ASTR + c) = *(uint2*)hh;
        *(uint2*)(sB + (AQL/2) + r * ASTR + c) = *(uint2*)ll;
    }

    const uint32_t aOff = (uint32_t)((w * 16 + (lane & 7) + ((lane >> 3) & 1) * 8) * 272
                                     + (lane >> 4) * 16);
    const uint32_t bRowOff = (uint32_t)(((lane & 7) + (lane >> 4) * 8) * 272
                                        + ((lane >> 3) & 1) * 16);
    const uint32_t vOff = (uint32_t)(((lane & 7) + ((lane >> 3) & 1) * 8) * 272
                                     + (lane >> 4) * 16);

    const int gi0 = i0 + w * 16 + (lane >> 2);
    const int gi1 = gi0 + 8;
    const int cb  = (lane & 3) * 2;
    float m0 = -INFINITY, m1 = -INFINITY, l0 = 0.f, l1 = 0.f;

    float o[16][4];
#pragma unroll
    for (int f = 0; f < 16; f++)
#pragma unroll
        for (int r = 0; r < 4; r++) o[f][r] = 0.f;

    for (int j0t = 64; j0t < SB; j0t += 64) {
        int mdist = max(abs(i0 - (j0t + 63)), abs((i0 + 63) - j0t));
        if (mdist <= 256) continue;

        __syncthreads();
#pragma unroll
        for (int it = 0; it < 16; it++) {
            int flat = it * 512 + tid * 4;
            int r = flat >> 7, c = flat & 127;
            float4 kvv = *(const float4*)(kbase + (size_t)(j0t + r) * KVF + c);
            __nv_bfloat16 hh[4], ll[4];
            bfsplit(kvv.x, hh[0], ll[0]); bfsplit(kvv.y, hh[1], ll[1]);
            bfsplit(kvv.z, hh[2], ll[2]); bfsplit(kvv.w, hh[3], ll[3]);
            *(uint2*)(sB + (AKH/2) + r * ASTR + c) = *(uint2*)hh;
            *(uint2*)(sB + (AKL/2) + r * ASTR + c) = *(uint2*)ll;
            float4 vv = *(const float4*)(vbase + (size_t)(j0t + r) * KVF + c);
            bfsplit(vv.x, hh[0], ll[0]); bfsplit(vv.y, hh[1], ll[1]);
            bfsplit(vv.z, hh[2], ll[2]); bfsplit(vv.w, hh[3], ll[3]);
            *(uint2*)(sB + (AVH/2) + r * ASTR + c) = *(uint2*)hh;
            *(uint2*)(sB + (AVL/2) + r * ASTR + c) = *(uint2*)ll;
        }
        __syncthreads();

        float sacc[8][4];
#pragma unroll
        for (int j = 0; j < 8; j++)
#pragma unroll
            for (int r = 0; r < 4; r++) sacc[j][r] = 0.f;

#pragma unroll
        for (int kk = 0; kk < 8; kk++) {
            uint32_t qh[4], ql[4];
            ldsm4(qh[0], qh[1], qh[2], qh[3], sb + AQH + aOff + kk * 32);
            ldsm4(ql[0], ql[1], ql[2], ql[3], sb + AQL + aOff + kk * 32);
#pragma unroll
            for (int g = 0; g < 4; g++) {
                uint32_t kh[4], kl[4];
                uint32_t bo = bRowOff + (uint32_t)(g * 16 * 272) + kk * 32;
                ldsm4(kh[0], kh[1], kh[2], kh[3], sb + AKH + bo);
                ldsm4(kl[0], kl[1], kl[2], kl[3], sb + AKL + bo);
                mma_bf16(sacc[2*g],   qh[0], qh[1], qh[2], qh[3], kh[0], kh[1]);
                mma_bf16(sacc[2*g],   qh[0], qh[1], qh[2], qh[3], kl[0], kl[1]);
                mma_bf16(sacc[2*g],   ql[0], ql[1], ql[2], ql[3], kh[0], kh[1]);
                mma_bf16(sacc[2*g+1], qh[0], qh[1], qh[2], qh[3], kh[2], kh[3]);
                mma_bf16(sacc[2*g+1], qh[0], qh[1], qh[2], qh[3], kl[2], kl[3]);
                mma_bf16(sacc[2*g+1], ql[0], ql[1], ql[2], ql[3], kh[2], kh[3]);
            }
        }

        float tmax0 = -INFINITY, tmax1 = -INFINITY;
#pragma unroll
        for (int j = 0; j < 8; j++) {
            int gj = j0t + j * 8 + cb;
#pragma unroll
            for (int e = 0; e < 4; e++) {
                int gi = (e < 2) ? gi0 : gi1;
                int dist = abs(gi - (gj + (e & 1)));
                float val = (dist <= 256) ? -1e9f
                                          : (sacc[j][e] * scale - slope * (float)dist);
                sacc[j][e] = val;
                if (e < 2) tmax0 = fmaxf(tmax0, val);
                else       tmax1 = fmaxf(tmax1, val);
            }
        }
        tmax0 = fmaxf(tmax0, __shfl_xor_sync(0xffffffffu, tmax0, 1));
        tmax0 = fmaxf(tmax0, __shfl_xor_sync(0xffffffffu, tmax0, 2));
        tmax1 = fmaxf(tmax1, __shfl_xor_sync(0xffffffffu, tmax1, 1));
        tmax1 = fmaxf(tmax1, __shfl_xor_sync(0xffffffffu, tmax1, 2));

        float mn0 = fmaxf(m0, tmax0), mn1 = fmaxf(m1, tmax1);
        float f0 = __expf(m0 - mn0), f1 = __expf(m1 - mn1);
        float rs0 = 0.f, rs1 = 0.f;
#pragma unroll
        for (int j = 0; j < 8; j++) {
            float p0 = __expf(sacc[j][0] - mn0);
            float p1 = __expf(sacc[j][1] - mn0);
            float p2 = __expf(sacc[j][2] - mn1);
            float p3 = __expf(sacc[j][3] - mn1);
            sacc[j][0] = p0; sacc[j][1] = p1; sacc[j][2] = p2; sacc[j][3] = p3;
            rs0 += p0 + p1; rs1 += p2 + p3;
        }
        rs0 += __shfl_xor_sync(0xffffffffu, rs0, 1);
        rs0 += __shfl_xor_sync(0xffffffffu, rs0, 2);
        rs1 += __shfl_xor_sync(0xffffffffu, rs1, 1);
        rs1 += __shfl_xor_sync(0xffffffffu, rs1, 2);
        l0 = l0 * f0 + rs0; l1 = l1 * f1 + rs1;
        m0 = mn0; m1 = mn1;

#pragma unroll
        for (int f = 0; f < 16; f++) {
            o[f][0] *= f0; o[f][1] *= f0;
            o[f][2] *= f1; o[f][3] *= f1;
        }

#pragma unroll
        for (int kk = 0; kk < 4; kk++) {
            uint32_t pH[4], pL[4];
            {
                __nv_bfloat16 h0, l0b, h1, l1b;
                bfsplit(sacc[2*kk][0], h0, l0b);  bfsplit(sacc[2*kk][1], h1, l1b);
                pH[0] = pack_bf2(h0, h1); pL[0] = pack_bf2(l0b, l1b);
                bfsplit(sacc[2*kk][2], h0, l0b);  bfsplit(sacc[2*kk][3], h1, l1b);
                pH[1] = pack_bf2(h0, h1); pL[1] = pack_bf2(l0b, l1b);
                bfsplit(sacc[2*kk+1][0], h0, l0b); bfsplit(sacc[2*kk+1][1], h1, l1b);
                pH[2] = pack_bf2(h0, h1); pL[2] = pack_bf2(l0b, l1b);
                bfsplit(sacc[2*kk+1][2], h0, l0b); bfsplit(sacc[2*kk+1][3], h1, l1b);
                pH[3] = pack_bf2(h0, h1); pL[3] = pack_bf2(l0b, l1b);
            }
#pragma unroll
            for (int g = 0; g < 8; g++) {
                uint32_t vh[4], vl[4];
                uint32_t vo = vOff + (uint32_t)(kk * 16 * 272) + (uint32_t)(g * 32);
                ldsm4t(vh[0], vh[1], vh[2], vh[3], sb + AVH + vo);
                ldsm4t(vl[0], vl[1], vl[2], vl[3], sb + AVL + vo);
                mma_bf16(o[2*g],   pH[0], pH[1], pH[2], pH[3], vh[0], vh[1]);
                mma_bf16(o[2*g],   pH[0], pH[1], pH[2], pH[3], vl[0], vl[1]);
                mma_bf16(o[2*g],   pL[0], pL[1], pL[2], pL[3], vh[0], vh[1]);
                mma_bf16(o[2*g+1], pH[0], pH[1], pH[2], pH[3], vh[2], vh[3]);
                mma_bf16(o[2*g+1], pH[0], pH[1], pH[2], pH[3], vl[2], vl[3]);
                mma_bf16(o[2*g+1], pL[0], pL[1], pL[2], pL[3], vh[2], vh[3]);
            }
        }
    }

    float inv0 = 1.f / l0, inv1 = 1.f / l1;
    size_t row0 = (size_t)(b * SB) + gi0;
    size_t row1 = (size_t)(b * SB) + gi1;
#pragma unroll
    for (int f = 0; f < 16; f++) {
        int cg = h * HD + f * 8 + cb;
        *(float2*)(out + row0 * DIMD + cg) = make_float2(o[f][0] * inv0, o[f][1] * inv0);
        *(float2*)(out + row1 * DIMD + cg) = make_float2(o[f][2] * inv1, o[f][3] * inv1);
    }
}

// ---------------- launcher ----------------
extern "C" void kernel_launch(void* const* d_in, const int* in_sizes, int n_in,
                              void* d_out, int out_size) {
    (void)in_sizes; (void)n_in; (void)out_size;
    const float* x   = (const float*)d_in[0];
    const float* Wq  = (const float*)d_in[1];
    const float* Wkv = (const float*)d_in[2];
    const float* Wo  = (const float*)d_in[3];
    const float* bo  = (const float*)d_in[4];
    float* out = (float*)d_out;

    float *qb, *kvb, *attnb;
    cudaGetSymbolAddress((void**)&qb,    g_q);
    cudaGetSymbolAddress((void**)&kvb,   g_kv);
    cudaGetSymbolAddress((void**)&attnb, g_at);
    __nv_bfloat16 *xqh, *xql, *xh, *xl, *ath, *atl, *wqh, *wql, *wkvh, *wkvl, *woh, *wol;
    cudaGetSymbolAddress((void**)&xqh, g_xq_h);  cudaGetSymbolAddress((void**)&xql, g_xq_l);
    cudaGetSymbolAddress((void**)&xh,  g_x_h);   cudaGetSymbolAddress((void**)&xl,  g_x_l);
    cudaGetSymbolAddress((void**)&ath, g_at_h);  cudaGetSymbolAddress((void**)&atl, g_at_l);
    cudaGetSymbolAddress((void**)&wqh, g_wq_h);  cudaGetSymbolAddress((void**)&wql, g_wq_l);
    cudaGetSymbolAddress((void**)&wkvh,g_wkv_h); cudaGetSymbolAddress((void**)&wkvl,g_wkv_l);
    cudaGetSymbolAddress((void**)&woh, g_wo_h);  cudaGetSymbolAddress((void**)&wol, g_wo_l);

    cudaFuncSetAttribute(attn_mma_kernel, cudaFuncAttributeMaxDynamicSharedMemorySize,
                         ATTN_SMEM_BYTES);
    cudaFuncSetAttribute(gemm3_kernel, cudaFuncAttributeMaxDynamicSharedMemorySize,
                         GEMM_SMEM);

    // gating + operand splits
    gate_split_kernel<<<ROWS, 256>>>(x, xqh, xql);
    split_kernel<<<(ROWS * DIMD) / 1024, 256>>>(x, xh, xl, ROWS * DIMD);
    transpose_split_kernel<<<dim3(DIMD/32, DIMD/32), dim3(32, 8)>>>(Wq,  wqh,  wql,  DIMD, DIMD);
    transpose_split_kernel<<<dim3(KVF/32,  DIMD/32), dim3(32, 8)>>>(Wkv, wkvh, wkvl, DIMD, KVF);
    transpose_split_kernel<<<dim3(DIMD/32, DIMD/32), dim3(32, 8)>>>(Wo,  woh,  wol,  DIMD, DIMD);

    // projections on tensor cores
    gemm3_kernel<<<dim3(DIMD/128, ROWS/256), 256, GEMM_SMEM>>>(
        xqh, xql, wqh, wql, nullptr, qb, ROWS, DIMD, DIMD);
    gemm3_kernel<<<dim3(KVF/128, ROWS/256), 256, GEMM_SMEM>>>(
        xh, xl, wkvh, wkvl, nullptr, kvb, ROWS, KVF, DIMD);

    // attention
    vmean_kernel<<<BATCH * NKVH, 1024>>>(kvb, attnb);
    dim3 ga(31, NH, BATCH);
    attn_mma_kernel<<<ga, 128, ATTN_SMEM_BYTES>>>(qb, kvb, attnb);

    // output projection
    split_kernel<<<(ROWS * DIMD) / 1024, 256>>>(attnb, ath, atl, ROWS * DIMD);
    gemm3_kernel<<<dim3(DIMD/128, ROWS/256), 256, GEMM_SMEM>>>(
        ath, atl, woh, wol, bo, out, ROWS, DIMD, DIMD);
}

// round 10
// speedup vs baseline: 2.6018x; 1.1541x over previous
#include <cuda_runtime.h>
#include <cuda_bf16.h>
#include <cuda_fp16.h>
#include <cstdint>
#include <stdint.h>
#include <math.h>

#define SB    2048
#define DIMD  2048
#define BATCH 2
#define NH    16
#define NKVH  4
#define HD    128
#define KVF   1024
#define ROWS  (BATCH*SB)   // 4096

// ---------------- scratch (device globals: allocation-free) ----------------
__device__ float g_q [(size_t)ROWS*DIMD];
__device__ float g_kv[(size_t)ROWS*KVF];

// reused buffers (declared bf16; fp16 users reinterpret — same element size)
__device__ __nv_bfloat16 g_xq_h[(size_t)ROWS*DIMD];            // fp16 xq (gated)
__device__ __nv_bfloat16 g_x_h [(size_t)ROWS*DIMD];            // fp16 x
__device__ __nv_bfloat16 g_at_h[(size_t)ROWS*DIMD], g_at_l[(size_t)ROWS*DIMD]; // bf16 at hi/lo
__device__ __nv_bfloat16 g_wq_h [(size_t)DIMD*DIMD], g_wq_l [(size_t)DIMD*DIMD]; // fp16 WqT hi/lo
__device__ __nv_bfloat16 g_wkv_h[(size_t)KVF *DIMD], g_wkv_l[(size_t)KVF *DIMD]; // fp16 WkvT hi/lo
__device__ __nv_bfloat16 g_wo_h [(size_t)DIMD*DIMD], g_wo_l [(size_t)DIMD*DIMD]; // bf16 WoT hi/lo

// ---------------- helpers ----------------
__device__ __forceinline__ void bfsplit(float v, __nv_bfloat16& h, __nv_bfloat16& l) {
    h = __float2bfloat16_rn(v);
    l = __float2bfloat16_rn(v - __bfloat162float(h));
}
__device__ __forceinline__ void hsplit(float v, __half& h, __half& l) {
    h = __float2half_rn(v);
    l = __float2half_rn(v - __half2float(h));
}
__device__ __forceinline__ uint32_t pack_bf2(__nv_bfloat16 a, __nv_bfloat16 b) {
    __nv_bfloat162 t; t.x = a; t.y = b;
    return *(uint32_t*)&t;
}

// ---------------- kernel 1: complexity gate -> fp16 xq AND fp16 x ----------
__global__ __launch_bounds__(256) void gate_h_kernel(const float* __restrict__ x,
                                                     __half* __restrict__ xqh,
                                                     __half* __restrict__ xh) {
    int row = blockIdx.x;
    const float* xr = x + (size_t)row * DIMD;
    float s = 0.f;
    for (int c = threadIdx.x; c < DIMD; c += 256) s += fabsf(xr[c]);
    __shared__ float red[256];
    red[threadIdx.x] = s; __syncthreads();
    for (int off = 128; off > 0; off >>= 1) {
        if (threadIdx.x < off) red[threadIdx.x] += red[threadIdx.x + off];
        __syncthreads();
    }
    float cw = 1.f / (1.f + __expf(-red[0]));
    size_t base = (size_t)row * DIMD;
    for (int c = threadIdx.x; c < DIMD; c += 256) {
        float v = xr[c];
        xh [base + c] = __float2half_rn(v);
        xqh[base + c] = __float2half_rn(v * cw);
    }
}

// ---------------- transpose+split W[K][N] -> T[N][K], bf16 hi/lo -----------
__global__ __launch_bounds__(256) void transpose_split_kernel(
    const float* __restrict__ W, __nv_bfloat16* __restrict__ Th,
    __nv_bfloat16* __restrict__ Tl, int K, int N) {
    __shared__ float tile[32][33];
    int n0 = blockIdx.x * 32, k0 = blockIdx.y * 32;
    int tx = threadIdx.x, ty = threadIdx.y;
#pragma unroll
    for (int r = ty; r < 32; r += 8)
        tile[r][tx] = W[(size_t)(k0 + r) * N + n0 + tx];
    __syncthreads();
#pragma unroll
    for (int r = ty; r < 32; r += 8) {
        float v = tile[tx][r];
        __nv_bfloat16 h, l; bfsplit(v, h, l);
        size_t o = (size_t)(n0 + r) * K + k0 + tx;
        Th[o] = h; Tl[o] = l;
    }
}

// ---------------- transpose+split W[K][N] -> T[N][K], fp16 hi/lo -----------
__global__ __launch_bounds__(256) void transpose_split_h_kernel(
    const float* __restrict__ W, __half* __restrict__ Th,
    __half* __restrict__ Tl, int K, int N) {
    __shared__ float tile[32][33];
    int n0 = blockIdx.x * 32, k0 = blockIdx.y * 32;
    int tx = threadIdx.x, ty = threadIdx.y;
#pragma unroll
    for (int r = ty; r < 32; r += 8)
        tile[r][tx] = W[(size_t)(k0 + r) * N + n0 + tx];
    __syncthreads();
#pragma unroll
    for (int r = ty; r < 32; r += 8) {
        float v = tile[tx][r];
        __half h, l; hsplit(v, h, l);
        size_t o = (size_t)(n0 + r) * K + k0 + tx;
        Th[o] = h; Tl[o] = l;
    }
}

// ---------------- mma primitives ----------------
__device__ __forceinline__ void cp16(uint32_t dst, const void* src) {
    asm volatile("cp.async.cg.shared.global [%0], [%1], 16;\n" :: "r"(dst), "l"(src));
}
__device__ __forceinline__ void cp_commit() { asm volatile("cp.async.commit_group;\n"); }
__device__ __forceinline__ void cp_wait1() { asm volatile("cp.async.wait_group 1;\n"); }
__device__ __forceinline__ void cp_wait0() { asm volatile("cp.async.wait_group 0;\n"); }
__device__ __forceinline__ void ldsm4(uint32_t& r0, uint32_t& r1, uint32_t& r2, uint32_t& r3,
                                      uint32_t addr) {
    asm volatile("ldmatrix.sync.aligned.m8n8.x4.shared.b16 {%0,%1,%2,%3}, [%4];\n"
                 : "=r"(r0), "=r"(r1), "=r"(r2), "=r"(r3) : "r"(addr));
}
__device__ __forceinline__ void ldsm4t(uint32_t& r0, uint32_t& r1, uint32_t& r2, uint32_t& r3,
                                       uint32_t addr) {
    asm volatile("ldmatrix.sync.aligned.m8n8.x4.trans.shared.b16 {%0,%1,%2,%3}, [%4];\n"
                 : "=r"(r0), "=r"(r1), "=r"(r2), "=r"(r3) : "r"(addr));
}
__device__ __forceinline__ void mma_bf16(float* d, uint32_t a0, uint32_t a1, uint32_t a2,
                                         uint32_t a3, uint32_t b0, uint32_t b1) {
    asm volatile("mma.sync.aligned.m16n8k16.row.col.f32.bf16.bf16.f32 "
                 "{%0,%1,%2,%3}, {%4,%5,%6,%7}, {%8,%9}, {%0,%1,%2,%3};\n"
                 : "+f"(d[0]), "+f"(d[1]), "+f"(d[2]), "+f"(d[3])
                 : "r"(a0), "r"(a1), "r"(a2), "r"(a3), "r"(b0), "r"(b1));
}
__device__ __forceinline__ void mma_f16(float* d, uint32_t a0, uint32_t a1, uint32_t a2,
                                        uint32_t a3, uint32_t b0, uint32_t b1) {
    asm volatile("mma.sync.aligned.m16n8k16.row.col.f32.f16.f16.f32 "
                 "{%0,%1,%2,%3}, {%4,%5,%6,%7}, {%8,%9}, {%0,%1,%2,%3};\n"
                 : "+f"(d[0]), "+f"(d[1]), "+f"(d[2]), "+f"(d[3])
                 : "r"(a0), "r"(a1), "r"(a2), "r"(a3), "r"(b0), "r"(b1));
}

// ---------------- shared tile constants (256x128 block, 8 warps 64x64) ------
#define SROWB 80                 // padded smem row stride bytes
#define ABUF  (256*SROWB)        // 20480 B
#define BBUF  (128*SROWB)        // 10240 B
#define STAGEB  (2*ABUF + 2*BBUF)   // bf16x3 stage: Ah|Al|Bh|Bl = 61440
#define GEMM_SMEM (2*STAGEB)        // 122880
#define STAGE2B (ABUF + 2*BBUF)     // fp16x2 stage: A|Bh|Bl = 40960
#define GEMM2_SMEM (2*STAGE2B)      // 81920

// ---------------- fp16 2-product GEMM: C = A @ (Bh+Bl)^T --------------------
__global__ __launch_bounds__(256, 1) void gemm2h_kernel(
    const __half* __restrict__ A,
    const __half* __restrict__ Bhi, const __half* __restrict__ Blo,
    float* __restrict__ C, int M, int N, int K) {
    extern __shared__ char smem[];
    const uint32_t sb = (uint32_t)__cvta_generic_to_shared(smem);
    const int tid = threadIdx.x;
    const int lane = tid & 31, wid = tid >> 5;
    const int warpM = wid >> 1, warpN = wid & 1;
    const int mBlk = blockIdx.y * 256, nBlk = blockIdx.x * 128;

    const size_t aG = (size_t)(mBlk + tid) * K;
    const int brow = tid >> 1, bc0 = (tid & 1) * 2;
    const size_t bG = (size_t)(nBlk + brow) * K + bc0 * 8;
    const uint32_t aD = sb + tid * SROWB;
    const uint32_t bD = sb + ABUF + brow * SROWB + bc0 * 16;

    const int aRow = warpM * 64 + (lane & 7) + ((lane >> 3) & 1) * 8;
    const uint32_t aLd = aRow * SROWB + (lane >> 4) * 16;
    const int bRow = warpN * 64 + (lane & 7) + (lane >> 4) * 8;
    const uint32_t bLd = bRow * SROWB + ((lane >> 3) & 1) * 16;

    float acc[4][8][4];
#pragma unroll
    for (int i = 0; i < 4; i++)
#pragma unroll
        for (int j = 0; j < 8; j++)
#pragma unroll
            for (int r = 0; r < 4; r++) acc[i][j][r] = 0.f;

    const int nkt = K / 32;

    {
#pragma unroll
        for (int c = 0; c < 4; c++) cp16(aD + c * 16, A + aG + c * 8);
        cp16(bD,             Bhi + bG);
        cp16(bD + 16,        Bhi + bG + 8);
        cp16(bD + BBUF,      Blo + bG);
        cp16(bD + BBUF + 16, Blo + bG + 8);
        cp_commit();
    }

    for (int kt = 0; kt < nkt; kt++) {
        const int cur = kt & 1;
        if (kt + 1 < nkt) {
            const uint32_t so = (cur ^ 1) * STAGE2B;
            const size_t off = (size_t)(kt + 1) * 32;
#pragma unroll
            for (int c = 0; c < 4; c++) cp16(aD + so + c * 16, A + aG + off + c * 8);
            cp16(bD + so,             Bhi + bG + off);
            cp16(bD + so + 16,        Bhi + bG + off + 8);
            cp16(bD + so + BBUF,      Blo + bG + off);
            cp16(bD + so + BBUF + 16, Blo + bG + off + 8);
            cp_commit();
            cp_wait1();
        } else {
            cp_wait0();
        }
        __syncthreads();

        const uint32_t base = sb + cur * STAGE2B;
#pragma unroll
        for (int kkB = 0; kkB < 64; kkB += 32) {
            uint32_t bh[16], bl[16];
#pragma unroll
            for (int g = 0; g < 4; g++) {
                uint32_t bo = base + ABUF + bLd + kkB + (uint32_t)(g * 16 * SROWB);
                ldsm4(bh[4*g], bh[4*g+1], bh[4*g+2], bh[4*g+3], bo);
                ldsm4(bl[4*g], bl[4*g+1], bl[4*g+2], bl[4*g+3], bo + BBUF);
            }
#pragma unroll
            for (int i = 0; i < 4; i++) {
                uint32_t ah[4];
                ldsm4(ah[0], ah[1], ah[2], ah[3],
                      base + aLd + (uint32_t)(i * 16 * SROWB) + kkB);
#pragma unroll
                for (int j = 0; j < 8; j++) {
                    mma_f16(acc[i][j], ah[0], ah[1], ah[2], ah[3], bh[2*j], bh[2*j+1]);
                    mma_f16(acc[i][j], ah[0], ah[1], ah[2], ah[3], bl[2*j], bl[2*j+1]);
                }
            }
        }
        __syncthreads();
    }

#pragma unroll
    for (int i = 0; i < 4; i++) {
#pragma unroll
        for (int j = 0; j < 8; j++) {
            int rg = mBlk + warpM * 64 + i * 16 + (lane >> 2);
            int cg = nBlk + warpN * 64 + j * 8 + (lane & 3) * 2;
            *(float2*)(C + (size_t)rg * N + cg)       = make_float2(acc[i][j][0], acc[i][j][1]);
            *(float2*)(C + (size_t)(rg + 8) * N + cg) = make_float2(acc[i][j][2], acc[i][j][3]);
        }
    }
}

// ---------------- bf16x3 GEMM (Wo path): C = A @ Bt^T + bias ---------------
__global__ __launch_bounds__(256, 1) void gemm3_kernel(
    const __nv_bfloat16* __restrict__ Ahi, const __nv_bfloat16* __restrict__ Alo,
    const __nv_bfloat16* __restrict__ Bhi, const __nv_bfloat16* __restrict__ Blo,
    const float* __restrict__ bias, float* __restrict__ C,
    int M, int N, int K) {
    extern __shared__ char smem[];
    const uint32_t sb = (uint32_t)__cvta_generic_to_shared(smem);
    const int tid = threadIdx.x;
    const int lane = tid & 31, wid = tid >> 5;
    const int warpM = wid >> 1, warpN = wid & 1;
    const int mBlk = blockIdx.y * 256, nBlk = blockIdx.x * 128;

    const size_t aG = (size_t)(mBlk + tid) * K;
    const int brow = tid >> 1, bc0 = (tid & 1) * 2;
    const size_t bG = (size_t)(nBlk + brow) * K + bc0 * 8;
    const uint32_t aD = sb + tid * SROWB;
    const uint32_t bD = sb + 2*ABUF + brow * SROWB + bc0 * 16;

    const int aRow = warpM * 64 + (lane & 7) + ((lane >> 3) & 1) * 8;
    const uint32_t aLd = aRow * SROWB + (lane >> 4) * 16;
    const int bRow = warpN * 64 + (lane & 7) + (lane >> 4) * 8;
    const uint32_t bLd = bRow * SROWB + ((lane >> 3) & 1) * 16;

    float acc[4][8][4];
#pragma unroll
    for (int i = 0; i < 4; i++)
#pragma unroll
        for (int j = 0; j < 8; j++)
#pragma unroll
            for (int r = 0; r < 4; r++) acc[i][j][r] = 0.f;

    const int nkt = K / 32;

    {
#pragma unroll
        for (int c = 0; c < 4; c++) {
            cp16(aD + c * 16,        Ahi + aG + c * 8);
            cp16(aD + ABUF + c * 16, Alo + aG + c * 8);
        }
        cp16(bD,               Bhi + bG);
        cp16(bD + 16,          Bhi + bG + 8);
        cp16(bD + BBUF,        Blo + bG);
        cp16(bD + BBUF + 16,   Blo + bG + 8);
        cp_commit();
    }

    for (int kt = 0; kt < nkt; kt++) {
        const int cur = kt & 1;
        if (kt + 1 < nkt) {
            const uint32_t so = (cur ^ 1) * STAGEB;
            const size_t off = (size_t)(kt + 1) * 32;
#pragma unroll
            for (int c = 0; c < 4; c++) {
                cp16(aD + so + c * 16,        Ahi + aG + off + c * 8);
                cp16(aD + so + ABUF + c * 16, Alo + aG + off + c * 8);
            }
            cp16(bD + so,             Bhi + bG + off);
            cp16(bD + so + 16,        Bhi + bG + off + 8);
            cp16(bD + so + BBUF,      Blo + bG + off);
            cp16(bD + so + BBUF + 16, Blo + bG + off + 8);
            cp_commit();
            cp_wait1();
        } else {
            cp_wait0();
        }
        __syncthreads();

        const uint32_t base = sb + cur * STAGEB;
#pragma unroll
        for (int kkB = 0; kkB < 64; kkB += 32) {
            uint32_t bh[16], bl[16];
#pragma unroll
            for (int g = 0; g < 4; g++) {
                uint32_t bo = base + 2*ABUF + bLd + kkB + (uint32_t)(g * 16 * SROWB);
                ldsm4(bh[4*g], bh[4*g+1], bh[4*g+2], bh[4*g+3], bo);
                ldsm4(bl[4*g], bl[4*g+1], bl[4*g+2], bl[4*g+3], bo + BBUF);
            }
#pragma unroll
            for (int i = 0; i < 4; i++) {
                uint32_t ah[4], al[4];
                uint32_t ao = base + aLd + (uint32_t)(i * 16 * SROWB) + kkB;
                ldsm4(ah[0], ah[1], ah[2], ah[3], ao);
                ldsm4(al[0], al[1], al[2], al[3], ao + ABUF);
#pragma unroll
                for (int j = 0; j < 8; j++) {
                    mma_bf16(acc[i][j], ah[0], ah[1], ah[2], ah[3], bh[2*j], bh[2*j+1]);
                    mma_bf16(acc[i][j], ah[0], ah[1], ah[2], ah[3], bl[2*j], bl[2*j+1]);
                    mma_bf16(acc[i][j], al[0], al[1], al[2], al[3], bh[2*j], bh[2*j+1]);
                }
            }
        }
        __syncthreads();
    }

#pragma unroll
    for (int i = 0; i < 4; i++) {
#pragma unroll
        for (int j = 0; j < 8; j++) {
            int rg = mBlk + warpM * 64 + i * 16 + (lane >> 2);
            int cg = nBlk + warpN * 64 + j * 8 + (lane & 3) * 2;
            float b0 = 0.f, b1 = 0.f;
            if (bias) { b0 = bias[cg]; b1 = bias[cg + 1]; }
            *(float2*)(C + (size_t)rg * N + cg) =
                make_float2(acc[i][j][0] + b0, acc[i][j][1] + b1);
            *(float2*)(C + (size_t)(rg + 8) * N + cg) =
                make_float2(acc[i][j][2] + b0, acc[i][j][3] + b1);
        }
    }
}

// ---------------- vmean: global query rows (i<64) -> bf16 hi/lo at ---------
__global__ __launch_bounds__(1024) void vmean_kernel(const float* __restrict__ kv,
                                                     __nv_bfloat16* __restrict__ ath,
                                                     __nv_bfloat16* __restrict__ atl) {
    int b = blockIdx.x >> 2, kvh = blockIdx.x & 3;
    int d = threadIdx.x & 127;
    int c = threadIdx.x >> 7;
    const float* v = kv + (size_t)b * SB * KVF + NKVH * HD + kvh * HD + d;
    float s = 0.f;
    int j0 = c * 256;
#pragma unroll 8
    for (int j = j0; j < j0 + 256; j++) s += v[(size_t)j * KVF];
    __shared__ float red[8][128];
    red[c][d] = s;
    __syncthreads();
    if (c == 0) {
        float t = 0.f;
#pragma unroll
        for (int u = 0; u < 8; u++) t += red[u][d];
        t *= (1.0f / 2048.0f);
        __nv_bfloat16 th, tl; bfsplit(t, th, tl);
        for (int hh = 0; hh < 4; hh++) {
            int h = kvh * 4 + hh;
            for (int i = 0; i < 64; i++) {
                size_t idx = ((size_t)(b * SB) + i) * DIMD + h * HD + d;
                ath[idx] = th; atl[idx] = tl;
            }
        }
    }
}

// ---------------- tensor-core flash attention (inverted window mask) --------
#define ASTR 136
#define ATILE (64*ASTR)
#define AQH 0
#define AQL (ATILE*2)
#define AKH (2*ATILE*2)
#define AKL (3*ATILE*2)
#define AVH (4*ATILE*2)
#define AVL (5*ATILE*2)
#define ATTN_SMEM_BYTES (6*ATILE*2)

__global__ __launch_bounds__(128) void attn_mma_kernel(
    const float* __restrict__ q, const float* __restrict__ kv,
    __nv_bfloat16* __restrict__ ath, __nv_bfloat16* __restrict__ atl) {
    extern __shared__ char asmem[];
    __nv_bfloat16* sB = (__nv_bfloat16*)asmem;
    const uint32_t sb = (uint32_t)__cvta_generic_to_shared(asmem);

    const int tid = threadIdx.x;
    const int lane = tid & 31, w = tid >> 5;
    const int i0 = 64 + blockIdx.x * 64;
    const int h  = blockIdx.y;
    const int b  = blockIdx.z;
    const int kvh = h >> 2;
    const float slope = exp2f(-0.5f * (float)(h + 1));
    const float scale = 0.08838834764831845f;

    const float* qbase = q  + ((size_t)(b * SB + i0) * DIMD) + h * HD;
    const float* kbase = kv + ((size_t)b * SB * KVF) + kvh * HD;
    const float* vbase = kbase + NKVH * HD;

#pragma unroll
    for (int it = 0; it < 16; it++) {
        int flat = it * 512 + tid * 4;
        int r = flat >> 7, c = flat & 127;
        float4 v = *(const float4*)(qbase + (size_t)r * DIMD + c);
        __nv_bfloat16 hh[4], ll[4];
        bfsplit(v.x, hh[0], ll[0]); bfsplit(v.y, hh[1], ll[1]);
        bfsplit(v.z, hh[2], ll[2]); bfsplit(v.w, hh[3], ll[3]);
        *(uint2*)(sB + (AQH/2) + r * ASTR + c) = *(uint2*)hh;
        *(uint2*)(sB + (AQL/2) + r * ASTR + c) = *(uint2*)ll;
    }

    const uint32_t aOff = (uint32_t)((w * 16 + (lane & 7) + ((lane >> 3) & 1) * 8) * 272
                                     + (lane >> 4) * 16);
    const uint32_t bRowOff = (uint32_t)(((lane & 7) + (lane >> 4) * 8) * 272
                                        + ((lane >> 3) & 1) * 16);
    const uint32_t vOff = (uint32_t)(((lane & 7) + ((lane >> 3) & 1) * 8) * 272
                                     + (lane >> 4) * 16);

    const int gi0 = i0 + w * 16 + (lane >> 2);
    const int gi1 = gi0 + 8;
    const int cb  = (lane & 3) * 2;
    float m0 = -INFINITY, m1 = -INFINITY, l0 = 0.f, l1 = 0.f;

    float o[16][4];
#pragma unroll
    for (int f = 0; f < 16; f++)
#pragma unroll
        for (int r = 0; r < 4; r++) o[f][r] = 0.f;

    for (int j0t = 64; j0t < SB; j0t += 64) {
        int mdist = max(abs(i0 - (j0t + 63)), abs((i0 + 63) - j0t));
        if (mdist <= 256) continue;

        __syncthreads();
#pragma unroll
        for (int it = 0; it < 16; it++) {
            int flat = it * 512 + tid * 4;
            int r = flat >> 7, c = flat & 127;
            float4 kvv = *(const float4*)(kbase + (size_t)(j0t + r) * KVF + c);
            __nv_bfloat16 hh[4], ll[4];
            bfsplit(kvv.x, hh[0], ll[0]); bfsplit(kvv.y, hh[1], ll[1]);
            bfsplit(kvv.z, hh[2], ll[2]); bfsplit(kvv.w, hh[3], ll[3]);
            *(uint2*)(sB + (AKH/2) + r * ASTR + c) = *(uint2*)hh;
            *(uint2*)(sB + (AKL/2) + r * ASTR + c) = *(uint2*)ll;
            float4 vv = *(const float4*)(vbase + (size_t)(j0t + r) * KVF + c);
            bfsplit(vv.x, hh[0], ll[0]); bfsplit(vv.y, hh[1], ll[1]);
            bfsplit(vv.z, hh[2], ll[2]); bfsplit(vv.w, hh[3], ll[3]);
            *(uint2*)(sB + (AVH/2) + r * ASTR + c) = *(uint2*)hh;
            *(uint2*)(sB + (AVL/2) + r * ASTR + c) = *(uint2*)ll;
        }
        __syncthreads();

        float sacc[8][4];
#pragma unroll
        for (int j = 0; j < 8; j++)
#pragma unroll
            for (int r = 0; r < 4; r++) sacc[j][r] = 0.f;

#pragma unroll
        for (int kk = 0; kk < 8; kk++) {
            uint32_t qh[4], ql[4];
            ldsm4(qh[0], qh[1], qh[2], qh[3], sb + AQH + aOff + kk * 32);
            ldsm4(ql[0], ql[1], ql[2], ql[3], sb + AQL + aOff + kk * 32);
#pragma unroll
            for (int g = 0; g < 4; g++) {
                uint32_t kh[4], kl[4];
                uint32_t bo = bRowOff + (uint32_t)(g * 16 * 272) + kk * 32;
                ldsm4(kh[0], kh[1], kh[2], kh[3], sb + AKH + bo);
                ldsm4(kl[0], kl[1], kl[2], kl[3], sb + AKL + bo);
                mma_bf16(sacc[2*g],   qh[0], qh[1], qh[2], qh[3], kh[0], kh[1]);
                mma_bf16(sacc[2*g],   qh[0], qh[1], qh[2], qh[3], kl[0], kl[1]);
                mma_bf16(sacc[2*g],   ql[0], ql[1], ql[2], ql[3], kh[0], kh[1]);
                mma_bf16(sacc[2*g+1], qh[0], qh[1], qh[2], qh[3], kh[2], kh[3]);
                mma_bf16(sacc[2*g+1], qh[0], qh[1], qh[2], qh[3], kl[2], kl[3]);
                mma_bf16(sacc[2*g+1], ql[0], ql[1], ql[2], ql[3], kh[2], kh[3]);
            }
        }

        float tmax0 = -INFINITY, tmax1 = -INFINITY;
#pragma unroll
        for (int j = 0; j < 8; j++) {
            int gj = j0t + j * 8 + cb;
#pragma unroll
            for (int e = 0; e < 4; e++) {
                int gi = (e < 2) ? gi0 : gi1;
                int dist = abs(gi - (gj + (e & 1)));
                float val = (dist <= 256) ? -1e9f
                                          : (sacc[j][e] * scale - slope * (float)dist);
                sacc[j][e] = val;
                if (e < 2) tmax0 = fmaxf(tmax0, val);
                else       tmax1 = fmaxf(tmax1, val);
            }
        }
        tmax0 = fmaxf(tmax0, __shfl_xor_sync(0xffffffffu, tmax0, 1));
        tmax0 = fmaxf(tmax0, __shfl_xor_sync(0xffffffffu, tmax0, 2));
        tmax1 = fmaxf(tmax1, __shfl_xor_sync(0xffffffffu, tmax1, 1));
        tmax1 = fmaxf(tmax1, __shfl_xor_sync(0xffffffffu, tmax1, 2));

        float mn0 = fmaxf(m0, tmax0), mn1 = fmaxf(m1, tmax1);
        float f0 = __expf(m0 - mn0), f1 = __expf(m1 - mn1);
        float rs0 = 0.f, rs1 = 0.f;
#pragma unroll
        for (int j = 0; j < 8; j++) {
            float p0 = __expf(sacc[j][0] - mn0);
            float p1 = __expf(sacc[j][1] - mn0);
            float p2 = __expf(sacc[j][2] - mn1);
            float p3 = __expf(sacc[j][3] - mn1);
            sacc[j][0] = p0; sacc[j][1] = p1; sacc[j][2] = p2; sacc[j][3] = p3;
            rs0 += p0 + p1; rs1 += p2 + p3;
        }
        rs0 += __shfl_xor_sync(0xffffffffu, rs0, 1);
        rs0 += __shfl_xor_sync(0xffffffffu, rs0, 2);
        rs1 += __shfl_xor_sync(0xffffffffu, rs1, 1);
        rs1 += __shfl_xor_sync(0xffffffffu, rs1, 2);
        l0 = l0 * f0 + rs0; l1 = l1 * f1 + rs1;
        m0 = mn0; m1 = mn1;

#pragma unroll
        for (int f = 0; f < 16; f++) {
            o[f][0] *= f0; o[f][1] *= f0;
            o[f][2] *= f1; o[f][3] *= f1;
        }

#pragma unroll
        for (int kk = 0; kk < 4; kk++) {
            uint32_t pH[4], pL[4];
            {
                __nv_bfloat16 h0, l0b, h1, l1b;
                bfsplit(sacc[2*kk][0], h0, l0b);  bfsplit(sacc[2*kk][1], h1, l1b);
                pH[0] = pack_bf2(h0, h1); pL[0] = pack_bf2(l0b, l1b);
                bfsplit(sacc[2*kk][2], h0, l0b);  bfsplit(sacc[2*kk][3], h1, l1b);
                pH[1] = pack_bf2(h0, h1); pL[1] = pack_bf2(l0b, l1b);
                bfsplit(sacc[2*kk+1][0], h0, l0b); bfsplit(sacc[2*kk+1][1], h1, l1b);
                pH[2] = pack_bf2(h0, h1); pL[2] = pack_bf2(l0b, l1b);
                bfsplit(sacc[2*kk+1][2], h0, l0b); bfsplit(sacc[2*kk+1][3], h1, l1b);
                pH[3] = pack_bf2(h0, h1); pL[3] = pack_bf2(l0b, l1b);
            }
#pragma unroll
            for (int g = 0; g < 8; g++) {
                uint32_t vh[4], vl[4];
                uint32_t vo = vOff + (uint32_t)(kk * 16 * 272) + (uint32_t)(g * 32);
                ldsm4t(vh[0], vh[1], vh[2], vh[3], sb + AVH + vo);
                ldsm4t(vl[0], vl[1], vl[2], vl[3], sb + AVL + vo);
                mma_bf16(o[2*g],   pH[0], pH[1], pH[2], pH[3], vh[0], vh[1]);
                mma_bf16(o[2*g],   pH[0], pH[1], pH[2], pH[3], vl[0], vl[1]);
                mma_bf16(o[2*g],   pL[0], pL[1], pL[2], pL[3], vh[0], vh[1]);
                mma_bf16(o[2*g+1], pH[0], pH[1], pH[2], pH[3], vh[2], vh[3]);
                mma_bf16(o[2*g+1], pH[0], pH[1], pH[2], pH[3], vl[2], vl[3]);
                mma_bf16(o[2*g+1], pL[0], pL[1], pL[2], pL[3], vh[2], vh[3]);
            }
        }
    }

    // epilogue: divide by l, split to bf16 hi/lo, write directly
    float inv0 = 1.f / l0, inv1 = 1.f / l1;
    size_t row0 = (size_t)(b * SB) + gi0;
    size_t row1 = (size_t)(b * SB) + gi1;
#pragma unroll
    for (int f = 0; f < 16; f++) {
        int cg = h * HD + f * 8 + cb;
        __nv_bfloat16 h0, lo0, h1, lo1;
        bfsplit(o[f][0] * inv0, h0, lo0); bfsplit(o[f][1] * inv0, h1, lo1);
        *(uint32_t*)(ath + row0 * DIMD + cg) = pack_bf2(h0, h1);
        *(uint32_t*)(atl + row0 * DIMD + cg) = pack_bf2(lo0, lo1);
        bfsplit(o[f][2] * inv1, h0, lo0); bfsplit(o[f][3] * inv1, h1, lo1);
        *(uint32_t*)(ath + row1 * DIMD + cg) = pack_bf2(h0, h1);
        *(uint32_t*)(atl + row1 * DIMD + cg) = pack_bf2(lo0, lo1);
    }
}

// ---------------- launcher ----------------
extern "C" void kernel_launch(void* const* d_in, const int* in_sizes, int n_in,
                              void* d_out, int out_size) {
    (void)in_sizes; (void)n_in; (void)out_size;
    const float* x   = (const float*)d_in[0];
    const float* Wq  = (const float*)d_in[1];
    const float* Wkv = (const float*)d_in[2];
    const float* Wo  = (const float*)d_in[3];
    const float* bo  = (const float*)d_in[4];
    float* out = (float*)d_out;

    float *qb, *kvb;
    cudaGetSymbolAddress((void**)&qb,  g_q);
    cudaGetSymbolAddress((void**)&kvb, g_kv);
    __nv_bfloat16 *xq16b, *x16b, *ath, *atl, *wq16hb, *wq16lb, *wkv16hb, *wkv16lb, *woh, *wol;
    cudaGetSymbolAddress((void**)&xq16b,  g_xq_h);
    cudaGetSymbolAddress((void**)&x16b,   g_x_h);
    cudaGetSymbolAddress((void**)&ath,    g_at_h);
    cudaGetSymbolAddress((void**)&atl,    g_at_l);
    cudaGetSymbolAddress((void**)&wq16hb, g_wq_h);  cudaGetSymbolAddress((void**)&wq16lb, g_wq_l);
    cudaGetSymbolAddress((void**)&wkv16hb,g_wkv_h); cudaGetSymbolAddress((void**)&wkv16lb,g_wkv_l);
    cudaGetSymbolAddress((void**)&woh,    g_wo_h);  cudaGetSymbolAddress((void**)&wol,    g_wo_l);

    __half* xq16   = (__half*)xq16b;
    __half* x16    = (__half*)x16b;
    __half* wq16h  = (__half*)wq16hb;
    __half* wq16l  = (__half*)wq16lb;
    __half* wkv16h = (__half*)wkv16hb;
    __half* wkv16l = (__half*)wkv16lb;

    cudaFuncSetAttribute(attn_mma_kernel, cudaFuncAttributeMaxDynamicSharedMemorySize,
                         ATTN_SMEM_BYTES);
    cudaFuncSetAttribute(gemm3_kernel, cudaFuncAttributeMaxDynamicSharedMemorySize,
                         GEMM_SMEM);
    cudaFuncSetAttribute(gemm2h_kernel, cudaFuncAttributeMaxDynamicSharedMemorySize,
                         GEMM2_SMEM);

    // gating + operand prep
    gate_h_kernel<<<ROWS, 256>>>(x, xq16, x16);
    transpose_split_h_kernel<<<dim3(DIMD/32, DIMD/32), dim3(32, 8)>>>(Wq,  wq16h,  wq16l,  DIMD, DIMD);
    transpose_split_h_kernel<<<dim3(KVF/32,  DIMD/32), dim3(32, 8)>>>(Wkv, wkv16h, wkv16l, DIMD, KVF);
    transpose_split_kernel<<<dim3(DIMD/32, DIMD/32), dim3(32, 8)>>>(Wo, woh, wol, DIMD, DIMD);

    // projections: fp16 2-product on tensor cores
    gemm2h_kernel<<<dim3(DIMD/128, ROWS/256), 256, GEMM2_SMEM>>>(
        xq16, wq16h, wq16l, qb, ROWS, DIMD, DIMD);
    gemm2h_kernel<<<dim3(KVF/128, ROWS/256), 256, GEMM2_SMEM>>>(
        x16, wkv16h, wkv16l, kvb, ROWS, KVF, DIMD);

    // attention (writes bf16 hi/lo of `at` directly)
    vmean_kernel<<<BATCH * NKVH, 1024>>>(kvb, ath, atl);
    dim3 ga(31, NH, BATCH);
    attn_mma_kernel<<<ga, 128, ATTN_SMEM_BYTES>>>(qb, kvb, ath, atl);

    // output projection: bf16 3-product (precision-critical, direct path)
    gemm3_kernel<<<dim3(DIMD/128, ROWS/256), 256, GEMM_SMEM>>>(
        ath, atl, woh, wol, bo, out, ROWS, DIMD, DIMD);
}

// round 11
// speedup vs baseline: 3.3131x; 1.2734x over previous
#include <cuda_runtime.h>
#include <cuda_bf16.h>
#include <cuda_fp16.h>
#include <cstdint>
#include <stdint.h>
#include <math.h>

#define SB    2048
#define DIMD  2048
#define BATCH 2
#define NH    16
#define NKVH  4
#define HD    128
#define KVF   1024
#define ROWS  (BATCH*SB)   // 4096

// ---------------- scratch (device globals: allocation-free) ----------------
__device__ float g_q [(size_t)ROWS*DIMD];
__device__ float g_kv[(size_t)ROWS*KVF];

__device__ __half g_xq16[(size_t)ROWS*DIMD];             // fp16 gated x
__device__ __half g_x16 [(size_t)ROWS*DIMD];             // fp16 x
__device__ __half g_at16[(size_t)ROWS*DIMD];             // fp16 attention out
__device__ __half g_wq_h [(size_t)DIMD*DIMD], g_wq_l [(size_t)DIMD*DIMD];
__device__ __half g_wkv_h[(size_t)KVF *DIMD], g_wkv_l[(size_t)KVF *DIMD];
__device__ __half g_wo_h [(size_t)DIMD*DIMD], g_wo_l [(size_t)DIMD*DIMD];

// ---------------- helpers ----------------
__device__ __forceinline__ void hsplit(float v, __half& h, __half& l) {
    h = __float2half_rn(v);
    l = __float2half_rn(v - __half2float(h));
}
__device__ __forceinline__ uint32_t pack_h2(__half a, __half b) {
    __half2 t; t.x = a; t.y = b;
    return *(uint32_t*)&t;
}

// ---------------- kernel 1: complexity gate -> fp16 xq AND fp16 x ----------
__global__ __launch_bounds__(256) void gate_h_kernel(const float* __restrict__ x,
                                                     __half* __restrict__ xqh,
                                                     __half* __restrict__ xh) {
    int row = blockIdx.x;
    const float* xr = x + (size_t)row * DIMD;
    float s = 0.f;
    for (int c = threadIdx.x; c < DIMD; c += 256) s += fabsf(xr[c]);
    __shared__ float red[256];
    red[threadIdx.x] = s; __syncthreads();
    for (int off = 128; off > 0; off >>= 1) {
        if (threadIdx.x < off) red[threadIdx.x] += red[threadIdx.x + off];
        __syncthreads();
    }
    float cw = 1.f / (1.f + __expf(-red[0]));
    size_t base = (size_t)row * DIMD;
    for (int c = threadIdx.x; c < DIMD; c += 256) {
        float v = xr[c];
        xh [base + c] = __float2half_rn(v);
        xqh[base + c] = __float2half_rn(v * cw);
    }
}

// ---------------- transpose+split W[K][N] -> T[N][K], fp16 hi/lo -----------
__global__ __launch_bounds__(256) void transpose_split_h_kernel(
    const float* __restrict__ W, __half* __restrict__ Th,
    __half* __restrict__ Tl, int K, int N) {
    __shared__ float tile[32][33];
    int n0 = blockIdx.x * 32, k0 = blockIdx.y * 32;
    int tx = threadIdx.x, ty = threadIdx.y;
#pragma unroll
    for (int r = ty; r < 32; r += 8)
        tile[r][tx] = W[(size_t)(k0 + r) * N + n0 + tx];
    __syncthreads();
#pragma unroll
    for (int r = ty; r < 32; r += 8) {
        float v = tile[tx][r];
        __half h, l; hsplit(v, h, l);
        size_t o = (size_t)(n0 + r) * K + k0 + tx;
        Th[o] = h; Tl[o] = l;
    }
}

// ---------------- mma primitives ----------------
__device__ __forceinline__ void cp16(uint32_t dst, const void* src) {
    asm volatile("cp.async.cg.shared.global [%0], [%1], 16;\n" :: "r"(dst), "l"(src));
}
__device__ __forceinline__ void cp_commit() { asm volatile("cp.async.commit_group;\n"); }
__device__ __forceinline__ void cp_wait1() { asm volatile("cp.async.wait_group 1;\n"); }
__device__ __forceinline__ void cp_wait0() { asm volatile("cp.async.wait_group 0;\n"); }
__device__ __forceinline__ void ldsm4(uint32_t& r0, uint32_t& r1, uint32_t& r2, uint32_t& r3,
                                      uint32_t addr) {
    asm volatile("ldmatrix.sync.aligned.m8n8.x4.shared.b16 {%0,%1,%2,%3}, [%4];\n"
                 : "=r"(r0), "=r"(r1), "=r"(r2), "=r"(r3) : "r"(addr));
}
__device__ __forceinline__ void ldsm4t(uint32_t& r0, uint32_t& r1, uint32_t& r2, uint32_t& r3,
                                       uint32_t addr) {
    asm volatile("ldmatrix.sync.aligned.m8n8.x4.trans.shared.b16 {%0,%1,%2,%3}, [%4];\n"
                 : "=r"(r0), "=r"(r1), "=r"(r2), "=r"(r3) : "r"(addr));
}
__device__ __forceinline__ void mma_f16(float* d, uint32_t a0, uint32_t a1, uint32_t a2,
                                        uint32_t a3, uint32_t b0, uint32_t b1) {
    asm volatile("mma.sync.aligned.m16n8k16.row.col.f32.f16.f16.f32 "
                 "{%0,%1,%2,%3}, {%4,%5,%6,%7}, {%8,%9}, {%0,%1,%2,%3};\n"
                 : "+f"(d[0]), "+f"(d[1]), "+f"(d[2]), "+f"(d[3])
                 : "r"(a0), "r"(a1), "r"(a2), "r"(a3), "r"(b0), "r"(b1));
}

// ---------------- shared tile constants (256x128 block, 8 warps 64x64) ------
#define SROWB 80
#define ABUF  (256*SROWB)        // 20480 B
#define BBUF  (128*SROWB)        // 10240 B
#define STAGE2B (ABUF + 2*BBUF)  // A|Bh|Bl = 40960
#define GEMM2_SMEM (2*STAGE2B)   // 81920

// ---------------- fp16 2-product GEMM: C = A @ (Bh+Bl)^T (+bias) ------------
__global__ __launch_bounds__(256, 1) void gemm2h_kernel(
    const __half* __restrict__ A,
    const __half* __restrict__ Bhi, const __half* __restrict__ Blo,
    const float* __restrict__ bias, float* __restrict__ C,
    int M, int N, int K) {
    extern __shared__ char smem[];
    const uint32_t sb = (uint32_t)__cvta_generic_to_shared(smem);
    const int tid = threadIdx.x;
    const int lane = tid & 31, wid = tid >> 5;
    const int warpM = wid >> 1, warpN = wid & 1;
    const int mBlk = blockIdx.y * 256, nBlk = blockIdx.x * 128;

    const size_t aG = (size_t)(mBlk + tid) * K;
    const int brow = tid >> 1, bc0 = (tid & 1) * 2;
    const size_t bG = (size_t)(nBlk + brow) * K + bc0 * 8;
    const uint32_t aD = sb + tid * SROWB;
    const uint32_t bD = sb + ABUF + brow * SROWB + bc0 * 16;

    const int aRow = warpM * 64 + (lane & 7) + ((lane >> 3) & 1) * 8;
    const uint32_t aLd = aRow * SROWB + (lane >> 4) * 16;
    const int bRow = warpN * 64 + (lane & 7) + (lane >> 4) * 8;
    const uint32_t bLd = bRow * SROWB + ((lane >> 3) & 1) * 16;

    float acc[4][8][4];
#pragma unroll
    for (int i = 0; i < 4; i++)
#pragma unroll
        for (int j = 0; j < 8; j++)
#pragma unroll
            for (int r = 0; r < 4; r++) acc[i][j][r] = 0.f;

    const int nkt = K / 32;

    {
#pragma unroll
        for (int c = 0; c < 4; c++) cp16(aD + c * 16, A + aG + c * 8);
        cp16(bD,             Bhi + bG);
        cp16(bD + 16,        Bhi + bG + 8);
        cp16(bD + BBUF,      Blo + bG);
        cp16(bD + BBUF + 16, Blo + bG + 8);
        cp_commit();
    }

    for (int kt = 0; kt < nkt; kt++) {
        const int cur = kt & 1;
        if (kt + 1 < nkt) {
            const uint32_t so = (cur ^ 1) * STAGE2B;
            const size_t off = (size_t)(kt + 1) * 32;
#pragma unroll
            for (int c = 0; c < 4; c++) cp16(aD + so + c * 16, A + aG + off + c * 8);
            cp16(bD + so,             Bhi + bG + off);
            cp16(bD + so + 16,        Bhi + bG + off + 8);
            cp16(bD + so + BBUF,      Blo + bG + off);
            cp16(bD + so + BBUF + 16, Blo + bG + off + 8);
            cp_commit();
            cp_wait1();
        } else {
            cp_wait0();
        }
        __syncthreads();

        const uint32_t base = sb + cur * STAGE2B;
#pragma unroll
        for (int kkB = 0; kkB < 64; kkB += 32) {
            uint32_t bh[16], bl[16];
#pragma unroll
            for (int g = 0; g < 4; g++) {
                uint32_t bo = base + ABUF + bLd + kkB + (uint32_t)(g * 16 * SROWB);
                ldsm4(bh[4*g], bh[4*g+1], bh[4*g+2], bh[4*g+3], bo);
                ldsm4(bl[4*g], bl[4*g+1], bl[4*g+2], bl[4*g+3], bo + BBUF);
            }
#pragma unroll
            for (int i = 0; i < 4; i++) {
                uint32_t ah[4];
                ldsm4(ah[0], ah[1], ah[2], ah[3],
                      base + aLd + (uint32_t)(i * 16 * SROWB) + kkB);
#pragma unroll
                for (int j = 0; j < 8; j++) {
                    mma_f16(acc[i][j], ah[0], ah[1], ah[2], ah[3], bh[2*j], bh[2*j+1]);
                    mma_f16(acc[i][j], ah[0], ah[1], ah[2], ah[3], bl[2*j], bl[2*j+1]);
                }
            }
        }
        __syncthreads();
    }

#pragma unroll
    for (int i = 0; i < 4; i++) {
#pragma unroll
        for (int j = 0; j < 8; j++) {
            int rg = mBlk + warpM * 64 + i * 16 + (lane >> 2);
            int cg = nBlk + warpN * 64 + j * 8 + (lane & 3) * 2;
            float b0 = 0.f, b1 = 0.f;
            if (bias) { b0 = bias[cg]; b1 = bias[cg + 1]; }
            *(float2*)(C + (size_t)rg * N + cg) =
                make_float2(acc[i][j][0] + b0, acc[i][j][1] + b1);
            *(float2*)(C + (size_t)(rg + 8) * N + cg) =
                make_float2(acc[i][j][2] + b0, acc[i][j][3] + b1);
        }
    }
}

// ---------------- vmean: global query rows (i<64) -> fp16 at ----------------
__global__ __launch_bounds__(1024) void vmean_kernel(const float* __restrict__ kv,
                                                     __half* __restrict__ at16) {
    int b = blockIdx.x >> 2, kvh = blockIdx.x & 3;
    int d = threadIdx.x & 127;
    int c = threadIdx.x >> 7;
    const float* v = kv + (size_t)b * SB * KVF + NKVH * HD + kvh * HD + d;
    float s = 0.f;
    int j0 = c * 256;
#pragma unroll 8
    for (int j = j0; j < j0 + 256; j++) s += v[(size_t)j * KVF];
    __shared__ float red[8][128];
    red[c][d] = s;
    __syncthreads();
    if (c == 0) {
        float t = 0.f;
#pragma unroll
        for (int u = 0; u < 8; u++) t += red[u][d];
        __half th = __float2half_rn(t * (1.0f / 2048.0f));
        for (int hh = 0; hh < 4; hh++) {
            int h = kvh * 4 + hh;
            for (int i = 0; i < 64; i++)
                at16[((size_t)(b * SB) + i) * DIMD + h * HD + d] = th;
        }
    }
}

// ---------------- fp16 tensor-core flash attention (inverted window mask) ---
// smem tiles (fp16, ASTR=136 halfs/row): Q | K | Vh | Vl
#define ASTR 136
#define ATILE (64*ASTR)
#define AQ  0
#define AK  (ATILE*2)
#define AVH (2*ATILE*2)
#define AVL (3*ATILE*2)
#define ATTN_SMEM_BYTES (4*ATILE*2)   // 69632

__global__ __launch_bounds__(128) void attn_mma_kernel(
    const float* __restrict__ q, const float* __restrict__ kv,
    __half* __restrict__ at16) {
    extern __shared__ char asmem[];
    __half* sB = (__half*)asmem;
    const uint32_t sb = (uint32_t)__cvta_generic_to_shared(asmem);

    const int tid = threadIdx.x;
    const int lane = tid & 31, w = tid >> 5;
    const int i0 = 64 + blockIdx.x * 64;
    const int h  = blockIdx.y;
    const int b  = blockIdx.z;
    const int kvh = h >> 2;
    const float slope = exp2f(-0.5f * (float)(h + 1));
    const float scale = 0.08838834764831845f;

    const float* qbase = q  + ((size_t)(b * SB + i0) * DIMD) + h * HD;
    const float* kbase = kv + ((size_t)b * SB * KVF) + kvh * HD;
    const float* vbase = kbase + NKVH * HD;

    // load Q tile -> single fp16
#pragma unroll
    for (int it = 0; it < 16; it++) {
        int flat = it * 512 + tid * 4;
        int r = flat >> 7, c = flat & 127;
        float4 v = *(const float4*)(qbase + (size_t)r * DIMD + c);
        __half hh[4];
        hh[0] = __float2half_rn(v.x); hh[1] = __float2half_rn(v.y);
        hh[2] = __float2half_rn(v.z); hh[3] = __float2half_rn(v.w);
        *(uint2*)(sB + (AQ/2) + r * ASTR + c) = *(uint2*)hh;
    }

    const uint32_t aOff = (uint32_t)((w * 16 + (lane & 7) + ((lane >> 3) & 1) * 8) * 272
                                     + (lane >> 4) * 16);
    const uint32_t bRowOff = (uint32_t)(((lane & 7) + (lane >> 4) * 8) * 272
                                        + ((lane >> 3) & 1) * 16);
    const uint32_t vOff = (uint32_t)(((lane & 7) + ((lane >> 3) & 1) * 8) * 272
                                     + (lane >> 4) * 16);

    const int gi0 = i0 + w * 16 + (lane >> 2);
    const int gi1 = gi0 + 8;
    const int cb  = (lane & 3) * 2;
    float m0 = -INFINITY, m1 = -INFINITY, l0 = 0.f, l1 = 0.f;

    float o[16][4];
#pragma unroll
    for (int f = 0; f < 16; f++)
#pragma unroll
        for (int r = 0; r < 4; r++) o[f][r] = 0.f;

    for (int j0t = 64; j0t < SB; j0t += 64) {
        int mdist = max(abs(i0 - (j0t + 63)), abs((i0 + 63) - j0t));
        if (mdist <= 256) continue;

        __syncthreads();
        // load K (single fp16) and V (fp16 hi/lo)
#pragma unroll
        for (int it = 0; it < 16; it++) {
            int flat = it * 512 + tid * 4;
            int r = flat >> 7, c = flat & 127;
            float4 kvv = *(const float4*)(kbase + (size_t)(j0t + r) * KVF + c);
            __half hh[4], ll[4];
            hh[0] = __float2half_rn(kvv.x); hh[1] = __float2half_rn(kvv.y);
            hh[2] = __float2half_rn(kvv.z); hh[3] = __float2half_rn(kvv.w);
            *(uint2*)(sB + (AK/2) + r * ASTR + c) = *(uint2*)hh;
            float4 vv = *(const float4*)(vbase + (size_t)(j0t + r) * KVF + c);
            hsplit(vv.x, hh[0], ll[0]); hsplit(vv.y, hh[1], ll[1]);
            hsplit(vv.z, hh[2], ll[2]); hsplit(vv.w, hh[3], ll[3]);
            *(uint2*)(sB + (AVH/2) + r * ASTR + c) = *(uint2*)hh;
            *(uint2*)(sB + (AVL/2) + r * ASTR + c) = *(uint2*)ll;
        }
        __syncthreads();

        // ---- S = Q K^T (single fp16) ----
        float sacc[8][4];
#pragma unroll
        for (int j = 0; j < 8; j++)
#pragma unroll
            for (int r = 0; r < 4; r++) sacc[j][r] = 0.f;

#pragma unroll
        for (int kk = 0; kk < 8; kk++) {
            uint32_t qf[4];
            ldsm4(qf[0], qf[1], qf[2], qf[3], sb + AQ + aOff + kk * 32);
#pragma unroll
            for (int g = 0; g < 4; g++) {
                uint32_t kf[4];
                ldsm4(kf[0], kf[1], kf[2], kf[3],
                      sb + AK + bRowOff + (uint32_t)(g * 16 * 272) + kk * 32);
                mma_f16(sacc[2*g],   qf[0], qf[1], qf[2], qf[3], kf[0], kf[1]);
                mma_f16(sacc[2*g+1], qf[0], qf[1], qf[2], qf[3], kf[2], kf[3]);
            }
        }

        // ---- mask + ALiBi + online softmax (fp32) ----
        float tmax0 = -INFINITY, tmax1 = -INFINITY;
#pragma unroll
        for (int j = 0; j < 8; j++) {
            int gj = j0t + j * 8 + cb;
#pragma unroll
            for (int e = 0; e < 4; e++) {
                int gi = (e < 2) ? gi0 : gi1;
                int dist = abs(gi - (gj + (e & 1)));
                float val = (dist <= 256) ? -1e9f
                                          : (sacc[j][e] * scale - slope * (float)dist);
                sacc[j][e] = val;
                if (e < 2) tmax0 = fmaxf(tmax0, val);
                else       tmax1 = fmaxf(tmax1, val);
            }
        }
        tmax0 = fmaxf(tmax0, __shfl_xor_sync(0xffffffffu, tmax0, 1));
        tmax0 = fmaxf(tmax0, __shfl_xor_sync(0xffffffffu, tmax0, 2));
        tmax1 = fmaxf(tmax1, __shfl_xor_sync(0xffffffffu, tmax1, 1));
        tmax1 = fmaxf(tmax1, __shfl_xor_sync(0xffffffffu, tmax1, 2));

        float mn0 = fmaxf(m0, tmax0), mn1 = fmaxf(m1, tmax1);
        float f0 = __expf(m0 - mn0), f1 = __expf(m1 - mn1);
        float rs0 = 0.f, rs1 = 0.f;
#pragma unroll
        for (int j = 0; j < 8; j++) {
            float p0 = __expf(sacc[j][0] - mn0);
            float p1 = __expf(sacc[j][1] - mn0);
            float p2 = __expf(sacc[j][2] - mn1);
            float p3 = __expf(sacc[j][3] - mn1);
            sacc[j][0] = p0; sacc[j][1] = p1; sacc[j][2] = p2; sacc[j][3] = p3;
            rs0 += p0 + p1; rs1 += p2 + p3;
        }
        rs0 += __shfl_xor_sync(0xffffffffu, rs0, 1);
        rs0 += __shfl_xor_sync(0xffffffffu, rs0, 2);
        rs1 += __shfl_xor_sync(0xffffffffu, rs1, 1);
        rs1 += __shfl_xor_sync(0xffffffffu, rs1, 2);
        l0 = l0 * f0 + rs0; l1 = l1 * f1 + rs1;
        m0 = mn0; m1 = mn1;

#pragma unroll
        for (int f = 0; f < 16; f++) {
            o[f][0] *= f0; o[f][1] *= f0;
            o[f][2] *= f1; o[f][3] *= f1;
        }

        // ---- O += P V (P single fp16, V hi/lo fp16) ----
#pragma unroll
        for (int kk = 0; kk < 4; kk++) {
            uint32_t pF[4];
            pF[0] = pack_h2(__float2half_rn(sacc[2*kk][0]),   __float2half_rn(sacc[2*kk][1]));
            pF[1] = pack_h2(__float2half_rn(sacc[2*kk][2]),   __float2half_rn(sacc[2*kk][3]));
            pF[2] = pack_h2(__float2half_rn(sacc[2*kk+1][0]), __float2half_rn(sacc[2*kk+1][1]));
            pF[3] = pack_h2(__float2half_rn(sacc[2*kk+1][2]), __float2half_rn(sacc[2*kk+1][3]));
#pragma unroll
            for (int g = 0; g < 8; g++) {
                uint32_t vh[4], vl[4];
                uint32_t vo = vOff + (uint32_t)(kk * 16 * 272) + (uint32_t)(g * 32);
                ldsm4t(vh[0], vh[1], vh[2], vh[3], sb + AVH + vo);
                ldsm4t(vl[0], vl[1], vl[2], vl[3], sb + AVL + vo);
                mma_f16(o[2*g],   pF[0], pF[1], pF[2], pF[3], vh[0], vh[1]);
                mma_f16(o[2*g],   pF[0], pF[1], pF[2], pF[3], vl[0], vl[1]);
                mma_f16(o[2*g+1], pF[0], pF[1], pF[2], pF[3], vh[2], vh[3]);
                mma_f16(o[2*g+1], pF[0], pF[1], pF[2], pF[3], vl[2], vl[3]);
            }
        }
    }

    // epilogue: divide by l, write single fp16
    float inv0 = 1.f / l0, inv1 = 1.f / l1;
    size_t row0 = (size_t)(b * SB) + gi0;
    size_t row1 = (size_t)(b * SB) + gi1;
#pragma unroll
    for (int f = 0; f < 16; f++) {
        int cg = h * HD + f * 8 + cb;
        *(uint32_t*)(at16 + row0 * DIMD + cg) =
            pack_h2(__float2half_rn(o[f][0] * inv0), __float2half_rn(o[f][1] * inv0));
        *(uint32_t*)(at16 + row1 * DIMD + cg) =
            pack_h2(__float2half_rn(o[f][2] * inv1), __float2half_rn(o[f][3] * inv1));
    }
}

// ---------------- launcher ----------------
extern "C" void kernel_launch(void* const* d_in, const int* in_sizes, int n_in,
                              void* d_out, int out_size) {
    (void)in_sizes; (void)n_in; (void)out_size;
    const float* x   = (const float*)d_in[0];
    const float* Wq  = (const float*)d_in[1];
    const float* Wkv = (const float*)d_in[2];
    const float* Wo  = (const float*)d_in[3];
    const float* bo  = (const float*)d_in[4];
    float* out = (float*)d_out;

    float *qb, *kvb;
    cudaGetSymbolAddress((void**)&qb,  g_q);
    cudaGetSymbolAddress((void**)&kvb, g_kv);
    __half *xq16, *x16, *at16, *wqh, *wql, *wkvh, *wkvl, *woh, *wol;
    cudaGetSymbolAddress((void**)&xq16, g_xq16);
    cudaGetSymbolAddress((void**)&x16,  g_x16);
    cudaGetSymbolAddress((void**)&at16, g_at16);
    cudaGetSymbolAddress((void**)&wqh,  g_wq_h);  cudaGetSymbolAddress((void**)&wql,  g_wq_l);
    cudaGetSymbolAddress((void**)&wkvh, g_wkv_h); cudaGetSymbolAddress((void**)&wkvl, g_wkv_l);
    cudaGetSymbolAddress((void**)&woh,  g_wo_h);  cudaGetSymbolAddress((void**)&wol,  g_wo_l);

    cudaFuncSetAttribute(attn_mma_kernel, cudaFuncAttributeMaxDynamicSharedMemorySize,
                         ATTN_SMEM_BYTES);
    cudaFuncSetAttribute(gemm2h_kernel, cudaFuncAttributeMaxDynamicSharedMemorySize,
                         GEMM2_SMEM);

    // gating + operand prep
    gate_h_kernel<<<ROWS, 256>>>(x, xq16, x16);
    transpose_split_h_kernel<<<dim3(DIMD/32, DIMD/32), dim3(32, 8)>>>(Wq,  wqh,  wql,  DIMD, DIMD);
    transpose_split_h_kernel<<<dim3(KVF/32,  DIMD/32), dim3(32, 8)>>>(Wkv, wkvh, wkvl, DIMD, KVF);
    transpose_split_h_kernel<<<dim3(DIMD/32, DIMD/32), dim3(32, 8)>>>(Wo,  woh,  wol,  DIMD, DIMD);

    // projections: fp16 2-product on tensor cores
    gemm2h_kernel<<<dim3(DIMD/128, ROWS/256), 256, GEMM2_SMEM>>>(
        xq16, wqh, wql, nullptr, qb, ROWS, DIMD, DIMD);
    gemm2h_kernel<<<dim3(KVF/128, ROWS/256), 256, GEMM2_SMEM>>>(
        x16, wkvh, wkvl, nullptr, kvb, ROWS, KVF, DIMD);

    // attention (writes fp16 at directly)
    vmean_kernel<<<BATCH * NKVH, 1024>>>(kvb, at16);
    dim3 ga(31, NH, BATCH);
    attn_mma_kernel<<<ga, 128, ATTN_SMEM_BYTES>>>(qb, kvb, at16);

    // output projection: fp16 2-product + bias
    gemm2h_kernel<<<dim3(DIMD/128, ROWS/256), 256, GEMM2_SMEM>>>(
        at16, woh, wol, bo, out, ROWS, DIMD, DIMD);
}

// round 13
// speedup vs baseline: 4.5604x; 1.3765x over previous
#include <cuda_runtime.h>
#include <cuda_bf16.h>
#include <cuda_fp16.h>
#include <cstdint>
#include <stdint.h>
#include <math.h>

#define SB    2048
#define DIMD  2048
#define BATCH 2
#define NH    16
#define NKVH  4
#define HD    128
#define KVF   1024
#define ROWS  (BATCH*SB)   // 4096

// ---------------- scratch (device globals: allocation-free) ----------------
__device__ float g_q [(size_t)ROWS*DIMD];
__device__ float g_kv[(size_t)ROWS*KVF];

__device__ __half g_xq16[(size_t)ROWS*DIMD];             // fp16 gated x
__device__ __half g_x16 [(size_t)ROWS*DIMD];             // fp16 x
__device__ __half g_at16[(size_t)ROWS*DIMD];             // fp16 attention out
__device__ __half g_wq16 [(size_t)DIMD*DIMD];            // fp16 WqT
__device__ __half g_wkv16[(size_t)KVF *DIMD];            // fp16 WkvT
__device__ __half g_wo16 [(size_t)DIMD*DIMD];            // fp16 WoT

// ---------------- helpers ----------------
__device__ __forceinline__ uint32_t pack_h2(__half a, __half b) {
    __half2 t; t.x = a; t.y = b;
    return *(uint32_t*)&t;
}

// ---------------- kernel 1: complexity gate -> fp16 xq AND fp16 x ----------
__global__ __launch_bounds__(256) void gate_h_kernel(const float* __restrict__ x,
                                                     __half* __restrict__ xqh,
                                                     __half* __restrict__ xh) {
    int row = blockIdx.x;
    const float* xr = x + (size_t)row * DIMD;
    float s = 0.f;
    for (int c = threadIdx.x; c < DIMD; c += 256) s += fabsf(xr[c]);
    __shared__ float red[256];
    red[threadIdx.x] = s; __syncthreads();
    for (int off = 128; off > 0; off >>= 1) {
        if (threadIdx.x < off) red[threadIdx.x] += red[threadIdx.x + off];
        __syncthreads();
    }
    float cw = 1.f / (1.f + __expf(-red[0]));
    size_t base = (size_t)row * DIMD;
    for (int c = threadIdx.x; c < DIMD; c += 256) {
        float v = xr[c];
        xh [base + c] = __float2half_rn(v);
        xqh[base + c] = __float2half_rn(v * cw);
    }
}

// ---------------- transpose W[K][N] -> T[N][K], single fp16 ----------------
__global__ __launch_bounds__(256) void transpose_h_kernel(
    const float* __restrict__ W, __half* __restrict__ T, int K, int N) {
    __shared__ float tile[32][33];
    int n0 = blockIdx.x * 32, k0 = blockIdx.y * 32;
    int tx = threadIdx.x, ty = threadIdx.y;
#pragma unroll
    for (int r = ty; r < 32; r += 8)
        tile[r][tx] = W[(size_t)(k0 + r) * N + n0 + tx];
    __syncthreads();
#pragma unroll
    for (int r = ty; r < 32; r += 8)
        T[(size_t)(n0 + r) * K + k0 + tx] = __float2half_rn(tile[tx][r]);
}

// ---------------- mma primitives ----------------
__device__ __forceinline__ void cp16(uint32_t dst, const void* src) {
    asm volatile("cp.async.cg.shared.global [%0], [%1], 16;\n" :: "r"(dst), "l"(src));
}
__device__ __forceinline__ void cp_commit() { asm volatile("cp.async.commit_group;\n"); }
__device__ __forceinline__ void cp_wait1() { asm volatile("cp.async.wait_group 1;\n"); }
__device__ __forceinline__ void cp_wait0() { asm volatile("cp.async.wait_group 0;\n"); }
__device__ __forceinline__ void ldsm4(uint32_t& r0, uint32_t& r1, uint32_t& r2, uint32_t& r3,
                                      uint32_t addr) {
    asm volatile("ldmatrix.sync.aligned.m8n8.x4.shared.b16 {%0,%1,%2,%3}, [%4];\n"
                 : "=r"(r0), "=r"(r1), "=r"(r2), "=r"(r3) : "r"(addr));
}
__device__ __forceinline__ void ldsm4t(uint32_t& r0, uint32_t& r1, uint32_t& r2, uint32_t& r3,
                                       uint32_t addr) {
    asm volatile("ldmatrix.sync.aligned.m8n8.x4.trans.shared.b16 {%0,%1,%2,%3}, [%4];\n"
                 : "=r"(r0), "=r"(r1), "=r"(r2), "=r"(r3) : "r"(addr));
}
__device__ __forceinline__ void mma_f16(float* d, uint32_t a0, uint32_t a1, uint32_t a2,
                                        uint32_t a3, uint32_t b0, uint32_t b1) {
    asm volatile("mma.sync.aligned.m16n8k16.row.col.f32.f16.f16.f32 "
                 "{%0,%1,%2,%3}, {%4,%5,%6,%7}, {%8,%9}, {%0,%1,%2,%3};\n"
                 : "+f"(d[0]), "+f"(d[1]), "+f"(d[2]), "+f"(d[3])
                 : "r"(a0), "r"(a1), "r"(a2), "r"(a3), "r"(b0), "r"(b1));
}

// ---------------- shared tile constants (256x128 block, 8 warps 64x64) ------
#define SROWB 80
#define ABUF  (256*SROWB)        // 20480 B
#define BBUF  (128*SROWB)        // 10240 B
#define STAGE1B (ABUF + BBUF)    // A|B = 30720
#define GEMM1_SMEM (2*STAGE1B)   // 61440

// ---------------- fp16 GEMM: C = A @ B^T (+bias) ----------------------------
__global__ __launch_bounds__(256, 1) void gemm1h_kernel(
    const __half* __restrict__ A, const __half* __restrict__ B,
    const float* __restrict__ bias, float* __restrict__ C,
    int M, int N, int K) {
    extern __shared__ char smem[];
    const uint32_t sb = (uint32_t)__cvta_generic_to_shared(smem);
    const int tid = threadIdx.x;
    const int lane = tid & 31, wid = tid >> 5;
    const int warpM = wid >> 1, warpN = wid & 1;
    const int mBlk = blockIdx.y * 256, nBlk = blockIdx.x * 128;

    const size_t aG = (size_t)(mBlk + tid) * K;
    const int brow = tid >> 1, bc0 = (tid & 1) * 2;
    const size_t bG = (size_t)(nBlk + brow) * K + bc0 * 8;
    const uint32_t aD = sb + tid * SROWB;
    const uint32_t bD = sb + ABUF + brow * SROWB + bc0 * 16;

    const int aRow = warpM * 64 + (lane & 7) + ((lane >> 3) & 1) * 8;
    const uint32_t aLd = aRow * SROWB + (lane >> 4) * 16;
    const int bRow = warpN * 64 + (lane & 7) + (lane >> 4) * 8;
    const uint32_t bLd = bRow * SROWB + ((lane >> 3) & 1) * 16;

    float acc[4][8][4];
#pragma unroll
    for (int i = 0; i < 4; i++)
#pragma unroll
        for (int j = 0; j < 8; j++)
#pragma unroll
            for (int r = 0; r < 4; r++) acc[i][j][r] = 0.f;

    const int nkt = K / 32;

    {
#pragma unroll
        for (int c = 0; c < 4; c++) cp16(aD + c * 16, A + aG + c * 8);
        cp16(bD,      B + bG);
        cp16(bD + 16, B + bG + 8);
        cp_commit();
    }

    for (int kt = 0; kt < nkt; kt++) {
        const int cur = kt & 1;
        if (kt + 1 < nkt) {
            const uint32_t so = (cur ^ 1) * STAGE1B;
            const size_t off = (size_t)(kt + 1) * 32;
#pragma unroll
            for (int c = 0; c < 4; c++) cp16(aD + so + c * 16, A + aG + off + c * 8);
            cp16(bD + so,      B + bG + off);
            cp16(bD + so + 16, B + bG + off + 8);
            cp_commit();
            cp_wait1();
        } else {
            cp_wait0();
        }
        __syncthreads();

        const uint32_t base = sb + cur * STAGE1B;
#pragma unroll
        for (int kkB = 0; kkB < 64; kkB += 32) {
            uint32_t bh[16];
#pragma unroll
            for (int g = 0; g < 4; g++) {
                ldsm4(bh[4*g], bh[4*g+1], bh[4*g+2], bh[4*g+3],
                      base + ABUF + bLd + kkB + (uint32_t)(g * 16 * SROWB));
            }
#pragma unroll
            for (int i = 0; i < 4; i++) {
                uint32_t ah[4];
                ldsm4(ah[0], ah[1], ah[2], ah[3],
                      base + aLd + (uint32_t)(i * 16 * SROWB) + kkB);
#pragma unroll
                for (int j = 0; j < 8; j++)
                    mma_f16(acc[i][j], ah[0], ah[1], ah[2], ah[3], bh[2*j], bh[2*j+1]);
            }
        }
        __syncthreads();
    }

#pragma unroll
    for (int i = 0; i < 4; i++) {
#pragma unroll
        for (int j = 0; j < 8; j++) {
            int rg = mBlk + warpM * 64 + i * 16 + (lane >> 2);
            int cg = nBlk + warpN * 64 + j * 8 + (lane & 3) * 2;
            float b0 = 0.f, b1 = 0.f;
            if (bias) { b0 = bias[cg]; b1 = bias[cg + 1]; }
            *(float2*)(C + (size_t)rg * N + cg) =
                make_float2(acc[i][j][0] + b0, acc[i][j][1] + b1);
            *(float2*)(C + (size_t)(rg + 8) * N + cg) =
                make_float2(acc[i][j][2] + b0, acc[i][j][3] + b1);
        }
    }
}

// ---------------- vmean: global query rows (i<64) -> fp16 at ----------------
__global__ __launch_bounds__(1024) void vmean_kernel(const float* __restrict__ kv,
                                                     __half* __restrict__ at16) {
    int b = blockIdx.x >> 2, kvh = blockIdx.x & 3;
    int d = threadIdx.x & 127;
    int c = threadIdx.x >> 7;
    const float* v = kv + (size_t)b * SB * KVF + NKVH * HD + kvh * HD + d;
    float s = 0.f;
    int j0 = c * 256;
#pragma unroll 8
    for (int j = j0; j < j0 + 256; j++) s += v[(size_t)j * KVF];
    __shared__ float red[8][128];
    red[c][d] = s;
    __syncthreads();
    if (c == 0) {
        float t = 0.f;
#pragma unroll
        for (int u = 0; u < 8; u++) t += red[u][d];
        __half th = __float2half_rn(t * (1.0f / 2048.0f));
        for (int hh = 0; hh < 4; hh++) {
            int h = kvh * 4 + hh;
            for (int i = 0; i < 64; i++)
                at16[((size_t)(b * SB) + i) * DIMD + h * HD + d] = th;
        }
    }
}

// ---------------- fp16 tensor-core flash attention (inverted window mask) ---
// smem tiles (fp16, ASTR=136 halfs/row): Q | K | V
#define ASTR 136
#define ATILE (64*ASTR)
#define AQ  0
#define AK  (ATILE*2)
#define AV  (2*ATILE*2)
#define ATTN_SMEM_BYTES (3*ATILE*2)   // 52224

__global__ __launch_bounds__(128) void attn_mma_kernel(
    const float* __restrict__ q, const float* __restrict__ kv,
    __half* __restrict__ at16) {
    extern __shared__ char asmem[];
    __half* sB = (__half*)asmem;
    const uint32_t sb = (uint32_t)__cvta_generic_to_shared(asmem);

    const int tid = threadIdx.x;
    const int lane = tid & 31, w = tid >> 5;
    const int i0 = 64 + blockIdx.x * 64;
    const int h  = blockIdx.y;
    const int b  = blockIdx.z;
    const int kvh = h >> 2;
    const float slope = exp2f(-0.5f * (float)(h + 1));
    const float scale = 0.08838834764831845f;

    const float* qbase = q  + ((size_t)(b * SB + i0) * DIMD) + h * HD;
    const float* kbase = kv + ((size_t)b * SB * KVF) + kvh * HD;
    const float* vbase = kbase + NKVH * HD;

    // load Q tile -> single fp16
#pragma unroll
    for (int it = 0; it < 16; it++) {
        int flat = it * 512 + tid * 4;
        int r = flat >> 7, c = flat & 127;
        float4 v = *(const float4*)(qbase + (size_t)r * DIMD + c);
        __half hh[4];
        hh[0] = __float2half_rn(v.x); hh[1] = __float2half_rn(v.y);
        hh[2] = __float2half_rn(v.z); hh[3] = __float2half_rn(v.w);
        *(uint2*)(sB + (AQ/2) + r * ASTR + c) = *(uint2*)hh;
    }

    const uint32_t aOff = (uint32_t)((w * 16 + (lane & 7) + ((lane >> 3) & 1) * 8) * 272
                                     + (lane >> 4) * 16);
    const uint32_t bRowOff = (uint32_t)(((lane & 7) + (lane >> 4) * 8) * 272
                                        + ((lane >> 3) & 1) * 16);
    const uint32_t vOff = (uint32_t)(((lane & 7) + ((lane >> 3) & 1) * 8) * 272
                                     + (lane >> 4) * 16);

    const int gi0 = i0 + w * 16 + (lane >> 2);
    const int gi1 = gi0 + 8;
    const int cb  = (lane & 3) * 2;
    float m0 = -INFINITY, m1 = -INFINITY, l0 = 0.f, l1 = 0.f;

    float o[16][4];
#pragma unroll
    for (int f = 0; f < 16; f++)
#pragma unroll
        for (int r = 0; r < 4; r++) o[f][r] = 0.f;

    for (int j0t = 64; j0t < SB; j0t += 64) {
        int mdist = max(abs(i0 - (j0t + 63)), abs((i0 + 63) - j0t));
        if (mdist <= 256) continue;

        __syncthreads();
        // load K and V tiles (single fp16)
#pragma unroll
        for (int it = 0; it < 16; it++) {
            int flat = it * 512 + tid * 4;
            int r = flat >> 7, c = flat & 127;
            float4 kvv = *(const float4*)(kbase + (size_t)(j0t + r) * KVF + c);
            __half hh[4];
            hh[0] = __float2half_rn(kvv.x); hh[1] = __float2half_rn(kvv.y);
            hh[2] = __float2half_rn(kvv.z); hh[3] = __float2half_rn(kvv.w);
            *(uint2*)(sB + (AK/2) + r * ASTR + c) = *(uint2*)hh;
            float4 vv = *(const float4*)(vbase + (size_t)(j0t + r) * KVF + c);
            hh[0] = __float2half_rn(vv.x); hh[1] = __float2half_rn(vv.y);
            hh[2] = __float2half_rn(vv.z); hh[3] = __float2half_rn(vv.w);
            *(uint2*)(sB + (AV/2) + r * ASTR + c) = *(uint2*)hh;
        }
        __syncthreads();

        // ---- S = Q K^T ----
        float sacc[8][4];
#pragma unroll
        for (int j = 0; j < 8; j++)
#pragma unroll
            for (int r = 0; r < 4; r++) sacc[j][r] = 0.f;

#pragma unroll
        for (int kk = 0; kk < 8; kk++) {
            uint32_t qf[4];
            ldsm4(qf[0], qf[1], qf[2], qf[3], sb + AQ + aOff + kk * 32);
#pragma unroll
            for (int g = 0; g < 4; g++) {
                uint32_t kf[4];
                ldsm4(kf[0], kf[1], kf[2], kf[3],
                      sb + AK + bRowOff + (uint32_t)(g * 16 * 272) + kk * 32);
                mma_f16(sacc[2*g],   qf[0], qf[1], qf[2], qf[3], kf[0], kf[1]);
                mma_f16(sacc[2*g+1], qf[0], qf[1], qf[2], qf[3], kf[2], kf[3]);
            }
        }

        // ---- mask + ALiBi + online softmax (fp32) ----
        float tmax0 = -INFINITY, tmax1 = -INFINITY;
#pragma unroll
        for (int j = 0; j < 8; j++) {
            int gj = j0t + j * 8 + cb;
#pragma unroll
            for (int e = 0; e < 4; e++) {
                int gi = (e < 2) ? gi0 : gi1;
                int dist = abs(gi - (gj + (e & 1)));
                float val = (dist <= 256) ? -1e9f
                                          : (sacc[j][e] * scale - slope * (float)dist);
                sacc[j][e] = val;
                if (e < 2) tmax0 = fmaxf(tmax0, val);
                else       tmax1 = fmaxf(tmax1, val);
            }
        }
        tmax0 = fmaxf(tmax0, __shfl_xor_sync(0xffffffffu, tmax0, 1));
        tmax0 = fmaxf(tmax0, __shfl_xor_sync(0xffffffffu, tmax0, 2));
        tmax1 = fmaxf(tmax1, __shfl_xor_sync(0xffffffffu, tmax1, 1));
        tmax1 = fmaxf(tmax1, __shfl_xor_sync(0xffffffffu, tmax1, 2));

        float mn0 = fmaxf(m0, tmax0), mn1 = fmaxf(m1, tmax1);
        float f0 = __expf(m0 - mn0), f1 = __expf(m1 - mn1);
        float rs0 = 0.f, rs1 = 0.f;
#pragma unroll
        for (int j = 0; j < 8; j++) {
            float p0 = __expf(sacc[j][0] - mn0);
            float p1 = __expf(sacc[j][1] - mn0);
            float p2 = __expf(sacc[j][2] - mn1);
            float p3 = __expf(sacc[j][3] - mn1);
            sacc[j][0] = p0; sacc[j][1] = p1; sacc[j][2] = p2; sacc[j][3] = p3;
            rs0 += p0 + p1; rs1 += p2 + p3;
        }
        rs0 += __shfl_xor_sync(0xffffffffu, rs0, 1);
        rs0 += __shfl_xor_sync(0xffffffffu, rs0, 2);
        rs1 += __shfl_xor_sync(0xffffffffu, rs1, 1);
        rs1 += __shfl_xor_sync(0xffffffffu, rs1, 2);
        l0 = l0 * f0 + rs0; l1 = l1 * f1 + rs1;
        m0 = mn0; m1 = mn1;

#pragma unroll
        for (int f = 0; f < 16; f++) {
            o[f][0] *= f0; o[f][1] *= f0;
            o[f][2] *= f1; o[f][3] *= f1;
        }

        // ---- O += P V (both single fp16) ----
#pragma unroll
        for (int kk = 0; kk < 4; kk++) {
            uint32_t pF[4];
            pF[0] = pack_h2(__float2half_rn(sacc[2*kk][0]),   __float2half_rn(sacc[2*kk][1]));
            pF[1] = pack_h2(__float2half_rn(sacc[2*kk][2]),   __float2half_rn(sacc[2*kk][3]));
            pF[2] = pack_h2(__float2half_rn(sacc[2*kk+1][0]), __float2half_rn(sacc[2*kk+1][1]));
            pF[3] = pack_h2(__float2half_rn(sacc[2*kk+1][2]), __float2half_rn(sacc[2*kk+1][3]));
#pragma unroll
            for (int g = 0; g < 8; g++) {
                uint32_t vh[4];
                ldsm4t(vh[0], vh[1], vh[2], vh[3],
                       sb + AV + vOff + (uint32_t)(kk * 16 * 272) + (uint32_t)(g * 32));
                mma_f16(o[2*g],   pF[0], pF[1], pF[2], pF[3], vh[0], vh[1]);
                mma_f16(o[2*g+1], pF[0], pF[1], pF[2], pF[3], vh[2], vh[3]);
            }
        }
    }

    // epilogue: divide by l, write single fp16
    float inv0 = 1.f / l0, inv1 = 1.f / l1;
    size_t row0 = (size_t)(b * SB) + gi0;
    size_t row1 = (size_t)(b * SB) + gi1;
#pragma unroll
    for (int f = 0; f < 16; f++) {
        int cg = h * HD + f * 8 + cb;
        *(uint32_t*)(at16 + row0 * DIMD + cg) =
            pack_h2(__float2half_rn(o[f][0] * inv0), __float2half_rn(o[f][1] * inv0));
        *(uint32_t*)(at16 + row1 * DIMD + cg) =
            pack_h2(__float2half_rn(o[f][2] * inv1), __float2half_rn(o[f][3] * inv1));
    }
}

// ---------------- launcher ----------------
extern "C" void kernel_launch(void* const* d_in, const int* in_sizes, int n_in,
                              void* d_out, int out_size) {
    (void)in_sizes; (void)n_in; (void)out_size;
    const float* x   = (const float*)d_in[0];
    const float* Wq  = (const float*)d_in[1];
    const float* Wkv = (const float*)d_in[2];
    const float* Wo  = (const float*)d_in[3];
    const float* bo  = (const float*)d_in[4];
    float* out = (float*)d_out;

    float *qb, *kvb;
    cudaGetSymbolAddress((void**)&qb,  g_q);
    cudaGetSymbolAddress((void**)&kvb, g_kv);
    __half *xq16, *x16, *at16, *wq16, *wkv16, *wo16;
    cudaGetSymbolAddress((void**)&xq16,  g_xq16);
    cudaGetSymbolAddress((void**)&x16,   g_x16);
    cudaGetSymbolAddress((void**)&at16,  g_at16);
    cudaGetSymbolAddress((void**)&wq16,  g_wq16);
    cudaGetSymbolAddress((void**)&wkv16, g_wkv16);
    cudaGetSymbolAddress((void**)&wo16,  g_wo16);

    cudaFuncSetAttribute(attn_mma_kernel, cudaFuncAttributeMaxDynamicSharedMemorySize,
                         ATTN_SMEM_BYTES);
    cudaFuncSetAttribute(gemm1h_kernel, cudaFuncAttributeMaxDynamicSharedMemorySize,
                         GEMM1_SMEM);

    // gating + operand prep
    gate_h_kernel<<<ROWS, 256>>>(x, xq16, x16);
    transpose_h_kernel<<<dim3(DIMD/32, DIMD/32), dim3(32, 8)>>>(Wq,  wq16,  DIMD, DIMD);
    transpose_h_kernel<<<dim3(KVF/32,  DIMD/32), dim3(32, 8)>>>(Wkv, wkv16, DIMD, KVF);
    transpose_h_kernel<<<dim3(DIMD/32, DIMD/32), dim3(32, 8)>>>(Wo,  wo16,  DIMD, DIMD);

    // projections: single fp16 on tensor cores
    gemm1h_kernel<<<dim3(DIMD/128, ROWS/256), 256, GEMM1_SMEM>>>(
        xq16, wq16, nullptr, qb, ROWS, DIMD, DIMD);
    gemm1h_kernel<<<dim3(KVF/128, ROWS/256), 256, GEMM1_SMEM>>>(
        x16, wkv16, nullptr, kvb, ROWS, KVF, DIMD);

    // attention (writes fp16 at directly)
    vmean_kernel<<<BATCH * NKVH, 1024>>>(kvb, at16);
    dim3 ga(31, NH, BATCH);
    attn_mma_kernel<<<ga, 128, ATTN_SMEM_BYTES>>>(qb, kvb, at16);

    // output projection: single fp16 + bias
    gemm1h_kernel<<<dim3(DIMD/128, ROWS/256), 256, GEMM1_SMEM>>>(
        at16, wo16, bo, out, ROWS, DIMD, DIMD);
}

// round 14
// speedup vs baseline: 5.0138x; 1.0994x over previous
#include <cuda_runtime.h>
#include <cuda_bf16.h>
#include <cuda_fp16.h>
#include <cstdint>
#include <stdint.h>
#include <math.h>

#define SB    2048
#define DIMD  2048
#define BATCH 2
#define NH    16
#define NKVH  4
#define HD    128
#define KVF   1024
#define ROWS  (BATCH*SB)   // 4096

// ---------------- scratch (device globals: allocation-free) ----------------
__device__ __half g_q16 [(size_t)ROWS*DIMD];             // fp16 q
__device__ __half g_kv16[(size_t)ROWS*KVF];              // fp16 k|v
__device__ __half g_xq16[(size_t)ROWS*DIMD];             // fp16 gated x
__device__ __half g_x16 [(size_t)ROWS*DIMD];             // fp16 x
__device__ __half g_at16[(size_t)ROWS*DIMD];             // fp16 attention out
__device__ __half g_wq16 [(size_t)DIMD*DIMD];            // fp16 WqT
__device__ __half g_wkv16[(size_t)KVF *DIMD];            // fp16 WkvT
__device__ __half g_wo16 [(size_t)DIMD*DIMD];            // fp16 WoT

// ---------------- helpers ----------------
__device__ __forceinline__ uint32_t pack_h2(__half a, __half b) {
    __half2 t; t.x = a; t.y = b;
    return *(uint32_t*)&t;
}

// ---------------- kernel 1: complexity gate -> fp16 xq AND fp16 x ----------
__global__ __launch_bounds__(256) void gate_h_kernel(const float* __restrict__ x,
                                                     __half* __restrict__ xqh,
                                                     __half* __restrict__ xh) {
    int row = blockIdx.x;
    const float* xr = x + (size_t)row * DIMD;
    float s = 0.f;
    for (int c = threadIdx.x; c < DIMD; c += 256) s += fabsf(xr[c]);
    __shared__ float red[256];
    red[threadIdx.x] = s; __syncthreads();
    for (int off = 128; off > 0; off >>= 1) {
        if (threadIdx.x < off) red[threadIdx.x] += red[threadIdx.x + off];
        __syncthreads();
    }
    float cw = 1.f / (1.f + __expf(-red[0]));
    size_t base = (size_t)row * DIMD;
    for (int c = threadIdx.x; c < DIMD; c += 256) {
        float v = xr[c];
        xh [base + c] = __float2half_rn(v);
        xqh[base + c] = __float2half_rn(v * cw);
    }
}

// ---------------- transpose W[K][N] -> T[N][K], single fp16 ----------------
__global__ __launch_bounds__(256) void transpose_h_kernel(
    const float* __restrict__ W, __half* __restrict__ T, int K, int N) {
    __shared__ float tile[32][33];
    int n0 = blockIdx.x * 32, k0 = blockIdx.y * 32;
    int tx = threadIdx.x, ty = threadIdx.y;
#pragma unroll
    for (int r = ty; r < 32; r += 8)
        tile[r][tx] = W[(size_t)(k0 + r) * N + n0 + tx];
    __syncthreads();
#pragma unroll
    for (int r = ty; r < 32; r += 8)
        T[(size_t)(n0 + r) * K + k0 + tx] = __float2half_rn(tile[tx][r]);
}

// ---------------- mma primitives ----------------
__device__ __forceinline__ void cp16(uint32_t dst, const void* src) {
    asm volatile("cp.async.cg.shared.global [%0], [%1], 16;\n" :: "r"(dst), "l"(src));
}
__device__ __forceinline__ void cp_commit() { asm volatile("cp.async.commit_group;\n"); }
__device__ __forceinline__ void cp_wait1() { asm volatile("cp.async.wait_group 1;\n"); }
__device__ __forceinline__ void cp_wait0() { asm volatile("cp.async.wait_group 0;\n"); }
__device__ __forceinline__ void ldsm4(uint32_t& r0, uint32_t& r1, uint32_t& r2, uint32_t& r3,
                                      uint32_t addr) {
    asm volatile("ldmatrix.sync.aligned.m8n8.x4.shared.b16 {%0,%1,%2,%3}, [%4];\n"
                 : "=r"(r0), "=r"(r1), "=r"(r2), "=r"(r3) : "r"(addr));
}
__device__ __forceinline__ void ldsm4t(uint32_t& r0, uint32_t& r1, uint32_t& r2, uint32_t& r3,
                                       uint32_t addr) {
    asm volatile("ldmatrix.sync.aligned.m8n8.x4.trans.shared.b16 {%0,%1,%2,%3}, [%4];\n"
                 : "=r"(r0), "=r"(r1), "=r"(r2), "=r"(r3) : "r"(addr));
}
__device__ __forceinline__ void mma_f16(float* d, uint32_t a0, uint32_t a1, uint32_t a2,
                                        uint32_t a3, uint32_t b0, uint32_t b1) {
    asm volatile("mma.sync.aligned.m16n8k16.row.col.f32.f16.f16.f32 "
                 "{%0,%1,%2,%3}, {%4,%5,%6,%7}, {%8,%9}, {%0,%1,%2,%3};\n"
                 : "+f"(d[0]), "+f"(d[1]), "+f"(d[2]), "+f"(d[3])
                 : "r"(a0), "r"(a1), "r"(a2), "r"(a3), "r"(b0), "r"(b1));
}

// ---------------- shared tile constants (256x128 block, 8 warps 64x64) ------
#define SROWB 80
#define ABUF  (256*SROWB)        // 20480 B
#define BBUF  (128*SROWB)        // 10240 B
#define STAGE1B (ABUF + BBUF)    // A|B = 30720
#define GEMM3S_SMEM (3*STAGE1B)  // 92160 (3-stage)

// ---- shared GEMM body macros (3-stage pipeline) ----
#define GEMM_ISSUE(s) do {                                                       \
    const uint32_t so = (uint32_t)(((s) % 3) * STAGE1B);                         \
    const size_t off = (size_t)(s) * 32;                                         \
    _Pragma("unroll")                                                            \
    for (int c = 0; c < 4; c++) cp16(aD + so + c * 16, A + aG + off + c * 8);    \
    cp16(bD + so,      B + bG + off);                                            \
    cp16(bD + so + 16, B + bG + off + 8);                                        \
    cp_commit();                                                                 \
} while (0)

// ---------------- fused Q+KV fp16 GEMM: fp16 out, 3-stage --------------------
// grid.x: 0..15 -> Q tile (A=xq, B=Wq, C=q16, N=2048); 16..23 -> KV tile.
__global__ __launch_bounds__(256, 1) void gemm_qkv_kernel(
    const __half* __restrict__ Aq, const __half* __restrict__ Ax,
    const __half* __restrict__ Bq, const __half* __restrict__ Bkv,
    __half* __restrict__ Cq, __half* __restrict__ Ckv) {
    extern __shared__ char smem[];
    const uint32_t sb = (uint32_t)__cvta_generic_to_shared(smem);
    const int tid = threadIdx.x;
    const int lane = tid & 31, wid = tid >> 5;
    const int warpM = wid >> 1, warpN = wid & 1;

    const bool isQ = blockIdx.x < 16;
    const __half* A = isQ ? Aq : Ax;
    const __half* B = isQ ? Bq : Bkv;
    __half* C = isQ ? Cq : Ckv;
    const int N = isQ ? DIMD : KVF;
    const int K = DIMD;
    const int mBlk = blockIdx.y * 256;
    const int nBlk = (isQ ? blockIdx.x : (blockIdx.x - 16)) * 128;

    const size_t aG = (size_t)(mBlk + tid) * K;
    const int brow = tid >> 1, bc0 = (tid & 1) * 2;
    const size_t bG = (size_t)(nBlk + brow) * K + bc0 * 8;
    const uint32_t aD = sb + tid * SROWB;
    const uint32_t bD = sb + ABUF + brow * SROWB + bc0 * 16;

    const int aRow = warpM * 64 + (lane & 7) + ((lane >> 3) & 1) * 8;
    const uint32_t aLd = aRow * SROWB + (lane >> 4) * 16;
    const int bRow = warpN * 64 + (lane & 7) + (lane >> 4) * 8;
    const uint32_t bLd = bRow * SROWB + ((lane >> 3) & 1) * 16;

    float acc[4][8][4];
#pragma unroll
    for (int i = 0; i < 4; i++)
#pragma unroll
        for (int j = 0; j < 8; j++)
#pragma unroll
            for (int r = 0; r < 4; r++) acc[i][j][r] = 0.f;

    const int nkt = K / 32;   // 64
    GEMM_ISSUE(0);
    GEMM_ISSUE(1);

    for (int kt = 0; kt < nkt; kt++) {
        if (kt < nkt - 1) cp_wait1(); else cp_wait0();
        __syncthreads();
        if (kt + 2 < nkt) GEMM_ISSUE(kt + 2);

        const uint32_t base = sb + (uint32_t)((kt % 3) * STAGE1B);
#pragma unroll
        for (int kkB = 0; kkB < 64; kkB += 32) {
            uint32_t bh[16];
#pragma unroll
            for (int g = 0; g < 4; g++)
                ldsm4(bh[4*g], bh[4*g+1], bh[4*g+2], bh[4*g+3],
                      base + ABUF + bLd + kkB + (uint32_t)(g * 16 * SROWB));
#pragma unroll
            for (int i = 0; i < 4; i++) {
                uint32_t ah[4];
                ldsm4(ah[0], ah[1], ah[2], ah[3],
                      base + aLd + (uint32_t)(i * 16 * SROWB) + kkB);
#pragma unroll
                for (int j = 0; j < 8; j++)
                    mma_f16(acc[i][j], ah[0], ah[1], ah[2], ah[3], bh[2*j], bh[2*j+1]);
            }
        }
    }

    // epilogue: fp16 output
#pragma unroll
    for (int i = 0; i < 4; i++) {
#pragma unroll
        for (int j = 0; j < 8; j++) {
            int rg = mBlk + warpM * 64 + i * 16 + (lane >> 2);
            int cg = nBlk + warpN * 64 + j * 8 + (lane & 3) * 2;
            *(uint32_t*)(C + (size_t)rg * N + cg) =
                pack_h2(__float2half_rn(acc[i][j][0]), __float2half_rn(acc[i][j][1]));
            *(uint32_t*)(C + (size_t)(rg + 8) * N + cg) =
                pack_h2(__float2half_rn(acc[i][j][2]), __float2half_rn(acc[i][j][3]));
        }
    }
}

// ---------------- Wo GEMM: fp32 out + bias, 3-stage --------------------------
__global__ __launch_bounds__(256, 1) void gemm_out_kernel(
    const __half* __restrict__ A, const __half* __restrict__ B,
    const float* __restrict__ bias, float* __restrict__ C) {
    extern __shared__ char smem[];
    const uint32_t sb = (uint32_t)__cvta_generic_to_shared(smem);
    const int tid = threadIdx.x;
    const int lane = tid & 31, wid = tid >> 5;
    const int warpM = wid >> 1, warpN = wid & 1;
    const int N = DIMD, K = DIMD;
    const int mBlk = blockIdx.y * 256, nBlk = blockIdx.x * 128;

    const size_t aG = (size_t)(mBlk + tid) * K;
    const int brow = tid >> 1, bc0 = (tid & 1) * 2;
    const size_t bG = (size_t)(nBlk + brow) * K + bc0 * 8;
    const uint32_t aD = sb + tid * SROWB;
    const uint32_t bD = sb + ABUF + brow * SROWB + bc0 * 16;

    const int aRow = warpM * 64 + (lane & 7) + ((lane >> 3) & 1) * 8;
    const uint32_t aLd = aRow * SROWB + (lane >> 4) * 16;
    const int bRow = warpN * 64 + (lane & 7) + (lane >> 4) * 8;
    const uint32_t bLd = bRow * SROWB + ((lane >> 3) & 1) * 16;

    float acc[4][8][4];
#pragma unroll
    for (int i = 0; i < 4; i++)
#pragma unroll
        for (int j = 0; j < 8; j++)
#pragma unroll
            for (int r = 0; r < 4; r++) acc[i][j][r] = 0.f;

    const int nkt = K / 32;
    GEMM_ISSUE(0);
    GEMM_ISSUE(1);

    for (int kt = 0; kt < nkt; kt++) {
        if (kt < nkt - 1) cp_wait1(); else cp_wait0();
        __syncthreads();
        if (kt + 2 < nkt) GEMM_ISSUE(kt + 2);

        const uint32_t base = sb + (uint32_t)((kt % 3) * STAGE1B);
#pragma unroll
        for (int kkB = 0; kkB < 64; kkB += 32) {
            uint32_t bh[16];
#pragma unroll
            for (int g = 0; g < 4; g++)
                ldsm4(bh[4*g], bh[4*g+1], bh[4*g+2], bh[4*g+3],
                      base + ABUF + bLd + kkB + (uint32_t)(g * 16 * SROWB));
#pragma unroll
            for (int i = 0; i < 4; i++) {
                uint32_t ah[4];
                ldsm4(ah[0], ah[1], ah[2], ah[3],
                      base + aLd + (uint32_t)(i * 16 * SROWB) + kkB);
#pragma unroll
                for (int j = 0; j < 8; j++)
                    mma_f16(acc[i][j], ah[0], ah[1], ah[2], ah[3], bh[2*j], bh[2*j+1]);
            }
        }
    }

#pragma unroll
    for (int i = 0; i < 4; i++) {
#pragma unroll
        for (int j = 0; j < 8; j++) {
            int rg = mBlk + warpM * 64 + i * 16 + (lane >> 2);
            int cg = nBlk + warpN * 64 + j * 8 + (lane & 3) * 2;
            float b0 = bias[cg], b1 = bias[cg + 1];
            *(float2*)(C + (size_t)rg * N + cg) =
                make_float2(acc[i][j][0] + b0, acc[i][j][1] + b1);
            *(float2*)(C + (size_t)(rg + 8) * N + cg) =
                make_float2(acc[i][j][2] + b0, acc[i][j][3] + b1);
        }
    }
}

// ---------------- vmean: global query rows (i<64) -> fp16 at ----------------
__global__ __launch_bounds__(1024) void vmean_kernel(const __half* __restrict__ kv,
                                                     __half* __restrict__ at16) {
    int b = blockIdx.x >> 2, kvh = blockIdx.x & 3;
    int d = threadIdx.x & 127;
    int c = threadIdx.x >> 7;
    const __half* v = kv + (size_t)b * SB * KVF + NKVH * HD + kvh * HD + d;
    float s = 0.f;
    int j0 = c * 256;
#pragma unroll 8
    for (int j = j0; j < j0 + 256; j++) s += __half2float(v[(size_t)j * KVF]);
    __shared__ float red[8][128];
    red[c][d] = s;
    __syncthreads();
    if (c == 0) {
        float t = 0.f;
#pragma unroll
        for (int u = 0; u < 8; u++) t += red[u][d];
        __half th = __float2half_rn(t * (1.0f / 2048.0f));
        for (int hh = 0; hh < 4; hh++) {
            int h = kvh * 4 + hh;
            for (int i = 0; i < 64; i++)
                at16[((size_t)(b * SB) + i) * DIMD + h * HD + d] = th;
        }
    }
}

// ---------------- fp16 tensor-core flash attention (inverted window mask) ---
// smem tiles (fp16, ASTR=136 halfs/row): Q | K | V
#define ASTR 136
#define ATILE (64*ASTR)
#define AQ  0
#define AK  (ATILE*2)
#define AV  (2*ATILE*2)
#define ATTN_SMEM_BYTES (3*ATILE*2)   // 52224

__global__ __launch_bounds__(128) void attn_mma_kernel(
    const __half* __restrict__ q, const __half* __restrict__ kv,
    __half* __restrict__ at16) {
    extern __shared__ char asmem[];
    __half* sB = (__half*)asmem;
    const uint32_t sb = (uint32_t)__cvta_generic_to_shared(asmem);

    const int tid = threadIdx.x;
    const int lane = tid & 31, w = tid >> 5;
    const int i0 = 64 + blockIdx.x * 64;
    const int h  = blockIdx.y;
    const int b  = blockIdx.z;
    const int kvh = h >> 2;
    const float slope = exp2f(-0.5f * (float)(h + 1));
    const float scale = 0.08838834764831845f;

    const __half* qbase = q  + ((size_t)(b * SB + i0) * DIMD) + h * HD;
    const __half* kbase = kv + ((size_t)b * SB * KVF) + kvh * HD;
    const __half* vbase = kbase + NKVH * HD;

    // load Q tile (already fp16 — straight copy)
#pragma unroll
    for (int it = 0; it < 8; it++) {
        int flat = it * 1024 + tid * 8;
        int r = flat >> 7, c = flat & 127;
        *(uint4*)(sB + (AQ/2) + r * ASTR + c) = *(const uint4*)(qbase + (size_t)r * DIMD + c);
    }

    const uint32_t aOff = (uint32_t)((w * 16 + (lane & 7) + ((lane >> 3) & 1) * 8) * 272
                                     + (lane >> 4) * 16);
    const uint32_t bRowOff = (uint32_t)(((lane & 7) + (lane >> 4) * 8) * 272
                                        + ((lane >> 3) & 1) * 16);
    const uint32_t vOff = (uint32_t)(((lane & 7) + ((lane >> 3) & 1) * 8) * 272
                                     + (lane >> 4) * 16);

    const int gi0 = i0 + w * 16 + (lane >> 2);
    const int gi1 = gi0 + 8;
    const int cb  = (lane & 3) * 2;
    float m0 = -INFINITY, m1 = -INFINITY, l0 = 0.f, l1 = 0.f;

    float o[16][4];
#pragma unroll
    for (int f = 0; f < 16; f++)
#pragma unroll
        for (int r = 0; r < 4; r++) o[f][r] = 0.f;

    for (int j0t = 64; j0t < SB; j0t += 64) {
        int mdist = max(abs(i0 - (j0t + 63)), abs((i0 + 63) - j0t));
        if (mdist <= 256) continue;

        __syncthreads();
        // load K and V tiles (already fp16 — straight copies)
#pragma unroll
        for (int it = 0; it < 8; it++) {
            int flat = it * 1024 + tid * 8;
            int r = flat >> 7, c = flat & 127;
            *(uint4*)(sB + (AK/2) + r * ASTR + c) =
                *(const uint4*)(kbase + (size_t)(j0t + r) * KVF + c);
            *(uint4*)(sB + (AV/2) + r * ASTR + c) =
                *(const uint4*)(vbase + (size_t)(j0t + r) * KVF + c);
        }
        __syncthreads();

        // ---- S = Q K^T ----
        float sacc[8][4];
#pragma unroll
        for (int j = 0; j < 8; j++)
#pragma unroll
            for (int r = 0; r < 4; r++) sacc[j][r] = 0.f;

#pragma unroll
        for (int kk = 0; kk < 8; kk++) {
            uint32_t qf[4];
            ldsm4(qf[0], qf[1], qf[2], qf[3], sb + AQ + aOff + kk * 32);
#pragma unroll
            for (int g = 0; g < 4; g++) {
                uint32_t kf[4];
                ldsm4(kf[0], kf[1], kf[2], kf[3],
                      sb + AK + bRowOff + (uint32_t)(g * 16 * 272) + kk * 32);
                mma_f16(sacc[2*g],   qf[0], qf[1], qf[2], qf[3], kf[0], kf[1]);
                mma_f16(sacc[2*g+1], qf[0], qf[1], qf[2], qf[3], kf[2], kf[3]);
            }
        }

        // ---- mask + ALiBi + online softmax (fp32) ----
        float tmax0 = -INFINITY, tmax1 = -INFINITY;
#pragma unroll
        for (int j = 0; j < 8; j++) {
            int gj = j0t + j * 8 + cb;
#pragma unroll
            for (int e = 0; e < 4; e++) {
                int gi = (e < 2) ? gi0 : gi1;
                int dist = abs(gi - (gj + (e & 1)));
                float val = (dist <= 256) ? -1e9f
                                          : (sacc[j][e] * scale - slope * (float)dist);
                sacc[j][e] = val;
                if (e < 2) tmax0 = fmaxf(tmax0, val);
                else       tmax1 = fmaxf(tmax1, val);
            }
        }
        tmax0 = fmaxf(tmax0, __shfl_xor_sync(0xffffffffu, tmax0, 1));
        tmax0 = fmaxf(tmax0, __shfl_xor_sync(0xffffffffu, tmax0, 2));
        tmax1 = fmaxf(tmax1, __shfl_xor_sync(0xffffffffu, tmax1, 1));
        tmax1 = fmaxf(tmax1, __shfl_xor_sync(0xffffffffu, tmax1, 2));

        float mn0 = fmaxf(m0, tmax0), mn1 = fmaxf(m1, tmax1);
        float f0 = __expf(m0 - mn0), f1 = __expf(m1 - mn1);
        float rs0 = 0.f, rs1 = 0.f;
#pragma unroll
        for (int j = 0; j < 8; j++) {
            float p0 = __expf(sacc[j][0] - mn0);
            float p1 = __expf(sacc[j][1] - mn0);
            float p2 = __expf(sacc[j][2] - mn1);
            float p3 = __expf(sacc[j][3] - mn1);
            sacc[j][0] = p0; sacc[j][1] = p1; sacc[j][2] = p2; sacc[j][3] = p3;
            rs0 += p0 + p1; rs1 += p2 + p3;
        }
        rs0 += __shfl_xor_sync(0xffffffffu, rs0, 1);
        rs0 += __shfl_xor_sync(0xffffffffu, rs0, 2);
        rs1 += __shfl_xor_sync(0xffffffffu, rs1, 1);
        rs1 += __shfl_xor_sync(0xffffffffu, rs1, 2);
        l0 = l0 * f0 + rs0; l1 = l1 * f1 + rs1;
        m0 = mn0; m1 = mn1;

#pragma unroll
        for (int f = 0; f < 16; f++) {
            o[f][0] *= f0; o[f][1] *= f0;
            o[f][2] *= f1; o[f][3] *= f1;
        }

        // ---- O += P V ----
#pragma unroll
        for (int kk = 0; kk < 4; kk++) {
            uint32_t pF[4];
            pF[0] = pack_h2(__float2half_rn(sacc[2*kk][0]),   __float2half_rn(sacc[2*kk][1]));
            pF[1] = pack_h2(__float2half_rn(sacc[2*kk][2]),   __float2half_rn(sacc[2*kk][3]));
            pF[2] = pack_h2(__float2half_rn(sacc[2*kk+1][0]), __float2half_rn(sacc[2*kk+1][1]));
            pF[3] = pack_h2(__float2half_rn(sacc[2*kk+1][2]), __float2half_rn(sacc[2*kk+1][3]));
#pragma unroll
            for (int g = 0; g < 8; g++) {
                uint32_t vh[4];
                ldsm4t(vh[0], vh[1], vh[2], vh[3],
                       sb + AV + vOff + (uint32_t)(kk * 16 * 272) + (uint32_t)(g * 32));
                mma_f16(o[2*g],   pF[0], pF[1], pF[2], pF[3], vh[0], vh[1]);
                mma_f16(o[2*g+1], pF[0], pF[1], pF[2], pF[3], vh[2], vh[3]);
            }
        }
    }

    // epilogue: divide by l, write single fp16
    float inv0 = 1.f / l0, inv1 = 1.f / l1;
    size_t row0 = (size_t)(b * SB) + gi0;
    size_t row1 = (size_t)(b * SB) + gi1;
#pragma unroll
    for (int f = 0; f < 16; f++) {
        int cg = h * HD + f * 8 + cb;
        *(uint32_t*)(at16 + row0 * DIMD + cg) =
            pack_h2(__float2half_rn(o[f][0] * inv0), __float2half_rn(o[f][1] * inv0));
        *(uint32_t*)(at16 + row1 * DIMD + cg) =
            pack_h2(__float2half_rn(o[f][2] * inv1), __float2half_rn(o[f][3] * inv1));
    }
}

// ---------------- launcher ----------------
extern "C" void kernel_launch(void* const* d_in, const int* in_sizes, int n_in,
                              void* d_out, int out_size) {
    (void)in_sizes; (void)n_in; (void)out_size;
    const float* x   = (const float*)d_in[0];
    const float* Wq  = (const float*)d_in[1];
    const float* Wkv = (const float*)d_in[2];
    const float* Wo  = (const float*)d_in[3];
    const float* bo  = (const float*)d_in[4];
    float* out = (float*)d_out;

    __half *q16, *kv16, *xq16, *x16, *at16, *wq16, *wkv16, *wo16;
    cudaGetSymbolAddress((void**)&q16,   g_q16);
    cudaGetSymbolAddress((void**)&kv16,  g_kv16);
    cudaGetSymbolAddress((void**)&xq16,  g_xq16);
    cudaGetSymbolAddress((void**)&x16,   g_x16);
    cudaGetSymbolAddress((void**)&at16,  g_at16);
    cudaGetSymbolAddress((void**)&wq16,  g_wq16);
    cudaGetSymbolAddress((void**)&wkv16, g_wkv16);
    cudaGetSymbolAddress((void**)&wo16,  g_wo16);

    cudaFuncSetAttribute(attn_mma_kernel, cudaFuncAttributeMaxDynamicSharedMemorySize,
                         ATTN_SMEM_BYTES);
    cudaFuncSetAttribute(gemm_qkv_kernel, cudaFuncAttributeMaxDynamicSharedMemorySize,
                         GEMM3S_SMEM);
    cudaFuncSetAttribute(gemm_out_kernel, cudaFuncAttributeMaxDynamicSharedMemorySize,
                         GEMM3S_SMEM);

    // gating + operand prep
    gate_h_kernel<<<ROWS, 256>>>(x, xq16, x16);
    transpose_h_kernel<<<dim3(DIMD/32, DIMD/32), dim3(32, 8)>>>(Wq,  wq16,  DIMD, DIMD);
    transpose_h_kernel<<<dim3(KVF/32,  DIMD/32), dim3(32, 8)>>>(Wkv, wkv16, DIMD, KVF);
    transpose_h_kernel<<<dim3(DIMD/32, DIMD/32), dim3(32, 8)>>>(Wo,  wo16,  DIMD, DIMD);

    // fused Q + KV projection (fp16 outputs)
    gemm_qkv_kernel<<<dim3(24, ROWS/256), 256, GEMM3S_SMEM>>>(
        xq16, x16, wq16, wkv16, q16, kv16);

    // attention (fp16 in, fp16 out)
    vmean_kernel<<<BATCH * NKVH, 1024>>>(kv16, at16);
    dim3 ga(31, NH, BATCH);
    attn_mma_kernel<<<ga, 128, ATTN_SMEM_BYTES>>>(q16, kv16, at16);

    // output projection (fp32 out + bias)
    gemm_out_kernel<<<dim3(DIMD/128, ROWS/256), 256, GEMM3S_SMEM>>>(
        at16, wo16, bo, out);
}